// round 9
// baseline (speedup 1.0000x reference)
#include <cuda_runtime.h>
#include <cuda_bf16.h>
#include <cstdint>

#define NN 100000
#define EE 300000
#define GG 4096
#define DD 256
#define LL 5
#define BN_EPS 1e-5f
#define NW 18

// ---------------- scratch (device globals; no allocations) ----------------
__device__ int g_off[NN + 2];                      // CSR offsets (by dst)
__device__ int g_cur[NN];                          // scatter cursors
__device__ uint32_t g_epack[EE];                   // src*256 + bondcode, dst-sorted
__device__ float g_lut[216 * DD];                  // bond-embedding LUT (fp32)
__device__ float g_agg[(size_t)NN * DD];           // edge aggregation
__device__ float g_t[(size_t)NN * DD];             // gemm2 out
__device__ float g_y[(size_t)NN * DD];             // gemm1 out
__device__ float g_vn[(size_t)GG * DD];            // virtual node state
__device__ float g_pooled[(size_t)GG * DD];        // raw pooled sum
__device__ float g_vt[(size_t)GG * DD];
__device__ float g_vt2[(size_t)GG * DD];
__device__ float g_stats[2 * DD];                  // big-path column sum / sumsq
__device__ float g_bnp[2 * DD];                    // big-path bn scale / shift
__device__ float g_stats_v[2 * DD];                // vn-path column sum / sumsq
__device__ float g_bnp_v[2 * DD];                  // vn-path bn scale / shift
__device__ int g_cnt[2];                           // last-CTA tickets (big, vn) — self-resetting
__device__ uint32_t g_whi[(size_t)NW * 128 * DD];  // pre-split W (bf16 hi)
__device__ uint32_t g_wlo[(size_t)NW * 128 * DD];  // pre-split W (bf16 lo)

__device__ __forceinline__ void red2(float* p, float a, float b) {
    asm volatile("red.global.add.v2.f32 [%0], {%1,%2};" :: "l"(p), "f"(a), "f"(b) : "memory");
}
__device__ __forceinline__ void red4(float* p, float a, float b, float c, float d) {
    asm volatile("red.global.add.v4.f32 [%0], {%1,%2,%3,%4};"
                 :: "l"(p), "f"(a), "f"(b), "f"(c), "f"(d) : "memory");
}
__device__ __forceinline__ void cp16(uint32_t smem_addr, const void* g) {
    asm volatile("cp.async.cg.shared.global [%0], [%1], 16;" :: "r"(smem_addr), "l"(g));
}
__device__ __forceinline__ void cp_commit() {
    asm volatile("cp.async.commit_group;");
}
__device__ __forceinline__ void cp_wait0() {
    asm volatile("cp.async.wait_group 0;");
}

__device__ __forceinline__ uint32_t pack_bf2(float a, float b) {
    __nv_bfloat162 t = __floats2bfloat162_rn(a, b);
    return *(uint32_t*)&t;
}
__device__ __forceinline__ void split_pack(float a, float b, uint32_t& hi, uint32_t& lo) {
    __nv_bfloat16 ah = __float2bfloat16_rn(a);
    __nv_bfloat16 bh = __float2bfloat16_rn(b);
    float al = a - __bfloat162float(ah);
    float bl = b - __bfloat162float(bh);
    __nv_bfloat162 h2; h2.x = ah; h2.y = bh;
    hi = *(uint32_t*)&h2;
    lo = pack_bf2(al, bl);
}

// last-CTA fused BN prep: call at very end of a GEMM epilogue.
// Safe: ticket taken after every block finished mainloop (bnp reads) + stats reds.
__device__ __forceinline__ void bn_prep_lastcta(
    int tid, int nblk, int* cnt, float* stats, float* bnp,
    const float* gamma, const float* beta, float Minv) {
    __threadfence();
    __shared__ int slast;
    if (tid == 0) slast = (atomicAdd(cnt, 1) == nblk - 1);
    __syncthreads();
    if (slast && tid < DD) {
        int c = tid;
        float s = __ldcg(&stats[c]);
        float s2 = __ldcg(&stats[DD + c]);
        float m = s * Minv;
        float var = s2 * Minv - m * m;
        float rs = rsqrtf(var + BN_EPS);
        float sc = gamma[c] * rs;
        bnp[c] = sc;
        bnp[DD + c] = beta[c] - m * sc;
        stats[c] = 0.f;
        stats[DD + c] = 0.f;
        if (tid == 0) *cnt = 0;
    }
}

// ---------------- small kernels ----------------
__global__ void k_zero(float* p, int n4) {
    int i = blockIdx.x * blockDim.x + threadIdx.x;
    if (i < n4) ((float4*)p)[i] = make_float4(0.f, 0.f, 0.f, 0.f);
}
__global__ void k_zero_off() {
    int i = blockIdx.x * blockDim.x + threadIdx.x;
    if (i < NN + 2) g_off[i] = 0;
}

__global__ void k_split_w(const float* __restrict__ W, uint32_t* __restrict__ hi,
                          uint32_t* __restrict__ lo) {
    int i = blockIdx.x * blockDim.x + threadIdx.x;
    if (i >= 128 * DD) return;
    int k2 = i >> 8, n = i & 255;
    float a = W[(size_t)(2 * k2) * DD + n];
    float b = W[(size_t)(2 * k2 + 1) * DD + n];
    split_pack(a, b, hi[i], lo[i]);
}

__global__ void k_build_lut(const float* __restrict__ bond_emb) {
    int idx = blockIdx.x * blockDim.x + threadIdx.x;
    if (idx >= 216 * 64) return;
    int c = idx >> 6;
    int d4 = (idx & 63) * 4;
    int v0 = c / 36, v1 = (c / 6) % 6, v2 = c % 6;
    float4 a = *(const float4*)(bond_emb + ((size_t)(0 * 6 + v0) * DD + d4));
    float4 b = *(const float4*)(bond_emb + ((size_t)(1 * 6 + v1) * DD + d4));
    float4 d = *(const float4*)(bond_emb + ((size_t)(2 * 6 + v2) * DD + d4));
    *(float4*)(g_lut + (size_t)c * DD + d4) =
        make_float4(a.x + b.x + d.x, a.y + b.y + d.y, a.z + b.z + d.z, a.w + b.w + d.w);
}

// ---- CSR build ----
__global__ void k_hist(const int* __restrict__ ei) {
    int e = blockIdx.x * blockDim.x + threadIdx.x;
    if (e < EE) atomicAdd(&g_off[ei[EE + e]], 1);
}

#define SCAN_T 1024
#define SCAN_CH 98   // ceil(NN / 1024)
__global__ void k_scan() {
    __shared__ int ssum[SCAN_T];
    int t = threadIdx.x;
    int begin = t * SCAN_CH;
    int end = min(NN, begin + SCAN_CH);
    int s = 0;
    for (int i = begin; i < end; i++) s += g_off[i];
    ssum[t] = s;
    __syncthreads();
    for (int d = 1; d < SCAN_T; d <<= 1) {
        int v = (t >= d) ? ssum[t - d] : 0;
        __syncthreads();
        ssum[t] += v;
        __syncthreads();
    }
    int run = ssum[t] - s;  // exclusive prefix
    for (int i = begin; i < end; i++) {
        int c = g_off[i];
        g_off[i] = run;
        g_cur[i] = run;
        run += c;
    }
    if (t == SCAN_T - 1) g_off[NN] = ssum[SCAN_T - 1];
}

__global__ void k_scatter_e(const int* __restrict__ ei, const int* __restrict__ ea_idx) {
    int e = blockIdx.x * blockDim.x + threadIdx.x;
    if (e >= EE) return;
    int dst = ei[EE + e];
    int src = ei[e];
    int code = ea_idx[e * 3 + 0] * 36 + ea_idx[e * 3 + 1] * 6 + ea_idx[e * 3 + 2];
    int pos = atomicAdd(&g_cur[dst], 1);
    g_epack[pos] = (uint32_t)src * 256u + (uint32_t)code;
}

// CSR aggregation: one warp per node, registers accumulate, single store
__global__ void __launch_bounds__(256)
k_agg(const float* __restrict__ h) {
    int gw = (blockIdx.x * 256 + threadIdx.x) >> 5;
    if (gw >= NN) return;
    int lane = threadIdx.x & 31;
    int base = lane * 8;
    float acc[8] = {0.f, 0.f, 0.f, 0.f, 0.f, 0.f, 0.f, 0.f};
    int p0 = g_off[gw], p1 = g_off[gw + 1];
    for (int p = p0; p < p1; p++) {
        uint32_t pk = __ldg(&g_epack[p]);
        const float* hr = h + (size_t)(pk >> 8) * DD + base;
        const float* lr = g_lut + (size_t)(pk & 255u) * DD + base;
        float4 h0 = *(const float4*)hr;
        float4 h1 = *(const float4*)(hr + 4);
        float4 l0 = *(const float4*)lr;
        float4 l1 = *(const float4*)(lr + 4);
        acc[0] += fmaxf(h0.x + l0.x, 0.f);
        acc[1] += fmaxf(h0.y + l0.y, 0.f);
        acc[2] += fmaxf(h0.z + l0.z, 0.f);
        acc[3] += fmaxf(h0.w + l0.w, 0.f);
        acc[4] += fmaxf(h1.x + l1.x, 0.f);
        acc[5] += fmaxf(h1.y + l1.y, 0.f);
        acc[6] += fmaxf(h1.z + l1.z, 0.f);
        acc[7] += fmaxf(h1.w + l1.w, 0.f);
    }
    float* o = g_agg + (size_t)gw * DD + base;
    *(float4*)o = make_float4(acc[0], acc[1], acc[2], acc[3]);
    *(float4*)(o + 4) = make_float4(acc[4], acc[5], acc[6], acc[7]);
}

// atom encoder: h0 = sum emb + vn0; also scatter h0 row into pooled
__global__ void k_encode_atoms(const int* __restrict__ x,
                               const float* __restrict__ atom_emb,
                               const float* __restrict__ vn_emb,
                               const int* __restrict__ batch,
                               float* __restrict__ out0) {
    int idx = blockIdx.x * blockDim.x + threadIdx.x;
    if (idx >= NN * 64) return;
    int n = idx >> 6;
    int d4 = (idx & 63) * 4;
    float4 acc = *(const float4*)(vn_emb + d4);
#pragma unroll
    for (int f = 0; f < 9; f++) {
        int v = __ldg(&x[n * 9 + f]);
        float4 e = *(const float4*)(atom_emb + ((size_t)(f * 120 + v) * DD + d4));
        acc.x += e.x; acc.y += e.y; acc.z += e.z; acc.w += e.w;
    }
    *(float4*)(out0 + (size_t)n * DD + d4) = acc;
    int g = __ldg(&batch[n]);
    red4(g_pooled + (size_t)g * DD + d4, acc.x, acc.y, acc.z, acc.w);
}

__global__ void k_vn_init(const float* __restrict__ vn_emb) {
    int i = blockIdx.x * blockDim.x + threadIdx.x;
    if (i < GG * DD) g_vn[i] = vn_emb[i & (DD - 1)];
}

// ---------------- GEMM common ----------------
__device__ __forceinline__ void mma_bf16(float* c, const uint32_t* a, uint32_t b0, uint32_t b1) {
    asm volatile(
        "mma.sync.aligned.m16n8k16.row.col.f32.bf16.bf16.f32 "
        "{%0,%1,%2,%3}, {%4,%5,%6,%7}, {%8,%9}, {%0,%1,%2,%3};"
        : "+f"(c[0]), "+f"(c[1]), "+f"(c[2]), "+f"(c[3])
        : "r"(a[0]), "r"(a[1]), "r"(a[2]), "r"(a[3]), "r"(b0), "r"(b1));
}

// MODE 1: A=(1+eps)h+agg.  MODE 2: A=relu(y*scale+shift).  MODE 3: A=A+A2.
template <int MODE>
__device__ __forceinline__ float4 load_a4(const float* A, const float* A2,
                                          const float* bnp, float e,
                                          size_t off, int kidx) {
    float4 v;
    if (MODE == 1) {
        float4 hv = *(const float4*)(A + off);
        float4 av = *(const float4*)(A2 + off);
        v.x = e * hv.x + av.x; v.y = e * hv.y + av.y;
        v.z = e * hv.z + av.z; v.w = e * hv.w + av.w;
    } else if (MODE == 2) {
        float4 yv = *(const float4*)(A + off);
        float4 sc = *(const float4*)(bnp + kidx);
        float4 sh = *(const float4*)(bnp + DD + kidx);
        v.x = fmaxf(yv.x * sc.x + sh.x, 0.f);
        v.y = fmaxf(yv.y * sc.y + sh.y, 0.f);
        v.z = fmaxf(yv.z * sc.z + sh.z, 0.f);
        v.w = fmaxf(yv.w * sc.w + sh.w, 0.f);
    } else {
        float4 hv = *(const float4*)(A + off);
        float4 av = *(const float4*)(A2 + off);
        v.x = hv.x + av.x; v.y = hv.y + av.y;
        v.z = hv.z + av.z; v.w = hv.w + av.w;
    }
    return v;
}

// ---------------- big GEMM: BM=64, BN=256, BK=32, 256 threads, occ 2 ----
// double-buffered pipeline + fused last-CTA bn_prep
#define BM 64
#define A_SZ 1152               // 16 * 72 u32
#define B_SZ 4224               // 16 * 264 u32
#define B_BASE (4 * A_SZ)
#define SMEM_BIG ((4 * A_SZ + 4 * B_SZ) * 4)

template <int MODE>
__global__ void __launch_bounds__(256, 2)
k_gemm_big(const float* __restrict__ A, const float* __restrict__ A2,
           const float* __restrict__ epsp, const uint32_t* __restrict__ Whi,
           const uint32_t* __restrict__ Wlo, const float* __restrict__ bias,
           float* __restrict__ C, int M, float* __restrict__ stats,
           const float* __restrict__ bnp,
           float* __restrict__ bnp_out, const float* __restrict__ gamma,
           const float* __restrict__ beta, float Minv, int* cnt, int nblk) {
    extern __shared__ uint32_t sm[];
    const uint32_t sbase = (uint32_t)__cvta_generic_to_shared(sm);

    int tid = threadIdx.x;
    int lane = tid & 31;
    int wid = tid >> 5;
    int wr = wid >> 2;
    int wc = wid & 3;
    int row0 = blockIdx.x * BM;

    float e = 0.f;
    if (MODE == 1) e = 1.0f + __ldg(epsp);

    const int ar0 = tid >> 3;
    const int akk = (tid & 7) * 4;
    const int br = tid >> 6;
    const int bn4 = (tid & 63) * 4;

    float acc[2][8][4];
#pragma unroll
    for (int i = 0; i < 2; i++)
#pragma unroll
        for (int j = 0; j < 8; j++)
#pragma unroll
            for (int r = 0; r < 4; r++) acc[i][j][r] = 0.f;

    float4 vA[2];

    auto issueB = [&](int k0, int buf) {
        const uint32_t* wh = Whi + (size_t)(k0 >> 1) * DD;
        const uint32_t* wl = Wlo + (size_t)(k0 >> 1) * DD;
        uint32_t bhi = sbase + (B_BASE + buf * 2 * B_SZ) * 4;
        uint32_t blo = bhi + B_SZ * 4;
#pragma unroll
        for (int q = 0; q < 4; q++) {
            int r = br + q * 4;
            cp16(bhi + (r * 264 + bn4) * 4, wh + (size_t)r * DD + bn4);
            cp16(blo + (r * 264 + bn4) * 4, wl + (size_t)r * DD + bn4);
        }
        cp_commit();
    };
    auto loadA = [&](int k0) {
#pragma unroll
        for (int q = 0; q < 2; q++) {
            int gr = row0 + ar0 + q * 32;
            vA[q] = make_float4(0.f, 0.f, 0.f, 0.f);
            if (gr < M) vA[q] = load_a4<MODE>(A, A2, bnp, e, (size_t)gr * DD + k0 + akk, k0 + akk);
        }
    };
    auto storeA = [&](int buf) {
        uint32_t* ahi = sm + buf * 2 * A_SZ;
        uint32_t* alo = ahi + A_SZ;
        int k2 = akk >> 1;
#pragma unroll
        for (int q = 0; q < 2; q++) {
            int r = ar0 + q * 32;
            uint32_t h0, l0, h1, l1;
            split_pack(vA[q].x, vA[q].y, h0, l0);
            split_pack(vA[q].z, vA[q].w, h1, l1);
            ahi[k2 * 72 + r] = h0;       alo[k2 * 72 + r] = l0;
            ahi[(k2 + 1) * 72 + r] = h1; alo[(k2 + 1) * 72 + r] = l1;
        }
    };

    issueB(0, 0);
    loadA(0);
    storeA(0);
    cp_wait0();
    __syncthreads();

#pragma unroll 1
    for (int it = 0; it < 8; it++) {
        int cur = it & 1;
        int nxt = cur ^ 1;
        if (it < 7) {
            issueB((it + 1) * 32, nxt);
            loadA((it + 1) * 32);
        }
        {
            const uint32_t* ahi = sm + cur * 2 * A_SZ;
            const uint32_t* alo = ahi + A_SZ;
            const uint32_t* bhi = sm + B_BASE + cur * 2 * B_SZ;
            const uint32_t* blo = bhi + B_SZ;
#pragma unroll
            for (int s = 0; s < 2; s++) {
                int kb = s * 8 + (lane & 3);
                uint32_t ah[2][4], al[2][4];
#pragma unroll
                for (int i = 0; i < 2; i++) {
                    int m = wr * 32 + i * 16 + (lane >> 2);
                    ah[i][0] = ahi[kb * 72 + m];       ah[i][1] = ahi[kb * 72 + m + 8];
                    ah[i][2] = ahi[(kb + 4) * 72 + m]; ah[i][3] = ahi[(kb + 4) * 72 + m + 8];
                    al[i][0] = alo[kb * 72 + m];       al[i][1] = alo[kb * 72 + m + 8];
                    al[i][2] = alo[(kb + 4) * 72 + m]; al[i][3] = alo[(kb + 4) * 72 + m + 8];
                }
#pragma unroll
                for (int j = 0; j < 8; j++) {
                    int n = wc * 64 + j * 8 + (lane >> 2);
                    uint32_t bh0 = bhi[kb * 264 + n], bh1 = bhi[(kb + 4) * 264 + n];
                    uint32_t bl0 = blo[kb * 264 + n], bl1 = blo[(kb + 4) * 264 + n];
#pragma unroll
                    for (int i = 0; i < 2; i++) {
                        mma_bf16(acc[i][j], ah[i], bh0, bh1);
                        mma_bf16(acc[i][j], ah[i], bl0, bl1);
                        mma_bf16(acc[i][j], al[i], bh0, bh1);
                    }
                }
            }
        }
        if (it < 7) {
            storeA(nxt);
            cp_wait0();
        }
        __syncthreads();
    }

#pragma unroll
    for (int j = 0; j < 8; j++) {
        int gc = wc * 64 + j * 8 + (lane & 3) * 2;
        float bx = __ldg(&bias[gc]);
        float by = __ldg(&bias[gc + 1]);
        float sx = 0.f, sy = 0.f, qx = 0.f, qy = 0.f;
#pragma unroll
        for (int i = 0; i < 2; i++) {
            int gr = row0 + wr * 32 + i * 16 + (lane >> 2);
            if (gr < M) {
                float2 v0 = make_float2(acc[i][j][0] + bx, acc[i][j][1] + by);
                *(float2*)(C + (size_t)gr * DD + gc) = v0;
                sx += v0.x; sy += v0.y; qx += v0.x * v0.x; qy += v0.y * v0.y;
            }
            if (gr + 8 < M) {
                float2 v1 = make_float2(acc[i][j][2] + bx, acc[i][j][3] + by);
                *(float2*)(C + (size_t)(gr + 8) * DD + gc) = v1;
                sx += v1.x; sy += v1.y; qx += v1.x * v1.x; qy += v1.y * v1.y;
            }
        }
#pragma unroll
        for (int d = 4; d < 32; d <<= 1) {
            sx += __shfl_xor_sync(0xffffffff, sx, d);
            sy += __shfl_xor_sync(0xffffffff, sy, d);
            qx += __shfl_xor_sync(0xffffffff, qx, d);
            qy += __shfl_xor_sync(0xffffffff, qy, d);
        }
        if ((lane >> 2) == 0) {
            red2(&stats[gc], sx, sy);
            red2(&stats[DD + gc], qx, qy);
        }
    }
    bn_prep_lastcta(tid, nblk, cnt, stats, bnp_out, gamma, beta, Minv);
}

// ---------------- small GEMM: BM=64, BN=128 (grid.y=2), 256 threads ----------------
template <int MODE>
__global__ void __launch_bounds__(256, 2)
k_gemm_small(const float* __restrict__ A, const float* __restrict__ A2,
             const uint32_t* __restrict__ Whi, const uint32_t* __restrict__ Wlo,
             const float* __restrict__ bias, float* __restrict__ C, int M,
             float* __restrict__ stats, const float* __restrict__ bnp,
             float* __restrict__ bnp_out, const float* __restrict__ gamma,
             const float* __restrict__ beta, float Minv, int* cnt, int nblk) {
    __shared__ uint32_t As_hi[16][72];
    __shared__ uint32_t As_lo[16][72];
    __shared__ uint32_t Bs_hi[16][136];
    __shared__ uint32_t Bs_lo[16][136];

    int tid = threadIdx.x;
    int lane = tid & 31;
    int wid = tid >> 5;
    int wr = wid >> 1;
    int wc = wid & 1;
    int row0 = blockIdx.x * 64;
    int col0 = blockIdx.y * 128;

    float acc[8][4];
#pragma unroll
    for (int j = 0; j < 8; j++)
#pragma unroll
        for (int r = 0; r < 4; r++) acc[j][r] = 0.f;

    for (int k0 = 0; k0 < DD; k0 += 32) {
#pragma unroll
        for (int q = 0; q < 2; q++) {
            int li = tid + q * 256;
            int r = li >> 3;
            int kk = (li & 7) * 4;
            float4 v = make_float4(0.f, 0.f, 0.f, 0.f);
            int gr = row0 + r;
            if (gr < M) v = load_a4<MODE>(A, A2, bnp, 0.f, (size_t)gr * DD + k0 + kk, k0 + kk);
            int k2 = kk >> 1;
            uint32_t h0, l0, h1, l1;
            split_pack(v.x, v.y, h0, l0);
            split_pack(v.z, v.w, h1, l1);
            As_hi[k2][r] = h0;     As_lo[k2][r] = l0;
            As_hi[k2 + 1][r] = h1; As_lo[k2 + 1][r] = l1;
        }
        {
            const uint32_t* wh = Whi + (size_t)(k0 >> 1) * DD + col0;
            const uint32_t* wl = Wlo + (size_t)(k0 >> 1) * DD + col0;
#pragma unroll
            for (int q = 0; q < 2; q++) {
                int li = tid + q * 256;
                int r = li >> 5;
                int n4 = (li & 31) * 4;
                *(uint4*)&Bs_hi[r][n4] = *(const uint4*)(wh + (size_t)r * DD + n4);
                *(uint4*)&Bs_lo[r][n4] = *(const uint4*)(wl + (size_t)r * DD + n4);
            }
        }
        __syncthreads();

#pragma unroll
        for (int s = 0; s < 2; s++) {
            int kb = s * 8 + (lane & 3);
            int m = wr * 16 + (lane >> 2);
            uint32_t ah[4], al[4];
            ah[0] = As_hi[kb][m];     ah[1] = As_hi[kb][m + 8];
            ah[2] = As_hi[kb + 4][m]; ah[3] = As_hi[kb + 4][m + 8];
            al[0] = As_lo[kb][m];     al[1] = As_lo[kb][m + 8];
            al[2] = As_lo[kb + 4][m]; al[3] = As_lo[kb + 4][m + 8];
#pragma unroll
            for (int j = 0; j < 8; j++) {
                int n = wc * 64 + j * 8 + (lane >> 2);
                uint32_t bh0 = Bs_hi[kb][n], bh1 = Bs_hi[kb + 4][n];
                uint32_t bl0 = Bs_lo[kb][n], bl1 = Bs_lo[kb + 4][n];
                mma_bf16(acc[j], ah, bh0, bh1);
                mma_bf16(acc[j], ah, bl0, bl1);
                mma_bf16(acc[j], al, bh0, bh1);
            }
        }
        __syncthreads();
    }

#pragma unroll
    for (int j = 0; j < 8; j++) {
        int gc = col0 + wc * 64 + j * 8 + (lane & 3) * 2;
        float bx = __ldg(&bias[gc]);
        float by = __ldg(&bias[gc + 1]);
        float sx = 0.f, sy = 0.f, qx = 0.f, qy = 0.f;
        int gr = row0 + wr * 16 + (lane >> 2);
        if (gr < M) {
            float2 v0 = make_float2(acc[j][0] + bx, acc[j][1] + by);
            *(float2*)(C + (size_t)gr * DD + gc) = v0;
            sx += v0.x; sy += v0.y; qx += v0.x * v0.x; qy += v0.y * v0.y;
        }
        if (gr + 8 < M) {
            float2 v1 = make_float2(acc[j][2] + bx, acc[j][3] + by);
            *(float2*)(C + (size_t)(gr + 8) * DD + gc) = v1;
            sx += v1.x; sy += v1.y; qx += v1.x * v1.x; qy += v1.y * v1.y;
        }
#pragma unroll
        for (int d = 4; d < 32; d <<= 1) {
            sx += __shfl_xor_sync(0xffffffff, sx, d);
            sy += __shfl_xor_sync(0xffffffff, sy, d);
            qx += __shfl_xor_sync(0xffffffff, qx, d);
            qy += __shfl_xor_sync(0xffffffff, qy, d);
        }
        if ((lane >> 2) == 0) {
            red2(&stats[gc], sx, sy);
            red2(&stats[DD + gc], qx, qy);
        }
    }
    bn_prep_lastcta(tid, nblk, cnt, stats, bnp_out, gamma, beta, Minv);
}

// ---------------- BN apply ----------------
__global__ void k_bn_apply(const float* __restrict__ Yin, float* __restrict__ Yout,
                           const float* __restrict__ bnp, const int* __restrict__ batch,
                           int M, int do_relu, int do_vn, int do_pool) {
    int idx = blockIdx.x * blockDim.x + threadIdx.x;
    if (idx >= M * 64) return;
    int r = idx >> 6;
    int c4 = (idx & 63) * 4;
    float4 sc = *(const float4*)(bnp + c4);
    float4 sh = *(const float4*)(bnp + DD + c4);
    float4 v = *(const float4*)(Yin + (size_t)r * DD + c4);
    v.x = v.x * sc.x + sh.x;
    v.y = v.y * sc.y + sh.y;
    v.z = v.z * sc.z + sh.z;
    v.w = v.w * sc.w + sh.w;
    if (do_relu) {
        v.x = fmaxf(v.x, 0.f); v.y = fmaxf(v.y, 0.f);
        v.z = fmaxf(v.z, 0.f); v.w = fmaxf(v.w, 0.f);
    }
    int g = 0;
    if (do_vn || do_pool) g = __ldg(&batch[r]);
    if (do_vn) {
        float4 w = *(const float4*)(g_vn + (size_t)g * DD + c4);
        v.x += w.x; v.y += w.y; v.z += w.z; v.w += w.w;
    }
    *(float4*)(Yout + (size_t)r * DD + c4) = v;
    if (do_pool) red4(g_pooled + (size_t)g * DD + c4, v.x, v.y, v.z, v.w);
}

// ---------------- host orchestration ----------------
extern "C" void kernel_launch(void* const* d_in, const int* in_sizes, int n_in,
                              void* d_out, int out_size) {
    const int* x          = (const int*)d_in[0];
    const int* edge_index = (const int*)d_in[1];
    const int* edge_attr  = (const int*)d_in[2];
    const int* batch      = (const int*)d_in[3];
    const float* atom_emb = (const float*)d_in[4];
    const float* bond_emb = (const float*)d_in[5];
    const float* vn_emb   = (const float*)d_in[6];
    const float* gin_eps  = (const float*)d_in[7];
    const float* conv_W1  = (const float*)d_in[8];
    const float* conv_b1  = (const float*)d_in[9];
    const float* conv_bn_g = (const float*)d_in[10];
    const float* conv_bn_b = (const float*)d_in[11];
    const float* conv_W2  = (const float*)d_in[12];
    const float* conv_b2  = (const float*)d_in[13];
    const float* outer_bn_g = (const float*)d_in[14];
    const float* outer_bn_b = (const float*)d_in[15];
    const float* vn_W1    = (const float*)d_in[16];
    const float* vn_b1    = (const float*)d_in[17];
    const float* vn_bn1_g = (const float*)d_in[18];
    const float* vn_bn1_b = (const float*)d_in[19];
    const float* vn_W2    = (const float*)d_in[20];
    const float* vn_b2    = (const float*)d_in[21];
    const float* vn_bn2_g = (const float*)d_in[22];
    const float* vn_bn2_b = (const float*)d_in[23];
    float* out = (float*)d_out;

    cudaFuncSetAttribute(k_gemm_big<1>, cudaFuncAttributeMaxDynamicSharedMemorySize, SMEM_BIG);
    cudaFuncSetAttribute(k_gemm_big<2>, cudaFuncAttributeMaxDynamicSharedMemorySize, SMEM_BIG);

    float *p_agg, *p_t, *p_y, *p_pooled, *p_vt, *p_vt2, *p_vn;
    float *p_stats, *p_bnp, *p_stats_v, *p_bnp_v;
    int* p_cnt;
    uint32_t *p_whi, *p_wlo;
    cudaGetSymbolAddress((void**)&p_agg, g_agg);
    cudaGetSymbolAddress((void**)&p_t, g_t);
    cudaGetSymbolAddress((void**)&p_y, g_y);
    cudaGetSymbolAddress((void**)&p_pooled, g_pooled);
    cudaGetSymbolAddress((void**)&p_vt, g_vt);
    cudaGetSymbolAddress((void**)&p_vt2, g_vt2);
    cudaGetSymbolAddress((void**)&p_vn, g_vn);
    cudaGetSymbolAddress((void**)&p_stats, g_stats);
    cudaGetSymbolAddress((void**)&p_bnp, g_bnp);
    cudaGetSymbolAddress((void**)&p_stats_v, g_stats_v);
    cudaGetSymbolAddress((void**)&p_bnp_v, g_bnp_v);
    cudaGetSymbolAddress((void**)&p_cnt, g_cnt);
    cudaGetSymbolAddress((void**)&p_whi, g_whi);
    cudaGetSymbolAddress((void**)&p_wlo, g_wlo);

    const size_t slot = (size_t)NN * DD;
    const size_t wslot = (size_t)128 * DD;
    const int blkN = (NN * 64 + 255) / 256;
    const float invN = 1.0f / (float)NN;
    const float invG = 1.0f / (float)GG;

    cudaStream_t sv;
    cudaStreamCreateWithFlags(&sv, cudaStreamNonBlocking);
    cudaEvent_t ev_start, ev_splits, ev_fork[LL], ev_join[LL];
    cudaEventCreateWithFlags(&ev_start, cudaEventDisableTiming);
    cudaEventCreateWithFlags(&ev_splits, cudaEventDisableTiming);
    for (int l = 0; l < LL; l++) {
        cudaEventCreateWithFlags(&ev_fork[l], cudaEventDisableTiming);
        cudaEventCreateWithFlags(&ev_join[l], cudaEventDisableTiming);
    }

    // ---- fork: weight splitting on sv, everything else on main ----
    cudaEventRecord(ev_start, 0);
    cudaStreamWaitEvent(sv, ev_start, 0);
    const int wgrid = (128 * DD + 255) / 256;
    for (int l = 0; l < LL; l++) {
        k_split_w<<<wgrid, 256, 0, sv>>>(conv_W1 + (size_t)l * DD * DD,
                                         p_whi + (size_t)l * wslot, p_wlo + (size_t)l * wslot);
        k_split_w<<<wgrid, 256, 0, sv>>>(conv_W2 + (size_t)l * DD * DD,
                                         p_whi + (size_t)(5 + l) * wslot,
                                         p_wlo + (size_t)(5 + l) * wslot);
    }
    for (int l = 0; l < LL - 1; l++) {
        k_split_w<<<wgrid, 256, 0, sv>>>(vn_W1 + (size_t)l * DD * DD,
                                         p_whi + (size_t)(10 + l) * wslot,
                                         p_wlo + (size_t)(10 + l) * wslot);
        k_split_w<<<wgrid, 256, 0, sv>>>(vn_W2 + (size_t)l * DD * DD,
                                         p_whi + (size_t)(14 + l) * wslot,
                                         p_wlo + (size_t)(14 + l) * wslot);
    }
    cudaEventRecord(ev_splits, sv);

    // main: zeros, CSR build, lut, encode, vn_init
    k_zero<<<1, 128>>>(p_stats, 128);
    k_zero<<<1, 128>>>(p_stats_v, 128);
    k_zero<<<(GG * 64 + 255) / 256, 256>>>(p_pooled, GG * 64);
    k_zero_off<<<(NN + 2 + 255) / 256, 256>>>();
    k_hist<<<(EE + 255) / 256, 256>>>(edge_index);
    k_scan<<<1, SCAN_T>>>();
    k_scatter_e<<<(EE + 255) / 256, 256>>>(edge_index, edge_attr);
    k_build_lut<<<(216 * 64 + 255) / 256, 256>>>(bond_emb);
    k_encode_atoms<<<blkN, 256>>>(x, atom_emb, vn_emb, batch, out);
    k_vn_init<<<(GG * DD + 255) / 256, 256>>>(vn_emb);
    cudaStreamWaitEvent(0, ev_splits, 0);   // big GEMMs need whi/wlo

    const int gBig = (NN + BM - 1) / BM;
    const dim3 gSmall((GG + 63) / 64, 2);
    const int nSmall = ((GG + 63) / 64) * 2;
    const int gAgg = (NN * 32 + 255) / 256;

    for (int l = 0; l < LL; l++) {
        float* h = out + (size_t)l * slot;            // h_in^l (vn already added)
        float* z_out = out + (size_t)(l + 1) * slot;

        // vn chain on sv, concurrent with k_agg + big GEMMs
        if (l < LL - 1) {
            cudaEventRecord(ev_fork[l], 0);
            cudaStreamWaitEvent(sv, ev_fork[l], 0);
            k_gemm_small<3><<<gSmall, 256, 0, sv>>>(p_pooled, p_vn,
                                                    p_whi + (size_t)(10 + l) * wslot,
                                                    p_wlo + (size_t)(10 + l) * wslot,
                                                    vn_b1 + l * DD, p_vt, GG,
                                                    p_stats_v, nullptr,
                                                    p_bnp_v, vn_bn1_g + l * DD,
                                                    vn_bn1_b + l * DD, invG,
                                                    p_cnt + 1, nSmall);
            k_zero<<<(GG * 64 + 255) / 256, 256, 0, sv>>>(p_pooled, GG * 64);
            k_gemm_small<2><<<gSmall, 256, 0, sv>>>(p_vt, nullptr,
                                                    p_whi + (size_t)(14 + l) * wslot,
                                                    p_wlo + (size_t)(14 + l) * wslot,
                                                    vn_b2 + l * DD, p_vt2, GG,
                                                    p_stats_v, p_bnp_v,
                                                    p_bnp_v, vn_bn2_g + l * DD,
                                                    vn_bn2_b + l * DD, invG,
                                                    p_cnt + 1, nSmall);
            k_bn_apply<<<(GG * 64 + 255) / 256, 256, 0, sv>>>(p_vt2, p_vn, p_bnp_v,
                                                              nullptr, GG, 1, 0, 0);
            cudaEventRecord(ev_join[l], sv);
        }

        // main path
        k_agg<<<gAgg, 256>>>(h);
        k_gemm_big<1><<<gBig, 256, SMEM_BIG>>>(h, p_agg, gin_eps + l,
                                               p_whi + (size_t)l * wslot,
                                               p_wlo + (size_t)l * wslot,
                                               conv_b1 + l * DD, p_y, NN,
                                               p_stats, nullptr,
                                               p_bnp, conv_bn_g + l * DD,
                                               conv_bn_b + l * DD, invN,
                                               p_cnt, gBig);
        k_gemm_big<2><<<gBig, 256, SMEM_BIG>>>(p_y, nullptr, nullptr,
                                               p_whi + (size_t)(5 + l) * wslot,
                                               p_wlo + (size_t)(5 + l) * wslot,
                                               conv_b2 + l * DD, p_t, NN,
                                               p_stats, p_bnp,
                                               p_bnp, outer_bn_g + l * DD,
                                               outer_bn_b + l * DD, invN,
                                               p_cnt, gBig);
        // final BN apply needs new vn (and pooled zeroed) -> join
        if (l < LL - 1) cudaStreamWaitEvent(0, ev_join[l], 0);
        int relu = (l < LL - 1) ? 1 : 0;
        int vnadd = (l < LL - 1) ? 1 : 0;
        int pool = (l < LL - 2) ? 1 : 0;
        k_bn_apply<<<blkN, 256>>>(p_t, z_out, p_bnp, batch, NN, relu, vnadd, pool);
    }
}

// round 10
// speedup vs baseline: 1.0729x; 1.0729x over previous
#include <cuda_runtime.h>
#include <cuda_bf16.h>
#include <cstdint>

#define NN 100000
#define EE 300000
#define GG 4096
#define DD 256
#define LL 5
#define BN_EPS 1e-5f
#define NW 18

// ---------------- scratch (device globals; no allocations) ----------------
__device__ int g_off[NN + 2];                      // CSR offsets (by dst)
__device__ int g_cur[NN];                          // scatter cursors
__device__ uint32_t g_epack[EE];                   // src*256 + bondcode, dst-sorted
__device__ float g_lut[216 * DD];                  // bond-embedding LUT (fp32)
__device__ float g_agg[(size_t)NN * DD];           // edge aggregation
__device__ float g_t[(size_t)NN * DD];             // gemm2 out
__device__ float g_y[(size_t)NN * DD];             // gemm1 out
__device__ float g_vn[(size_t)GG * DD];            // virtual node state
__device__ float g_pooled[(size_t)GG * DD];        // raw pooled sum
__device__ float g_vt[(size_t)GG * DD];
__device__ float g_vt2[(size_t)GG * DD];
__device__ float g_stats[2 * DD];                  // big-path column sum / sumsq
__device__ float g_bnp[2 * DD];                    // big-path bn scale / shift
__device__ float g_stats_v[2 * DD];                // vn-path column sum / sumsq
__device__ float g_bnp_v[2 * DD];                  // vn-path bn scale / shift
__device__ uint32_t g_whi[(size_t)NW * 128 * DD];  // pre-split W (bf16 hi)
__device__ uint32_t g_wlo[(size_t)NW * 128 * DD];  // pre-split W (bf16 lo)

__device__ __forceinline__ void red2(float* p, float a, float b) {
    asm volatile("red.global.add.v2.f32 [%0], {%1,%2};" :: "l"(p), "f"(a), "f"(b) : "memory");
}
__device__ __forceinline__ void red4(float* p, float a, float b, float c, float d) {
    asm volatile("red.global.add.v4.f32 [%0], {%1,%2,%3,%4};"
                 :: "l"(p), "f"(a), "f"(b), "f"(c), "f"(d) : "memory");
}
__device__ __forceinline__ void cp16(uint32_t smem_addr, const void* g) {
    asm volatile("cp.async.cg.shared.global [%0], [%1], 16;" :: "r"(smem_addr), "l"(g));
}
__device__ __forceinline__ void cp_commit() {
    asm volatile("cp.async.commit_group;");
}
__device__ __forceinline__ void cp_wait0() {
    asm volatile("cp.async.wait_group 0;");
}

__device__ __forceinline__ uint32_t pack_bf2(float a, float b) {
    __nv_bfloat162 t = __floats2bfloat162_rn(a, b);
    return *(uint32_t*)&t;
}
__device__ __forceinline__ void split_pack(float a, float b, uint32_t& hi, uint32_t& lo) {
    __nv_bfloat16 ah = __float2bfloat16_rn(a);
    __nv_bfloat16 bh = __float2bfloat16_rn(b);
    float al = a - __bfloat162float(ah);
    float bl = b - __bfloat162float(bh);
    __nv_bfloat162 h2; h2.x = ah; h2.y = bh;
    hi = *(uint32_t*)&h2;
    lo = pack_bf2(al, bl);
}

// ---------------- small kernels ----------------
__global__ void k_zero(float* p, int n4) {
    int i = blockIdx.x * blockDim.x + threadIdx.x;
    if (i < n4) ((float4*)p)[i] = make_float4(0.f, 0.f, 0.f, 0.f);
}
__global__ void k_zero_off() {
    int i = blockIdx.x * blockDim.x + threadIdx.x;
    if (i < NN + 2) g_off[i] = 0;
}

__global__ void k_split_w(const float* __restrict__ W, uint32_t* __restrict__ hi,
                          uint32_t* __restrict__ lo) {
    int i = blockIdx.x * blockDim.x + threadIdx.x;
    if (i >= 128 * DD) return;
    int k2 = i >> 8, n = i & 255;
    float a = W[(size_t)(2 * k2) * DD + n];
    float b = W[(size_t)(2 * k2 + 1) * DD + n];
    split_pack(a, b, hi[i], lo[i]);
}

__global__ void k_build_lut(const float* __restrict__ bond_emb) {
    int idx = blockIdx.x * blockDim.x + threadIdx.x;
    if (idx >= 216 * 64) return;
    int c = idx >> 6;
    int d4 = (idx & 63) * 4;
    int v0 = c / 36, v1 = (c / 6) % 6, v2 = c % 6;
    float4 a = *(const float4*)(bond_emb + ((size_t)(0 * 6 + v0) * DD + d4));
    float4 b = *(const float4*)(bond_emb + ((size_t)(1 * 6 + v1) * DD + d4));
    float4 d = *(const float4*)(bond_emb + ((size_t)(2 * 6 + v2) * DD + d4));
    *(float4*)(g_lut + (size_t)c * DD + d4) =
        make_float4(a.x + b.x + d.x, a.y + b.y + d.y, a.z + b.z + d.z, a.w + b.w + d.w);
}

// ---- CSR build ----
__global__ void k_hist(const int* __restrict__ ei) {
    int e = blockIdx.x * blockDim.x + threadIdx.x;
    if (e < EE) atomicAdd(&g_off[ei[EE + e]], 1);
}

#define SCAN_T 1024
#define SCAN_CH 98   // ceil(NN / 1024)
__global__ void k_scan() {
    __shared__ int ssum[SCAN_T];
    int t = threadIdx.x;
    int begin = t * SCAN_CH;
    int end = min(NN, begin + SCAN_CH);
    int s = 0;
    for (int i = begin; i < end; i++) s += g_off[i];
    ssum[t] = s;
    __syncthreads();
    for (int d = 1; d < SCAN_T; d <<= 1) {
        int v = (t >= d) ? ssum[t - d] : 0;
        __syncthreads();
        ssum[t] += v;
        __syncthreads();
    }
    int run = ssum[t] - s;  // exclusive prefix
    for (int i = begin; i < end; i++) {
        int c = g_off[i];
        g_off[i] = run;
        g_cur[i] = run;
        run += c;
    }
    if (t == SCAN_T - 1) g_off[NN] = ssum[SCAN_T - 1];
}

__global__ void k_scatter_e(const int* __restrict__ ei, const int* __restrict__ ea_idx) {
    int e = blockIdx.x * blockDim.x + threadIdx.x;
    if (e >= EE) return;
    int dst = ei[EE + e];
    int src = ei[e];
    int code = ea_idx[e * 3 + 0] * 36 + ea_idx[e * 3 + 1] * 6 + ea_idx[e * 3 + 2];
    int pos = atomicAdd(&g_cur[dst], 1);
    g_epack[pos] = (uint32_t)src * 256u + (uint32_t)code;
}

// CSR aggregation: one warp per node, registers accumulate, single store
__global__ void __launch_bounds__(256)
k_agg(const float* __restrict__ h) {
    int gw = (blockIdx.x * 256 + threadIdx.x) >> 5;
    if (gw >= NN) return;
    int lane = threadIdx.x & 31;
    int base = lane * 8;
    float acc[8] = {0.f, 0.f, 0.f, 0.f, 0.f, 0.f, 0.f, 0.f};
    int p0 = g_off[gw], p1 = g_off[gw + 1];
    for (int p = p0; p < p1; p++) {
        uint32_t pk = __ldg(&g_epack[p]);
        const float* hr = h + (size_t)(pk >> 8) * DD + base;
        const float* lr = g_lut + (size_t)(pk & 255u) * DD + base;
        float4 h0 = *(const float4*)hr;
        float4 h1 = *(const float4*)(hr + 4);
        float4 l0 = *(const float4*)lr;
        float4 l1 = *(const float4*)(lr + 4);
        acc[0] += fmaxf(h0.x + l0.x, 0.f);
        acc[1] += fmaxf(h0.y + l0.y, 0.f);
        acc[2] += fmaxf(h0.z + l0.z, 0.f);
        acc[3] += fmaxf(h0.w + l0.w, 0.f);
        acc[4] += fmaxf(h1.x + l1.x, 0.f);
        acc[5] += fmaxf(h1.y + l1.y, 0.f);
        acc[6] += fmaxf(h1.z + l1.z, 0.f);
        acc[7] += fmaxf(h1.w + l1.w, 0.f);
    }
    float* o = g_agg + (size_t)gw * DD + base;
    *(float4*)o = make_float4(acc[0], acc[1], acc[2], acc[3]);
    *(float4*)(o + 4) = make_float4(acc[4], acc[5], acc[6], acc[7]);
}

// atom encoder: h0 = sum emb + vn0; also scatter h0 row into pooled
__global__ void k_encode_atoms(const int* __restrict__ x,
                               const float* __restrict__ atom_emb,
                               const float* __restrict__ vn_emb,
                               const int* __restrict__ batch,
                               float* __restrict__ out0) {
    int idx = blockIdx.x * blockDim.x + threadIdx.x;
    if (idx >= NN * 64) return;
    int n = idx >> 6;
    int d4 = (idx & 63) * 4;
    float4 acc = *(const float4*)(vn_emb + d4);
#pragma unroll
    for (int f = 0; f < 9; f++) {
        int v = __ldg(&x[n * 9 + f]);
        float4 e = *(const float4*)(atom_emb + ((size_t)(f * 120 + v) * DD + d4));
        acc.x += e.x; acc.y += e.y; acc.z += e.z; acc.w += e.w;
    }
    *(float4*)(out0 + (size_t)n * DD + d4) = acc;
    int g = __ldg(&batch[n]);
    red4(g_pooled + (size_t)g * DD + d4, acc.x, acc.y, acc.z, acc.w);
}

__global__ void k_vn_init(const float* __restrict__ vn_emb) {
    int i = blockIdx.x * blockDim.x + threadIdx.x;
    if (i < GG * DD) g_vn[i] = vn_emb[i & (DD - 1)];
}

// ---------------- GEMM common ----------------
__device__ __forceinline__ void mma_bf16(float* c, const uint32_t* a, uint32_t b0, uint32_t b1) {
    asm volatile(
        "mma.sync.aligned.m16n8k16.row.col.f32.bf16.bf16.f32 "
        "{%0,%1,%2,%3}, {%4,%5,%6,%7}, {%8,%9}, {%0,%1,%2,%3};"
        : "+f"(c[0]), "+f"(c[1]), "+f"(c[2]), "+f"(c[3])
        : "r"(a[0]), "r"(a[1]), "r"(a[2]), "r"(a[3]), "r"(b0), "r"(b1));
}

// MODE 1: A=(1+eps)h+agg.  MODE 2: A=relu(y*scale+shift).  MODE 3: A=A+A2.
template <int MODE>
__device__ __forceinline__ float4 load_a4(const float* A, const float* A2,
                                          const float* bnp, float e,
                                          size_t off, int kidx) {
    float4 v;
    if (MODE == 1) {
        float4 hv = *(const float4*)(A + off);
        float4 av = *(const float4*)(A2 + off);
        v.x = e * hv.x + av.x; v.y = e * hv.y + av.y;
        v.z = e * hv.z + av.z; v.w = e * hv.w + av.w;
    } else if (MODE == 2) {
        float4 yv = *(const float4*)(A + off);
        float4 sc = *(const float4*)(bnp + kidx);
        float4 sh = *(const float4*)(bnp + DD + kidx);
        v.x = fmaxf(yv.x * sc.x + sh.x, 0.f);
        v.y = fmaxf(yv.y * sc.y + sh.y, 0.f);
        v.z = fmaxf(yv.z * sc.z + sh.z, 0.f);
        v.w = fmaxf(yv.w * sc.w + sh.w, 0.f);
    } else {
        float4 hv = *(const float4*)(A + off);
        float4 av = *(const float4*)(A2 + off);
        v.x = hv.x + av.x; v.y = hv.y + av.y;
        v.z = hv.z + av.z; v.w = hv.w + av.w;
    }
    return v;
}

// ---------------- big GEMM: BM=64, BN=256, BK=32, 256 threads, occ 2 ----
// double-buffered pipeline: B via cp.async, A via register prefetch; 1 sync/iter
#define BM 64
#define A_SZ 1152               // 16 * 72 u32
#define B_SZ 4224               // 16 * 264 u32
#define B_BASE (4 * A_SZ)
#define SMEM_BIG ((4 * A_SZ + 4 * B_SZ) * 4)

template <int MODE>
__global__ void __launch_bounds__(256, 2)
k_gemm_big(const float* __restrict__ A, const float* __restrict__ A2,
           const float* __restrict__ epsp, const uint32_t* __restrict__ Whi,
           const uint32_t* __restrict__ Wlo, const float* __restrict__ bias,
           float* __restrict__ C, int M, float* __restrict__ stats,
           const float* __restrict__ bnp) {
    extern __shared__ uint32_t sm[];
    const uint32_t sbase = (uint32_t)__cvta_generic_to_shared(sm);

    int tid = threadIdx.x;
    int lane = tid & 31;
    int wid = tid >> 5;
    int wr = wid >> 2;
    int wc = wid & 3;
    int row0 = blockIdx.x * BM;

    float e = 0.f;
    if (MODE == 1) e = 1.0f + __ldg(epsp);

    const int ar0 = tid >> 3;
    const int akk = (tid & 7) * 4;
    const int br = tid >> 6;
    const int bn4 = (tid & 63) * 4;

    float acc[2][8][4];
#pragma unroll
    for (int i = 0; i < 2; i++)
#pragma unroll
        for (int j = 0; j < 8; j++)
#pragma unroll
            for (int r = 0; r < 4; r++) acc[i][j][r] = 0.f;

    float4 vA[2];

    auto issueB = [&](int k0, int buf) {
        const uint32_t* wh = Whi + (size_t)(k0 >> 1) * DD;
        const uint32_t* wl = Wlo + (size_t)(k0 >> 1) * DD;
        uint32_t bhi = sbase + (B_BASE + buf * 2 * B_SZ) * 4;
        uint32_t blo = bhi + B_SZ * 4;
#pragma unroll
        for (int q = 0; q < 4; q++) {
            int r = br + q * 4;
            cp16(bhi + (r * 264 + bn4) * 4, wh + (size_t)r * DD + bn4);
            cp16(blo + (r * 264 + bn4) * 4, wl + (size_t)r * DD + bn4);
        }
        cp_commit();
    };
    auto loadA = [&](int k0) {
#pragma unroll
        for (int q = 0; q < 2; q++) {
            int gr = row0 + ar0 + q * 32;
            vA[q] = make_float4(0.f, 0.f, 0.f, 0.f);
            if (gr < M) vA[q] = load_a4<MODE>(A, A2, bnp, e, (size_t)gr * DD + k0 + akk, k0 + akk);
        }
    };
    auto storeA = [&](int buf) {
        uint32_t* ahi = sm + buf * 2 * A_SZ;
        uint32_t* alo = ahi + A_SZ;
        int k2 = akk >> 1;
#pragma unroll
        for (int q = 0; q < 2; q++) {
            int r = ar0 + q * 32;
            uint32_t h0, l0, h1, l1;
            split_pack(vA[q].x, vA[q].y, h0, l0);
            split_pack(vA[q].z, vA[q].w, h1, l1);
            ahi[k2 * 72 + r] = h0;       alo[k2 * 72 + r] = l0;
            ahi[(k2 + 1) * 72 + r] = h1; alo[(k2 + 1) * 72 + r] = l1;
        }
    };

    issueB(0, 0);
    loadA(0);
    storeA(0);
    cp_wait0();
    __syncthreads();

#pragma unroll 1
    for (int it = 0; it < 8; it++) {
        int cur = it & 1;
        int nxt = cur ^ 1;
        if (it < 7) {
            issueB((it + 1) * 32, nxt);
            loadA((it + 1) * 32);
        }
        {
            const uint32_t* ahi = sm + cur * 2 * A_SZ;
            const uint32_t* alo = ahi + A_SZ;
            const uint32_t* bhi = sm + B_BASE + cur * 2 * B_SZ;
            const uint32_t* blo = bhi + B_SZ;
#pragma unroll
            for (int s = 0; s < 2; s++) {
                int kb = s * 8 + (lane & 3);
                uint32_t ah[2][4], al[2][4];
#pragma unroll
                for (int i = 0; i < 2; i++) {
                    int m = wr * 32 + i * 16 + (lane >> 2);
                    ah[i][0] = ahi[kb * 72 + m];       ah[i][1] = ahi[kb * 72 + m + 8];
                    ah[i][2] = ahi[(kb + 4) * 72 + m]; ah[i][3] = ahi[(kb + 4) * 72 + m + 8];
                    al[i][0] = alo[kb * 72 + m];       al[i][1] = alo[kb * 72 + m + 8];
                    al[i][2] = alo[(kb + 4) * 72 + m]; al[i][3] = alo[(kb + 4) * 72 + m + 8];
                }
#pragma unroll
                for (int j = 0; j < 8; j++) {
                    int n = wc * 64 + j * 8 + (lane >> 2);
                    uint32_t bh0 = bhi[kb * 264 + n], bh1 = bhi[(kb + 4) * 264 + n];
                    uint32_t bl0 = blo[kb * 264 + n], bl1 = blo[(kb + 4) * 264 + n];
#pragma unroll
                    for (int i = 0; i < 2; i++) {
                        mma_bf16(acc[i][j], ah[i], bh0, bh1);
                        mma_bf16(acc[i][j], ah[i], bl0, bl1);
                        mma_bf16(acc[i][j], al[i], bh0, bh1);
                    }
                }
            }
        }
        if (it < 7) {
            storeA(nxt);
            cp_wait0();
        }
        __syncthreads();
    }

#pragma unroll
    for (int j = 0; j < 8; j++) {
        int gc = wc * 64 + j * 8 + (lane & 3) * 2;
        float bx = __ldg(&bias[gc]);
        float by = __ldg(&bias[gc + 1]);
        float sx = 0.f, sy = 0.f, qx = 0.f, qy = 0.f;
#pragma unroll
        for (int i = 0; i < 2; i++) {
            int gr = row0 + wr * 32 + i * 16 + (lane >> 2);
            if (gr < M) {
                float2 v0 = make_float2(acc[i][j][0] + bx, acc[i][j][1] + by);
                *(float2*)(C + (size_t)gr * DD + gc) = v0;
                sx += v0.x; sy += v0.y; qx += v0.x * v0.x; qy += v0.y * v0.y;
            }
            if (gr + 8 < M) {
                float2 v1 = make_float2(acc[i][j][2] + bx, acc[i][j][3] + by);
                *(float2*)(C + (size_t)(gr + 8) * DD + gc) = v1;
                sx += v1.x; sy += v1.y; qx += v1.x * v1.x; qy += v1.y * v1.y;
            }
        }
#pragma unroll
        for (int d = 4; d < 32; d <<= 1) {
            sx += __shfl_xor_sync(0xffffffff, sx, d);
            sy += __shfl_xor_sync(0xffffffff, sy, d);
            qx += __shfl_xor_sync(0xffffffff, qx, d);
            qy += __shfl_xor_sync(0xffffffff, qy, d);
        }
        if ((lane >> 2) == 0) {
            red2(&stats[gc], sx, sy);
            red2(&stats[DD + gc], qx, qy);
        }
    }
}

// ---------------- small GEMM: BM=64, BN=128 (grid.y=2), 256 threads ----------------
template <int MODE>
__global__ void __launch_bounds__(256, 2)
k_gemm_small(const float* __restrict__ A, const float* __restrict__ A2,
             const uint32_t* __restrict__ Whi, const uint32_t* __restrict__ Wlo,
             const float* __restrict__ bias, float* __restrict__ C, int M,
             float* __restrict__ stats, const float* __restrict__ bnp) {
    __shared__ uint32_t As_hi[16][72];
    __shared__ uint32_t As_lo[16][72];
    __shared__ uint32_t Bs_hi[16][136];
    __shared__ uint32_t Bs_lo[16][136];

    int tid = threadIdx.x;
    int lane = tid & 31;
    int wid = tid >> 5;
    int wr = wid >> 1;
    int wc = wid & 1;
    int row0 = blockIdx.x * 64;
    int col0 = blockIdx.y * 128;

    float acc[8][4];
#pragma unroll
    for (int j = 0; j < 8; j++)
#pragma unroll
        for (int r = 0; r < 4; r++) acc[j][r] = 0.f;

    for (int k0 = 0; k0 < DD; k0 += 32) {
#pragma unroll
        for (int q = 0; q < 2; q++) {
            int li = tid + q * 256;
            int r = li >> 3;
            int kk = (li & 7) * 4;
            float4 v = make_float4(0.f, 0.f, 0.f, 0.f);
            int gr = row0 + r;
            if (gr < M) v = load_a4<MODE>(A, A2, bnp, 0.f, (size_t)gr * DD + k0 + kk, k0 + kk);
            int k2 = kk >> 1;
            uint32_t h0, l0, h1, l1;
            split_pack(v.x, v.y, h0, l0);
            split_pack(v.z, v.w, h1, l1);
            As_hi[k2][r] = h0;     As_lo[k2][r] = l0;
            As_hi[k2 + 1][r] = h1; As_lo[k2 + 1][r] = l1;
        }
        {
            const uint32_t* wh = Whi + (size_t)(k0 >> 1) * DD + col0;
            const uint32_t* wl = Wlo + (size_t)(k0 >> 1) * DD + col0;
#pragma unroll
            for (int q = 0; q < 2; q++) {
                int li = tid + q * 256;
                int r = li >> 5;
                int n4 = (li & 31) * 4;
                *(uint4*)&Bs_hi[r][n4] = *(const uint4*)(wh + (size_t)r * DD + n4);
                *(uint4*)&Bs_lo[r][n4] = *(const uint4*)(wl + (size_t)r * DD + n4);
            }
        }
        __syncthreads();

#pragma unroll
        for (int s = 0; s < 2; s++) {
            int kb = s * 8 + (lane & 3);
            int m = wr * 16 + (lane >> 2);
            uint32_t ah[4], al[4];
            ah[0] = As_hi[kb][m];     ah[1] = As_hi[kb][m + 8];
            ah[2] = As_hi[kb + 4][m]; ah[3] = As_hi[kb + 4][m + 8];
            al[0] = As_lo[kb][m];     al[1] = As_lo[kb][m + 8];
            al[2] = As_lo[kb + 4][m]; al[3] = As_lo[kb + 4][m + 8];
#pragma unroll
            for (int j = 0; j < 8; j++) {
                int n = wc * 64 + j * 8 + (lane >> 2);
                uint32_t bh0 = Bs_hi[kb][n], bh1 = Bs_hi[kb + 4][n];
                uint32_t bl0 = Bs_lo[kb][n], bl1 = Bs_lo[kb + 4][n];
                mma_bf16(acc[j], ah, bh0, bh1);
                mma_bf16(acc[j], ah, bl0, bl1);
                mma_bf16(acc[j], al, bh0, bh1);
            }
        }
        __syncthreads();
    }

#pragma unroll
    for (int j = 0; j < 8; j++) {
        int gc = col0 + wc * 64 + j * 8 + (lane & 3) * 2;
        float bx = __ldg(&bias[gc]);
        float by = __ldg(&bias[gc + 1]);
        float sx = 0.f, sy = 0.f, qx = 0.f, qy = 0.f;
        int gr = row0 + wr * 16 + (lane >> 2);
        if (gr < M) {
            float2 v0 = make_float2(acc[j][0] + bx, acc[j][1] + by);
            *(float2*)(C + (size_t)gr * DD + gc) = v0;
            sx += v0.x; sy += v0.y; qx += v0.x * v0.x; qy += v0.y * v0.y;
        }
        if (gr + 8 < M) {
            float2 v1 = make_float2(acc[j][2] + bx, acc[j][3] + by);
            *(float2*)(C + (size_t)(gr + 8) * DD + gc) = v1;
            sx += v1.x; sy += v1.y; qx += v1.x * v1.x; qy += v1.y * v1.y;
        }
#pragma unroll
        for (int d = 4; d < 32; d <<= 1) {
            sx += __shfl_xor_sync(0xffffffff, sx, d);
            sy += __shfl_xor_sync(0xffffffff, sy, d);
            qx += __shfl_xor_sync(0xffffffff, qx, d);
            qy += __shfl_xor_sync(0xffffffff, qy, d);
        }
        if ((lane >> 2) == 0) {
            red2(&stats[gc], sx, sy);
            red2(&stats[DD + gc], qx, qy);
        }
    }
}

// ---------------- BN prep / apply (pointer-parameterized) ----------------
__global__ void k_bn_prep(float* __restrict__ stats, float* __restrict__ bnp,
                          const float* __restrict__ gamma, const float* __restrict__ beta,
                          float Minv) {
    int c = threadIdx.x;
    float m = stats[c] * Minv;
    float var = stats[DD + c] * Minv - m * m;
    float rs = rsqrtf(var + BN_EPS);
    float sc = gamma[c] * rs;
    bnp[c] = sc;
    bnp[DD + c] = beta[c] - m * sc;
    stats[c] = 0.f;
    stats[DD + c] = 0.f;
}

__global__ void k_bn_apply(const float* __restrict__ Yin, float* __restrict__ Yout,
                           const float* __restrict__ bnp, const int* __restrict__ batch,
                           int M, int do_relu, int do_vn, int do_pool) {
    int idx = blockIdx.x * blockDim.x + threadIdx.x;
    if (idx >= M * 64) return;
    int r = idx >> 6;
    int c4 = (idx & 63) * 4;
    float4 sc = *(const float4*)(bnp + c4);
    float4 sh = *(const float4*)(bnp + DD + c4);
    float4 v = *(const float4*)(Yin + (size_t)r * DD + c4);
    v.x = v.x * sc.x + sh.x;
    v.y = v.y * sc.y + sh.y;
    v.z = v.z * sc.z + sh.z;
    v.w = v.w * sc.w + sh.w;
    if (do_relu) {
        v.x = fmaxf(v.x, 0.f); v.y = fmaxf(v.y, 0.f);
        v.z = fmaxf(v.z, 0.f); v.w = fmaxf(v.w, 0.f);
    }
    int g = 0;
    if (do_vn || do_pool) g = __ldg(&batch[r]);
    if (do_vn) {
        float4 w = *(const float4*)(g_vn + (size_t)g * DD + c4);
        v.x += w.x; v.y += w.y; v.z += w.z; v.w += w.w;
    }
    *(float4*)(Yout + (size_t)r * DD + c4) = v;
    if (do_pool) red4(g_pooled + (size_t)g * DD + c4, v.x, v.y, v.z, v.w);
}

// ---------------- host orchestration ----------------
extern "C" void kernel_launch(void* const* d_in, const int* in_sizes, int n_in,
                              void* d_out, int out_size) {
    const int* x          = (const int*)d_in[0];
    const int* edge_index = (const int*)d_in[1];
    const int* edge_attr  = (const int*)d_in[2];
    const int* batch      = (const int*)d_in[3];
    const float* atom_emb = (const float*)d_in[4];
    const float* bond_emb = (const float*)d_in[5];
    const float* vn_emb   = (const float*)d_in[6];
    const float* gin_eps  = (const float*)d_in[7];
    const float* conv_W1  = (const float*)d_in[8];
    const float* conv_b1  = (const float*)d_in[9];
    const float* conv_bn_g = (const float*)d_in[10];
    const float* conv_bn_b = (const float*)d_in[11];
    const float* conv_W2  = (const float*)d_in[12];
    const float* conv_b2  = (const float*)d_in[13];
    const float* outer_bn_g = (const float*)d_in[14];
    const float* outer_bn_b = (const float*)d_in[15];
    const float* vn_W1    = (const float*)d_in[16];
    const float* vn_b1    = (const float*)d_in[17];
    const float* vn_bn1_g = (const float*)d_in[18];
    const float* vn_bn1_b = (const float*)d_in[19];
    const float* vn_W2    = (const float*)d_in[20];
    const float* vn_b2    = (const float*)d_in[21];
    const float* vn_bn2_g = (const float*)d_in[22];
    const float* vn_bn2_b = (const float*)d_in[23];
    float* out = (float*)d_out;

    cudaFuncSetAttribute(k_gemm_big<1>, cudaFuncAttributeMaxDynamicSharedMemorySize, SMEM_BIG);
    cudaFuncSetAttribute(k_gemm_big<2>, cudaFuncAttributeMaxDynamicSharedMemorySize, SMEM_BIG);

    float *p_agg, *p_t, *p_y, *p_pooled, *p_vt, *p_vt2, *p_vn;
    float *p_stats, *p_bnp, *p_stats_v, *p_bnp_v;
    uint32_t *p_whi, *p_wlo;
    cudaGetSymbolAddress((void**)&p_agg, g_agg);
    cudaGetSymbolAddress((void**)&p_t, g_t);
    cudaGetSymbolAddress((void**)&p_y, g_y);
    cudaGetSymbolAddress((void**)&p_pooled, g_pooled);
    cudaGetSymbolAddress((void**)&p_vt, g_vt);
    cudaGetSymbolAddress((void**)&p_vt2, g_vt2);
    cudaGetSymbolAddress((void**)&p_vn, g_vn);
    cudaGetSymbolAddress((void**)&p_stats, g_stats);
    cudaGetSymbolAddress((void**)&p_bnp, g_bnp);
    cudaGetSymbolAddress((void**)&p_stats_v, g_stats_v);
    cudaGetSymbolAddress((void**)&p_bnp_v, g_bnp_v);
    cudaGetSymbolAddress((void**)&p_whi, g_whi);
    cudaGetSymbolAddress((void**)&p_wlo, g_wlo);

    const size_t slot = (size_t)NN * DD;
    const size_t wslot = (size_t)128 * DD;
    const int blkN = (NN * 64 + 255) / 256;
    const float invN = 1.0f / (float)NN;
    const float invG = 1.0f / (float)GG;

    cudaStream_t sv;
    cudaStreamCreateWithFlags(&sv, cudaStreamNonBlocking);
    cudaEvent_t ev_start, ev_pre, ev_fork[LL], ev_join[LL];
    cudaEventCreateWithFlags(&ev_start, cudaEventDisableTiming);
    cudaEventCreateWithFlags(&ev_pre, cudaEventDisableTiming);
    for (int l = 0; l < LL; l++) {
        cudaEventCreateWithFlags(&ev_fork[l], cudaEventDisableTiming);
        cudaEventCreateWithFlags(&ev_join[l], cudaEventDisableTiming);
    }

    // ---- prologue fork: CSR build + stats zeros + weight splits on sv,
    //      encoders / lut / pooled-zero / vn_init on main ----
    cudaEventRecord(ev_start, 0);
    cudaStreamWaitEvent(sv, ev_start, 0);

    // sv chain
    k_zero_off<<<(NN + 2 + 255) / 256, 256, 0, sv>>>();
    k_hist<<<(EE + 255) / 256, 256, 0, sv>>>(edge_index);
    k_scan<<<1, SCAN_T, 0, sv>>>();
    k_scatter_e<<<(EE + 255) / 256, 256, 0, sv>>>(edge_index, edge_attr);
    k_zero<<<1, 128, 0, sv>>>(p_stats, 128);
    k_zero<<<1, 128, 0, sv>>>(p_stats_v, 128);
    const int wgrid = (128 * DD + 255) / 256;
    for (int l = 0; l < LL; l++) {
        k_split_w<<<wgrid, 256, 0, sv>>>(conv_W1 + (size_t)l * DD * DD,
                                         p_whi + (size_t)l * wslot, p_wlo + (size_t)l * wslot);
        k_split_w<<<wgrid, 256, 0, sv>>>(conv_W2 + (size_t)l * DD * DD,
                                         p_whi + (size_t)(5 + l) * wslot,
                                         p_wlo + (size_t)(5 + l) * wslot);
    }
    for (int l = 0; l < LL - 1; l++) {
        k_split_w<<<wgrid, 256, 0, sv>>>(vn_W1 + (size_t)l * DD * DD,
                                         p_whi + (size_t)(10 + l) * wslot,
                                         p_wlo + (size_t)(10 + l) * wslot);
        k_split_w<<<wgrid, 256, 0, sv>>>(vn_W2 + (size_t)l * DD * DD,
                                         p_whi + (size_t)(14 + l) * wslot,
                                         p_wlo + (size_t)(14 + l) * wslot);
    }
    cudaEventRecord(ev_pre, sv);

    // main chain
    k_zero<<<(GG * 64 + 255) / 256, 256>>>(p_pooled, GG * 64);
    k_build_lut<<<(216 * 64 + 255) / 256, 256>>>(bond_emb);
    k_encode_atoms<<<blkN, 256>>>(x, atom_emb, vn_emb, batch, out);
    k_vn_init<<<(GG * DD + 255) / 256, 256>>>(vn_emb);
    cudaStreamWaitEvent(0, ev_pre, 0);   // k_agg needs CSR; GEMMs need whi/wlo

    const int gBig = (NN + BM - 1) / BM;
    const dim3 gSmall((GG + 63) / 64, 2);
    const int gAgg = (NN * 32 + 255) / 256;

    for (int l = 0; l < LL; l++) {
        float* h = out + (size_t)l * slot;            // h_in^l (vn already added)
        float* z_out = out + (size_t)(l + 1) * slot;

        // vn chain on sv, concurrent with k_agg + big GEMMs
        if (l < LL - 1) {
            cudaEventRecord(ev_fork[l], 0);
            cudaStreamWaitEvent(sv, ev_fork[l], 0);
            k_gemm_small<3><<<gSmall, 256, 0, sv>>>(p_pooled, p_vn,
                                                    p_whi + (size_t)(10 + l) * wslot,
                                                    p_wlo + (size_t)(10 + l) * wslot,
                                                    vn_b1 + l * DD, p_vt, GG,
                                                    p_stats_v, nullptr);
            k_zero<<<(GG * 64 + 255) / 256, 256, 0, sv>>>(p_pooled, GG * 64);
            k_bn_prep<<<1, 256, 0, sv>>>(p_stats_v, p_bnp_v,
                                         vn_bn1_g + l * DD, vn_bn1_b + l * DD, invG);
            k_gemm_small<2><<<gSmall, 256, 0, sv>>>(p_vt, nullptr,
                                                    p_whi + (size_t)(14 + l) * wslot,
                                                    p_wlo + (size_t)(14 + l) * wslot,
                                                    vn_b2 + l * DD, p_vt2, GG,
                                                    p_stats_v, p_bnp_v);
            k_bn_prep<<<1, 256, 0, sv>>>(p_stats_v, p_bnp_v,
                                         vn_bn2_g + l * DD, vn_bn2_b + l * DD, invG);
            k_bn_apply<<<(GG * 64 + 255) / 256, 256, 0, sv>>>(p_vt2, p_vn, p_bnp_v,
                                                              nullptr, GG, 1, 0, 0);
            cudaEventRecord(ev_join[l], sv);
        }

        // main path
        k_agg<<<gAgg, 256>>>(h);
        k_gemm_big<1><<<gBig, 256, SMEM_BIG>>>(h, p_agg, gin_eps + l,
                                               p_whi + (size_t)l * wslot,
                                               p_wlo + (size_t)l * wslot,
                                               conv_b1 + l * DD, p_y, NN,
                                               p_stats, nullptr);
        k_bn_prep<<<1, 256>>>(p_stats, p_bnp, conv_bn_g + l * DD, conv_bn_b + l * DD, invN);
        k_gemm_big<2><<<gBig, 256, SMEM_BIG>>>(p_y, nullptr, nullptr,
                                               p_whi + (size_t)(5 + l) * wslot,
                                               p_wlo + (size_t)(5 + l) * wslot,
                                               conv_b2 + l * DD, p_t, NN,
                                               p_stats, p_bnp);
        k_bn_prep<<<1, 256>>>(p_stats, p_bnp, outer_bn_g + l * DD, outer_bn_b + l * DD, invN);
        // final BN apply needs new vn (and pooled zeroed) -> join
        if (l < LL - 1) cudaStreamWaitEvent(0, ev_join[l], 0);
        int relu = (l < LL - 1) ? 1 : 0;
        int vnadd = (l < LL - 1) ? 1 : 0;
        int pool = (l < LL - 2) ? 1 : 0;
        k_bn_apply<<<blkN, 256>>>(p_t, z_out, p_bnp, batch, NN, relu, vnadd, pool);
    }
}

// round 12
// speedup vs baseline: 1.1021x; 1.0272x over previous
#include <cuda_runtime.h>
#include <cuda_bf16.h>
#include <cstdint>

#define NN 100000
#define EE 300000
#define GG 4096
#define DD 256
#define LL 5
#define BN_EPS 1e-5f
#define NW 18

// ---------------- scratch (device globals; no allocations) ----------------
__device__ int g_off[NN + 2];                      // CSR offsets (by dst)
__device__ int g_cur[NN];                          // scatter cursors
__device__ uint32_t g_epack[EE];                   // src*256 + bondcode, dst-sorted
__device__ float g_lut[216 * DD];                  // bond-embedding LUT (fp32)
__device__ float g_t[(size_t)NN * DD];             // z / gemm2 out
__device__ float g_y[(size_t)NN * DD];             // gemm1 out
__device__ float g_vn[(size_t)GG * DD];            // virtual node state
__device__ float g_pooled[(size_t)GG * DD];        // raw pooled sum
__device__ float g_vt[(size_t)GG * DD];
__device__ float g_vt2[(size_t)GG * DD];
__device__ float g_stats[2 * DD];                  // big-path column sum / sumsq
__device__ float g_bnp[2 * DD];                    // big-path bn scale / shift
__device__ float g_stats_v[2 * DD];                // vn-path column sum / sumsq
__device__ float g_bnp_v[2 * DD];                  // vn-path bn scale / shift
__device__ uint32_t g_whi[(size_t)NW * 128 * DD];  // pre-split W (bf16 hi)
__device__ uint32_t g_wlo[(size_t)NW * 128 * DD];  // pre-split W (bf16 lo)

__device__ __forceinline__ void red2(float* p, float a, float b) {
    asm volatile("red.global.add.v2.f32 [%0], {%1,%2};" :: "l"(p), "f"(a), "f"(b) : "memory");
}
__device__ __forceinline__ void red4(float* p, float a, float b, float c, float d) {
    asm volatile("red.global.add.v4.f32 [%0], {%1,%2,%3,%4};"
                 :: "l"(p), "f"(a), "f"(b), "f"(c), "f"(d) : "memory");
}
__device__ __forceinline__ void cp16(uint32_t smem_addr, const void* g) {
    asm volatile("cp.async.cg.shared.global [%0], [%1], 16;" :: "r"(smem_addr), "l"(g));
}
__device__ __forceinline__ void cp_commit() {
    asm volatile("cp.async.commit_group;");
}
__device__ __forceinline__ void cp_wait0() {
    asm volatile("cp.async.wait_group 0;");
}

__device__ __forceinline__ uint32_t pack_bf2(float a, float b) {
    __nv_bfloat162 t = __floats2bfloat162_rn(a, b);
    return *(uint32_t*)&t;
}
__device__ __forceinline__ void split_pack(float a, float b, uint32_t& hi, uint32_t& lo) {
    __nv_bfloat16 ah = __float2bfloat16_rn(a);
    __nv_bfloat16 bh = __float2bfloat16_rn(b);
    float al = a - __bfloat162float(ah);
    float bl = b - __bfloat162float(bh);
    __nv_bfloat162 h2; h2.x = ah; h2.y = bh;
    hi = *(uint32_t*)&h2;
    lo = pack_bf2(al, bl);
}

// ---------------- small kernels ----------------
__global__ void k_zero(float* p, int n4) {
    int i = blockIdx.x * blockDim.x + threadIdx.x;
    if (i < n4) ((float4*)p)[i] = make_float4(0.f, 0.f, 0.f, 0.f);
}
__global__ void k_zero_off() {
    int i = blockIdx.x * blockDim.x + threadIdx.x;
    if (i < NN + 2) g_off[i] = 0;
}

__global__ void k_split_w(const float* __restrict__ W, uint32_t* __restrict__ hi,
                          uint32_t* __restrict__ lo) {
    int i = blockIdx.x * blockDim.x + threadIdx.x;
    if (i >= 128 * DD) return;
    int k2 = i >> 8, n = i & 255;
    float a = W[(size_t)(2 * k2) * DD + n];
    float b = W[(size_t)(2 * k2 + 1) * DD + n];
    split_pack(a, b, hi[i], lo[i]);
}

__global__ void k_build_lut(const float* __restrict__ bond_emb) {
    int idx = blockIdx.x * blockDim.x + threadIdx.x;
    if (idx >= 216 * 64) return;
    int c = idx >> 6;
    int d4 = (idx & 63) * 4;
    int v0 = c / 36, v1 = (c / 6) % 6, v2 = c % 6;
    float4 a = *(const float4*)(bond_emb + ((size_t)(0 * 6 + v0) * DD + d4));
    float4 b = *(const float4*)(bond_emb + ((size_t)(1 * 6 + v1) * DD + d4));
    float4 d = *(const float4*)(bond_emb + ((size_t)(2 * 6 + v2) * DD + d4));
    *(float4*)(g_lut + (size_t)c * DD + d4) =
        make_float4(a.x + b.x + d.x, a.y + b.y + d.y, a.z + b.z + d.z, a.w + b.w + d.w);
}

// ---- CSR build ----
__global__ void k_hist(const int* __restrict__ ei) {
    int e = blockIdx.x * blockDim.x + threadIdx.x;
    if (e < EE) atomicAdd(&g_off[ei[EE + e]], 1);
}

#define SCAN_T 1024
#define SCAN_CH 98   // ceil(NN / 1024)
__global__ void k_scan() {
    __shared__ int ssum[SCAN_T];
    int t = threadIdx.x;
    int begin = t * SCAN_CH;
    int end = min(NN, begin + SCAN_CH);
    int s = 0;
    for (int i = begin; i < end; i++) s += g_off[i];
    ssum[t] = s;
    __syncthreads();
    for (int d = 1; d < SCAN_T; d <<= 1) {
        int v = (t >= d) ? ssum[t - d] : 0;
        __syncthreads();
        ssum[t] += v;
        __syncthreads();
    }
    int run = ssum[t] - s;  // exclusive prefix
    for (int i = begin; i < end; i++) {
        int c = g_off[i];
        g_off[i] = run;
        g_cur[i] = run;
        run += c;
    }
    if (t == SCAN_T - 1) g_off[NN] = ssum[SCAN_T - 1];
}

__global__ void k_scatter_e(const int* __restrict__ ei, const int* __restrict__ ea_idx) {
    int e = blockIdx.x * blockDim.x + threadIdx.x;
    if (e >= EE) return;
    int dst = ei[EE + e];
    int src = ei[e];
    int code = ea_idx[e * 3 + 0] * 36 + ea_idx[e * 3 + 1] * 6 + ea_idx[e * 3 + 2];
    int pos = atomicAdd(&g_cur[dst], 1);
    g_epack[pos] = (uint32_t)src * 256u + (uint32_t)code;
}

// CSR aggregation fused with gin_combine: writes z = (1+eps)*h[node] + sum relu(h[src]+lut)
__global__ void __launch_bounds__(256)
k_agg(const float* __restrict__ h, const float* __restrict__ epsp) {
    int gw = (blockIdx.x * 256 + threadIdx.x) >> 5;
    if (gw >= NN) return;
    int lane = threadIdx.x & 31;
    int base = lane * 8;
    float e = 1.0f + __ldg(epsp);
    float acc[8] = {0.f, 0.f, 0.f, 0.f, 0.f, 0.f, 0.f, 0.f};
    int p0 = g_off[gw], p1 = g_off[gw + 1];
    for (int p = p0; p < p1; p++) {
        uint32_t pk = __ldg(&g_epack[p]);
        const float* hr = h + (size_t)(pk >> 8) * DD + base;
        const float* lr = g_lut + (size_t)(pk & 255u) * DD + base;
        float4 h0 = *(const float4*)hr;
        float4 h1 = *(const float4*)(hr + 4);
        float4 l0 = *(const float4*)lr;
        float4 l1 = *(const float4*)(lr + 4);
        acc[0] += fmaxf(h0.x + l0.x, 0.f);
        acc[1] += fmaxf(h0.y + l0.y, 0.f);
        acc[2] += fmaxf(h0.z + l0.z, 0.f);
        acc[3] += fmaxf(h0.w + l0.w, 0.f);
        acc[4] += fmaxf(h1.x + l1.x, 0.f);
        acc[5] += fmaxf(h1.y + l1.y, 0.f);
        acc[6] += fmaxf(h1.z + l1.z, 0.f);
        acc[7] += fmaxf(h1.w + l1.w, 0.f);
    }
    const float* hn = h + (size_t)gw * DD + base;
    float4 s0 = *(const float4*)hn;
    float4 s1 = *(const float4*)(hn + 4);
    float* o = g_t + (size_t)gw * DD + base;
    *(float4*)o = make_float4(e * s0.x + acc[0], e * s0.y + acc[1],
                              e * s0.z + acc[2], e * s0.w + acc[3]);
    *(float4*)(o + 4) = make_float4(e * s1.x + acc[4], e * s1.y + acc[5],
                                    e * s1.z + acc[6], e * s1.w + acc[7]);
}

// atom encoder: h0 = sum emb + vn0; also scatter h0 row into pooled
__global__ void k_encode_atoms(const int* __restrict__ x,
                               const float* __restrict__ atom_emb,
                               const float* __restrict__ vn_emb,
                               const int* __restrict__ batch,
                               float* __restrict__ out0) {
    int idx = blockIdx.x * blockDim.x + threadIdx.x;
    if (idx >= NN * 64) return;
    int n = idx >> 6;
    int d4 = (idx & 63) * 4;
    float4 acc = *(const float4*)(vn_emb + d4);
#pragma unroll
    for (int f = 0; f < 9; f++) {
        int v = __ldg(&x[n * 9 + f]);
        float4 e = *(const float4*)(atom_emb + ((size_t)(f * 120 + v) * DD + d4));
        acc.x += e.x; acc.y += e.y; acc.z += e.z; acc.w += e.w;
    }
    *(float4*)(out0 + (size_t)n * DD + d4) = acc;
    int g = __ldg(&batch[n]);
    red4(g_pooled + (size_t)g * DD + d4, acc.x, acc.y, acc.z, acc.w);
}

__global__ void k_vn_init(const float* __restrict__ vn_emb) {
    int i = blockIdx.x * blockDim.x + threadIdx.x;
    if (i < GG * DD) g_vn[i] = vn_emb[i & (DD - 1)];
}

// ---------------- GEMM common ----------------
__device__ __forceinline__ void mma_bf16(float* c, const uint32_t* a, uint32_t b0, uint32_t b1) {
    asm volatile(
        "mma.sync.aligned.m16n8k16.row.col.f32.bf16.bf16.f32 "
        "{%0,%1,%2,%3}, {%4,%5,%6,%7}, {%8,%9}, {%0,%1,%2,%3};"
        : "+f"(c[0]), "+f"(c[1]), "+f"(c[2]), "+f"(c[3])
        : "r"(a[0]), "r"(a[1]), "r"(a[2]), "r"(a[3]), "r"(b0), "r"(b1));
}

// MODE 0: A as-is.  MODE 2: A=relu(y*scale+shift).  MODE 3: A=A+A2.
template <int MODE>
__device__ __forceinline__ float4 load_a4(const float* A, const float* A2,
                                          const float* bnp, size_t off, int kidx) {
    float4 v;
    if (MODE == 0) {
        v = *(const float4*)(A + off);
    } else if (MODE == 2) {
        float4 yv = *(const float4*)(A + off);
        float4 sc = *(const float4*)(bnp + kidx);
        float4 sh = *(const float4*)(bnp + DD + kidx);
        v.x = fmaxf(yv.x * sc.x + sh.x, 0.f);
        v.y = fmaxf(yv.y * sc.y + sh.y, 0.f);
        v.z = fmaxf(yv.z * sc.z + sh.z, 0.f);
        v.w = fmaxf(yv.w * sc.w + sh.w, 0.f);
    } else {
        float4 hv = *(const float4*)(A + off);
        float4 av = *(const float4*)(A2 + off);
        v.x = hv.x + av.x; v.y = hv.y + av.y;
        v.z = hv.z + av.z; v.w = hv.w + av.w;
    }
    return v;
}

// ---------------- big GEMM: BM=64, BN=256, BK=32, 256 threads, occ 2 ----
// double-buffered pipeline: B via cp.async, A via register prefetch; 1 sync/iter
#define BM 64
#define A_SZ 1152               // 16 * 72 u32
#define B_SZ 4224               // 16 * 264 u32
#define B_BASE (4 * A_SZ)
#define SMEM_BIG ((4 * A_SZ + 4 * B_SZ) * 4)

template <int MODE>
__global__ void __launch_bounds__(256, 2)
k_gemm_big(const float* __restrict__ A, const float* __restrict__ A2,
           const uint32_t* __restrict__ Whi, const uint32_t* __restrict__ Wlo,
           const float* __restrict__ bias, float* __restrict__ C, int M,
           float* __restrict__ stats, const float* __restrict__ bnp) {
    extern __shared__ uint32_t sm[];
    const uint32_t sbase = (uint32_t)__cvta_generic_to_shared(sm);

    int tid = threadIdx.x;
    int lane = tid & 31;
    int wid = tid >> 5;
    int wr = wid >> 2;
    int wc = wid & 3;
    int row0 = blockIdx.x * BM;

    const int ar0 = tid >> 3;
    const int akk = (tid & 7) * 4;
    const int br = tid >> 6;
    const int bn4 = (tid & 63) * 4;

    float acc[2][8][4];
#pragma unroll
    for (int i = 0; i < 2; i++)
#pragma unroll
        for (int j = 0; j < 8; j++)
#pragma unroll
            for (int r = 0; r < 4; r++) acc[i][j][r] = 0.f;

    float4 vA[2];

    auto issueB = [&](int k0, int buf) {
        const uint32_t* wh = Whi + (size_t)(k0 >> 1) * DD;
        const uint32_t* wl = Wlo + (size_t)(k0 >> 1) * DD;
        uint32_t bhi = sbase + (B_BASE + buf * 2 * B_SZ) * 4;
        uint32_t blo = bhi + B_SZ * 4;
#pragma unroll
        for (int q = 0; q < 4; q++) {
            int r = br + q * 4;
            cp16(bhi + (r * 264 + bn4) * 4, wh + (size_t)r * DD + bn4);
            cp16(blo + (r * 264 + bn4) * 4, wl + (size_t)r * DD + bn4);
        }
        cp_commit();
    };
    auto loadA = [&](int k0) {
#pragma unroll
        for (int q = 0; q < 2; q++) {
            int gr = row0 + ar0 + q * 32;
            vA[q] = make_float4(0.f, 0.f, 0.f, 0.f);
            if (gr < M) vA[q] = load_a4<MODE>(A, A2, bnp, (size_t)gr * DD + k0 + akk, k0 + akk);
        }
    };
    auto storeA = [&](int buf) {
        uint32_t* ahi = sm + buf * 2 * A_SZ;
        uint32_t* alo = ahi + A_SZ;
        int k2 = akk >> 1;
#pragma unroll
        for (int q = 0; q < 2; q++) {
            int r = ar0 + q * 32;
            uint32_t h0, l0, h1, l1;
            split_pack(vA[q].x, vA[q].y, h0, l0);
            split_pack(vA[q].z, vA[q].w, h1, l1);
            ahi[k2 * 72 + r] = h0;       alo[k2 * 72 + r] = l0;
            ahi[(k2 + 1) * 72 + r] = h1; alo[(k2 + 1) * 72 + r] = l1;
        }
    };

    issueB(0, 0);
    loadA(0);
    storeA(0);
    cp_wait0();
    __syncthreads();

#pragma unroll 1
    for (int it = 0; it < 8; it++) {
        int cur = it & 1;
        int nxt = cur ^ 1;
        if (it < 7) {
            issueB((it + 1) * 32, nxt);
            loadA((it + 1) * 32);
        }
        {
            const uint32_t* ahi = sm + cur * 2 * A_SZ;
            const uint32_t* alo = ahi + A_SZ;
            const uint32_t* bhi = sm + B_BASE + cur * 2 * B_SZ;
            const uint32_t* blo = bhi + B_SZ;
#pragma unroll
            for (int s = 0; s < 2; s++) {
                int kb = s * 8 + (lane & 3);
                uint32_t ah[2][4], al[2][4];
#pragma unroll
                for (int i = 0; i < 2; i++) {
                    int m = wr * 32 + i * 16 + (lane >> 2);
                    ah[i][0] = ahi[kb * 72 + m];       ah[i][1] = ahi[kb * 72 + m + 8];
                    ah[i][2] = ahi[(kb + 4) * 72 + m]; ah[i][3] = ahi[(kb + 4) * 72 + m + 8];
                    al[i][0] = alo[kb * 72 + m];       al[i][1] = alo[kb * 72 + m + 8];
                    al[i][2] = alo[(kb + 4) * 72 + m]; al[i][3] = alo[(kb + 4) * 72 + m + 8];
                }
#pragma unroll
                for (int j = 0; j < 8; j++) {
                    int n = wc * 64 + j * 8 + (lane >> 2);
                    uint32_t bh0 = bhi[kb * 264 + n], bh1 = bhi[(kb + 4) * 264 + n];
                    uint32_t bl0 = blo[kb * 264 + n], bl1 = blo[(kb + 4) * 264 + n];
#pragma unroll
                    for (int i = 0; i < 2; i++) {
                        mma_bf16(acc[i][j], ah[i], bh0, bh1);
                        mma_bf16(acc[i][j], ah[i], bl0, bl1);
                        mma_bf16(acc[i][j], al[i], bh0, bh1);
                    }
                }
            }
        }
        if (it < 7) {
            storeA(nxt);
            cp_wait0();
        }
        __syncthreads();
    }

#pragma unroll
    for (int j = 0; j < 8; j++) {
        int gc = wc * 64 + j * 8 + (lane & 3) * 2;
        float bx = __ldg(&bias[gc]);
        float by = __ldg(&bias[gc + 1]);
        float sx = 0.f, sy = 0.f, qx = 0.f, qy = 0.f;
#pragma unroll
        for (int i = 0; i < 2; i++) {
            int gr = row0 + wr * 32 + i * 16 + (lane >> 2);
            if (gr < M) {
                float2 v0 = make_float2(acc[i][j][0] + bx, acc[i][j][1] + by);
                *(float2*)(C + (size_t)gr * DD + gc) = v0;
                sx += v0.x; sy += v0.y; qx += v0.x * v0.x; qy += v0.y * v0.y;
            }
            if (gr + 8 < M) {
                float2 v1 = make_float2(acc[i][j][2] + bx, acc[i][j][3] + by);
                *(float2*)(C + (size_t)(gr + 8) * DD + gc) = v1;
                sx += v1.x; sy += v1.y; qx += v1.x * v1.x; qy += v1.y * v1.y;
            }
        }
#pragma unroll
        for (int d = 4; d < 32; d <<= 1) {
            sx += __shfl_xor_sync(0xffffffff, sx, d);
            sy += __shfl_xor_sync(0xffffffff, sy, d);
            qx += __shfl_xor_sync(0xffffffff, qx, d);
            qy += __shfl_xor_sync(0xffffffff, qy, d);
        }
        if ((lane >> 2) == 0) {
            red2(&stats[gc], sx, sy);
            red2(&stats[DD + gc], qx, qy);
        }
    }
}

// ---------------- small GEMM: BM=64, BN=128 (grid.y=2), 256 threads ----------------
template <int MODE>
__global__ void __launch_bounds__(256, 2)
k_gemm_small(const float* __restrict__ A, const float* __restrict__ A2,
             const uint32_t* __restrict__ Whi, const uint32_t* __restrict__ Wlo,
             const float* __restrict__ bias, float* __restrict__ C, int M,
             float* __restrict__ stats, const float* __restrict__ bnp) {
    __shared__ uint32_t As_hi[16][72];
    __shared__ uint32_t As_lo[16][72];
    __shared__ uint32_t Bs_hi[16][136];
    __shared__ uint32_t Bs_lo[16][136];

    int tid = threadIdx.x;
    int lane = tid & 31;
    int wid = tid >> 5;
    int wr = wid >> 1;
    int wc = wid & 1;
    int row0 = blockIdx.x * 64;
    int col0 = blockIdx.y * 128;

    float acc[8][4];
#pragma unroll
    for (int j = 0; j < 8; j++)
#pragma unroll
        for (int r = 0; r < 4; r++) acc[j][r] = 0.f;

    for (int k0 = 0; k0 < DD; k0 += 32) {
#pragma unroll
        for (int q = 0; q < 2; q++) {
            int li = tid + q * 256;
            int r = li >> 3;
            int kk = (li & 7) * 4;
            float4 v = make_float4(0.f, 0.f, 0.f, 0.f);
            int gr = row0 + r;
            if (gr < M) v = load_a4<MODE>(A, A2, bnp, (size_t)gr * DD + k0 + kk, k0 + kk);
            int k2 = kk >> 1;
            uint32_t h0, l0, h1, l1;
            split_pack(v.x, v.y, h0, l0);
            split_pack(v.z, v.w, h1, l1);
            As_hi[k2][r] = h0;     As_lo[k2][r] = l0;
            As_hi[k2 + 1][r] = h1; As_lo[k2 + 1][r] = l1;
        }
        {
            const uint32_t* wh = Whi + (size_t)(k0 >> 1) * DD + col0;
            const uint32_t* wl = Wlo + (size_t)(k0 >> 1) * DD + col0;
#pragma unroll
            for (int q = 0; q < 2; q++) {
                int li = tid + q * 256;
                int r = li >> 5;
                int n4 = (li & 31) * 4;
                *(uint4*)&Bs_hi[r][n4] = *(const uint4*)(wh + (size_t)r * DD + n4);
                *(uint4*)&Bs_lo[r][n4] = *(const uint4*)(wl + (size_t)r * DD + n4);
            }
        }
        __syncthreads();

#pragma unroll
        for (int s = 0; s < 2; s++) {
            int kb = s * 8 + (lane & 3);
            int m = wr * 16 + (lane >> 2);
            uint32_t ah[4], al[4];
            ah[0] = As_hi[kb][m];     ah[1] = As_hi[kb][m + 8];
            ah[2] = As_hi[kb + 4][m]; ah[3] = As_hi[kb + 4][m + 8];
            al[0] = As_lo[kb][m];     al[1] = As_lo[kb][m + 8];
            al[2] = As_lo[kb + 4][m]; al[3] = As_lo[kb + 4][m + 8];
#pragma unroll
            for (int j = 0; j < 8; j++) {
                int n = wc * 64 + j * 8 + (lane >> 2);
                uint32_t bh0 = Bs_hi[kb][n], bh1 = Bs_hi[kb + 4][n];
                uint32_t bl0 = Bs_lo[kb][n], bl1 = Bs_lo[kb + 4][n];
                mma_bf16(acc[j], ah, bh0, bh1);
                mma_bf16(acc[j], ah, bl0, bl1);
                mma_bf16(acc[j], al, bh0, bh1);
            }
        }
        __syncthreads();
    }

#pragma unroll
    for (int j = 0; j < 8; j++) {
        int gc = col0 + wc * 64 + j * 8 + (lane & 3) * 2;
        float bx = __ldg(&bias[gc]);
        float by = __ldg(&bias[gc + 1]);
        float sx = 0.f, sy = 0.f, qx = 0.f, qy = 0.f;
        int gr = row0 + wr * 16 + (lane >> 2);
        if (gr < M) {
            float2 v0 = make_float2(acc[j][0] + bx, acc[j][1] + by);
            *(float2*)(C + (size_t)gr * DD + gc) = v0;
            sx += v0.x; sy += v0.y; qx += v0.x * v0.x; qy += v0.y * v0.y;
        }
        if (gr + 8 < M) {
            float2 v1 = make_float2(acc[j][2] + bx, acc[j][3] + by);
            *(float2*)(C + (size_t)(gr + 8) * DD + gc) = v1;
            sx += v1.x; sy += v1.y; qx += v1.x * v1.x; qy += v1.y * v1.y;
        }
#pragma unroll
        for (int d = 4; d < 32; d <<= 1) {
            sx += __shfl_xor_sync(0xffffffff, sx, d);
            sy += __shfl_xor_sync(0xffffffff, sy, d);
            qx += __shfl_xor_sync(0xffffffff, qx, d);
            qy += __shfl_xor_sync(0xffffffff, qy, d);
        }
        if ((lane >> 2) == 0) {
            red2(&stats[gc], sx, sy);
            red2(&stats[DD + gc], qx, qy);
        }
    }
}

// ---------------- BN prep / apply ----------------
__global__ void k_bn_prep(float* __restrict__ stats, float* __restrict__ bnp,
                          const float* __restrict__ gamma, const float* __restrict__ beta,
                          float Minv) {
    int c = threadIdx.x;
    float m = stats[c] * Minv;
    float var = stats[DD + c] * Minv - m * m;
    float rs = rsqrtf(var + BN_EPS);
    float sc = gamma[c] * rs;
    bnp[c] = sc;
    bnp[DD + c] = beta[c] - m * sc;
    stats[c] = 0.f;
    stats[DD + c] = 0.f;
}

__global__ void k_bn_apply(const float* __restrict__ Yin, float* __restrict__ Yout,
                           const float* __restrict__ bnp, const int* __restrict__ batch,
                           int M, int do_relu, int do_vn, int do_pool) {
    int idx = blockIdx.x * blockDim.x + threadIdx.x;
    if (idx >= M * 64) return;
    int r = idx >> 6;
    int c4 = (idx & 63) * 4;
    float4 sc = *(const float4*)(bnp + c4);
    float4 sh = *(const float4*)(bnp + DD + c4);
    float4 v = *(const float4*)(Yin + (size_t)r * DD + c4);
    v.x = v.x * sc.x + sh.x;
    v.y = v.y * sc.y + sh.y;
    v.z = v.z * sc.z + sh.z;
    v.w = v.w * sc.w + sh.w;
    if (do_relu) {
        v.x = fmaxf(v.x, 0.f); v.y = fmaxf(v.y, 0.f);
        v.z = fmaxf(v.z, 0.f); v.w = fmaxf(v.w, 0.f);
    }
    int g = 0;
    if (do_vn || do_pool) g = __ldg(&batch[r]);
    if (do_vn) {
        float4 w = *(const float4*)(g_vn + (size_t)g * DD + c4);
        v.x += w.x; v.y += w.y; v.z += w.z; v.w += w.w;
    }
    *(float4*)(Yout + (size_t)r * DD + c4) = v;
    if (do_pool) red4(g_pooled + (size_t)g * DD + c4, v.x, v.y, v.z, v.w);
}

// ---------------- host orchestration ----------------
extern "C" void kernel_launch(void* const* d_in, const int* in_sizes, int n_in,
                              void* d_out, int out_size) {
    const int* x          = (const int*)d_in[0];
    const int* edge_index = (const int*)d_in[1];
    const int* edge_attr  = (const int*)d_in[2];
    const int* batch      = (const int*)d_in[3];
    const float* atom_emb = (const float*)d_in[4];
    const float* bond_emb = (const float*)d_in[5];
    const float* vn_emb   = (const float*)d_in[6];
    const float* gin_eps  = (const float*)d_in[7];
    const float* conv_W1  = (const float*)d_in[8];
    const float* conv_b1  = (const float*)d_in[9];
    const float* conv_bn_g = (const float*)d_in[10];
    const float* conv_bn_b = (const float*)d_in[11];
    const float* conv_W2  = (const float*)d_in[12];
    const float* conv_b2  = (const float*)d_in[13];
    const float* outer_bn_g = (const float*)d_in[14];
    const float* outer_bn_b = (const float*)d_in[15];
    const float* vn_W1    = (const float*)d_in[16];
    const float* vn_b1    = (const float*)d_in[17];
    const float* vn_bn1_g = (const float*)d_in[18];
    const float* vn_bn1_b = (const float*)d_in[19];
    const float* vn_W2    = (const float*)d_in[20];
    const float* vn_b2    = (const float*)d_in[21];
    const float* vn_bn2_g = (const float*)d_in[22];
    const float* vn_bn2_b = (const float*)d_in[23];
    float* out = (float*)d_out;

    cudaFuncSetAttribute(k_gemm_big<0>, cudaFuncAttributeMaxDynamicSharedMemorySize, SMEM_BIG);
    cudaFuncSetAttribute(k_gemm_big<2>, cudaFuncAttributeMaxDynamicSharedMemorySize, SMEM_BIG);

    float *p_t, *p_y, *p_pooled, *p_vt, *p_vt2, *p_vn;
    float *p_stats, *p_bnp, *p_stats_v, *p_bnp_v;
    uint32_t *p_whi, *p_wlo;
    cudaGetSymbolAddress((void**)&p_t, g_t);
    cudaGetSymbolAddress((void**)&p_y, g_y);
    cudaGetSymbolAddress((void**)&p_pooled, g_pooled);
    cudaGetSymbolAddress((void**)&p_vt, g_vt);
    cudaGetSymbolAddress((void**)&p_vt2, g_vt2);
    cudaGetSymbolAddress((void**)&p_vn, g_vn);
    cudaGetSymbolAddress((void**)&p_stats, g_stats);
    cudaGetSymbolAddress((void**)&p_bnp, g_bnp);
    cudaGetSymbolAddress((void**)&p_stats_v, g_stats_v);
    cudaGetSymbolAddress((void**)&p_bnp_v, g_bnp_v);
    cudaGetSymbolAddress((void**)&p_whi, g_whi);
    cudaGetSymbolAddress((void**)&p_wlo, g_wlo);

    const size_t slot = (size_t)NN * DD;
    const size_t wslot = (size_t)128 * DD;
    const int blkN = (NN * 64 + 255) / 256;
    const float invN = 1.0f / (float)NN;
    const float invG = 1.0f / (float)GG;

    cudaStream_t sv;
    cudaStreamCreateWithFlags(&sv, cudaStreamNonBlocking);
    cudaEvent_t ev_start, ev_pre, ev_fork[LL], ev_join[LL];
    cudaEventCreateWithFlags(&ev_start, cudaEventDisableTiming);
    cudaEventCreateWithFlags(&ev_pre, cudaEventDisableTiming);
    for (int l = 0; l < LL; l++) {
        cudaEventCreateWithFlags(&ev_fork[l], cudaEventDisableTiming);
        cudaEventCreateWithFlags(&ev_join[l], cudaEventDisableTiming);
    }

    // ---- prologue fork: CSR build + stats zeros + weight splits on sv,
    //      encoders / lut / pooled-zero / vn_init on main ----
    cudaEventRecord(ev_start, 0);
    cudaStreamWaitEvent(sv, ev_start, 0);

    // sv chain
    k_zero_off<<<(NN + 2 + 255) / 256, 256, 0, sv>>>();
    k_hist<<<(EE + 255) / 256, 256, 0, sv>>>(edge_index);
    k_scan<<<1, SCAN_T, 0, sv>>>();
    k_scatter_e<<<(EE + 255) / 256, 256, 0, sv>>>(edge_index, edge_attr);
    k_zero<<<1, 128, 0, sv>>>(p_stats, 128);
    k_zero<<<1, 128, 0, sv>>>(p_stats_v, 128);
    const int wgrid = (128 * DD + 255) / 256;
    for (int l = 0; l < LL; l++) {
        k_split_w<<<wgrid, 256, 0, sv>>>(conv_W1 + (size_t)l * DD * DD,
                                         p_whi + (size_t)l * wslot, p_wlo + (size_t)l * wslot);
        k_split_w<<<wgrid, 256, 0, sv>>>(conv_W2 + (size_t)l * DD * DD,
                                         p_whi + (size_t)(5 + l) * wslot,
                                         p_wlo + (size_t)(5 + l) * wslot);
    }
    for (int l = 0; l < LL - 1; l++) {
        k_split_w<<<wgrid, 256, 0, sv>>>(vn_W1 + (size_t)l * DD * DD,
                                         p_whi + (size_t)(10 + l) * wslot,
                                         p_wlo + (size_t)(10 + l) * wslot);
        k_split_w<<<wgrid, 256, 0, sv>>>(vn_W2 + (size_t)l * DD * DD,
                                         p_whi + (size_t)(14 + l) * wslot,
                                         p_wlo + (size_t)(14 + l) * wslot);
    }
    cudaEventRecord(ev_pre, sv);

    // main chain
    k_zero<<<(GG * 64 + 255) / 256, 256>>>(p_pooled, GG * 64);
    k_build_lut<<<(216 * 64 + 255) / 256, 256>>>(bond_emb);
    k_encode_atoms<<<blkN, 256>>>(x, atom_emb, vn_emb, batch, out);
    k_vn_init<<<(GG * DD + 255) / 256, 256>>>(vn_emb);
    cudaStreamWaitEvent(0, ev_pre, 0);   // k_agg needs CSR; GEMMs need whi/wlo

    const int gBig = (NN + BM - 1) / BM;
    const dim3 gSmall((GG + 63) / 64, 2);
    const int gAgg = (NN * 32 + 255) / 256;

    for (int l = 0; l < LL; l++) {
        float* h = out + (size_t)l * slot;            // h_in^l (vn already added)
        float* z_out = out + (size_t)(l + 1) * slot;

        // vn chain on sv, concurrent with k_agg + big GEMMs
        if (l < LL - 1) {
            cudaEventRecord(ev_fork[l], 0);
            cudaStreamWaitEvent(sv, ev_fork[l], 0);
            k_gemm_small<3><<<gSmall, 256, 0, sv>>>(p_pooled, p_vn,
                                                    p_whi + (size_t)(10 + l) * wslot,
                                                    p_wlo + (size_t)(10 + l) * wslot,
                                                    vn_b1 + l * DD, p_vt, GG,
                                                    p_stats_v, nullptr);
            k_zero<<<(GG * 64 + 255) / 256, 256, 0, sv>>>(p_pooled, GG * 64);
            k_bn_prep<<<1, 256, 0, sv>>>(p_stats_v, p_bnp_v,
                                         vn_bn1_g + l * DD, vn_bn1_b + l * DD, invG);
            k_gemm_small<2><<<gSmall, 256, 0, sv>>>(p_vt, nullptr,
                                                    p_whi + (size_t)(14 + l) * wslot,
                                                    p_wlo + (size_t)(14 + l) * wslot,
                                                    vn_b2 + l * DD, p_vt2, GG,
                                                    p_stats_v, p_bnp_v);
            k_bn_prep<<<1, 256, 0, sv>>>(p_stats_v, p_bnp_v,
                                         vn_bn2_g + l * DD, vn_bn2_b + l * DD, invG);
            k_bn_apply<<<(GG * 64 + 255) / 256, 256, 0, sv>>>(p_vt2, p_vn, p_bnp_v,
                                                              nullptr, GG, 1, 0, 0);
            cudaEventRecord(ev_join[l], sv);
        }

        // main path: fused agg+combine writes z into g_t, then plain-A GEMM1
        k_agg<<<gAgg, 256>>>(h, gin_eps + l);
        k_gemm_big<0><<<gBig, 256, SMEM_BIG>>>(p_t, nullptr,
                                               p_whi + (size_t)l * wslot,
                                               p_wlo + (size_t)l * wslot,
                                               conv_b1 + l * DD, p_y, NN,
                                               p_stats, nullptr);
        k_bn_prep<<<1, 256>>>(p_stats, p_bnp, conv_bn_g + l * DD, conv_bn_b + l * DD, invN);
        k_gemm_big<2><<<gBig, 256, SMEM_BIG>>>(p_y, nullptr,
                                               p_whi + (size_t)(5 + l) * wslot,
                                               p_wlo + (size_t)(5 + l) * wslot,
                                               conv_b2 + l * DD, p_t, NN,
                                               p_stats, p_bnp);
        k_bn_prep<<<1, 256>>>(p_stats, p_bnp, outer_bn_g + l * DD, outer_bn_b + l * DD, invN);
        // final BN apply needs new vn (and pooled zeroed) -> join
        if (l < LL - 1) cudaStreamWaitEvent(0, ev_join[l], 0);
        int relu = (l < LL - 1) ? 1 : 0;
        int vnadd = (l < LL - 1) ? 1 : 0;
        int pool = (l < LL - 2) ? 1 : 0;
        k_bn_apply<<<blkN, 256>>>(p_t, z_out, p_bnp, batch, NN, relu, vnadd, pool);
    }
}

// round 14
// speedup vs baseline: 1.1114x; 1.0084x over previous
#include <cuda_runtime.h>
#include <cuda_bf16.h>
#include <cstdint>

#define NN 100000
#define EE 300000
#define GG 4096
#define DD 256
#define LL 5
#define BN_EPS 1e-5f
#define NW 18

// ---------------- scratch (device globals; no allocations) ----------------
__device__ int g_off[NN + 2];
__device__ int g_cur[NN];
__device__ uint32_t g_epack[EE];
__device__ float g_lut[216 * DD];
__device__ float g_t[(size_t)NN * DD];
__device__ float g_y[(size_t)NN * DD];
__device__ float g_vn[(size_t)GG * DD];
__device__ float g_pooled[(size_t)GG * DD];
__device__ float g_vt[(size_t)GG * DD];
__device__ float g_vt2[(size_t)GG * DD];
__device__ float g_stats[2 * DD];                  // GEMM1 output stats
__device__ float g_stats2[2 * DD];                 // GEMM2 output stats
__device__ float g_stats_v[2 * DD];                // vn-path stats
__device__ float g_bnp_v[2 * DD];                  // vn-path bn scale/shift
__device__ uint32_t g_whi[(size_t)NW * 128 * DD];
__device__ uint32_t g_wlo[(size_t)NW * 128 * DD];

__device__ __forceinline__ void red2(float* p, float a, float b) {
    asm volatile("red.global.add.v2.f32 [%0], {%1,%2};" :: "l"(p), "f"(a), "f"(b) : "memory");
}
__device__ __forceinline__ void red4(float* p, float a, float b, float c, float d) {
    asm volatile("red.global.add.v4.f32 [%0], {%1,%2,%3,%4};"
                 :: "l"(p), "f"(a), "f"(b), "f"(c), "f"(d) : "memory");
}
__device__ __forceinline__ void cp16(uint32_t smem_addr, const void* g) {
    asm volatile("cp.async.cg.shared.global [%0], [%1], 16;" :: "r"(smem_addr), "l"(g));
}
__device__ __forceinline__ void cp_commit() {
    asm volatile("cp.async.commit_group;");
}
__device__ __forceinline__ void cp_wait0() {
    asm volatile("cp.async.wait_group 0;");
}

__device__ __forceinline__ uint32_t pack_bf2(float a, float b) {
    __nv_bfloat162 t = __floats2bfloat162_rn(a, b);
    return *(uint32_t*)&t;
}
__device__ __forceinline__ void split_pack(float a, float b, uint32_t& hi, uint32_t& lo) {
    __nv_bfloat16 ah = __float2bfloat16_rn(a);
    __nv_bfloat16 bh = __float2bfloat16_rn(b);
    float al = a - __bfloat162float(ah);
    float bl = b - __bfloat162float(bh);
    __nv_bfloat162 h2; h2.x = ah; h2.y = bh;
    hi = *(uint32_t*)&h2;
    lo = pack_bf2(al, bl);
}

// ---------------- small kernels ----------------
__global__ void k_zero(float* p, int n4) {
    int i = blockIdx.x * blockDim.x + threadIdx.x;
    if (i < n4) ((float4*)p)[i] = make_float4(0.f, 0.f, 0.f, 0.f);
}
__global__ void k_zero_off() {
    int i = blockIdx.x * blockDim.x + threadIdx.x;
    if (i < NN + 2) g_off[i] = 0;
}

__global__ void k_split_w(const float* __restrict__ W, uint32_t* __restrict__ hi,
                          uint32_t* __restrict__ lo) {
    int i = blockIdx.x * blockDim.x + threadIdx.x;
    if (i >= 128 * DD) return;
    int k2 = i >> 8, n = i & 255;
    float a = W[(size_t)(2 * k2) * DD + n];
    float b = W[(size_t)(2 * k2 + 1) * DD + n];
    split_pack(a, b, hi[i], lo[i]);
}

__global__ void k_build_lut(const float* __restrict__ bond_emb) {
    int idx = blockIdx.x * blockDim.x + threadIdx.x;
    if (idx >= 216 * 64) return;
    int c = idx >> 6;
    int d4 = (idx & 63) * 4;
    int v0 = c / 36, v1 = (c / 6) % 6, v2 = c % 6;
    float4 a = *(const float4*)(bond_emb + ((size_t)(0 * 6 + v0) * DD + d4));
    float4 b = *(const float4*)(bond_emb + ((size_t)(1 * 6 + v1) * DD + d4));
    float4 d = *(const float4*)(bond_emb + ((size_t)(2 * 6 + v2) * DD + d4));
    *(float4*)(g_lut + (size_t)c * DD + d4) =
        make_float4(a.x + b.x + d.x, a.y + b.y + d.y, a.z + b.z + d.z, a.w + b.w + d.w);
}

// ---- CSR build ----
__global__ void k_hist(const int* __restrict__ ei) {
    int e = blockIdx.x * blockDim.x + threadIdx.x;
    if (e < EE) atomicAdd(&g_off[ei[EE + e]], 1);
}

#define SCAN_T 1024
#define SCAN_CH 98
__global__ void k_scan() {
    __shared__ int ssum[SCAN_T];
    int t = threadIdx.x;
    int begin = t * SCAN_CH;
    int end = min(NN, begin + SCAN_CH);
    int s = 0;
    for (int i = begin; i < end; i++) s += g_off[i];
    ssum[t] = s;
    __syncthreads();
    for (int d = 1; d < SCAN_T; d <<= 1) {
        int v = (t >= d) ? ssum[t - d] : 0;
        __syncthreads();
        ssum[t] += v;
        __syncthreads();
    }
    int run = ssum[t] - s;
    for (int i = begin; i < end; i++) {
        int c = g_off[i];
        g_off[i] = run;
        g_cur[i] = run;
        run += c;
    }
    if (t == SCAN_T - 1) g_off[NN] = ssum[SCAN_T - 1];
}

__global__ void k_scatter_e(const int* __restrict__ ei, const int* __restrict__ ea_idx) {
    int e = blockIdx.x * blockDim.x + threadIdx.x;
    if (e >= EE) return;
    int dst = ei[EE + e];
    int src = ei[e];
    int code = ea_idx[e * 3 + 0] * 36 + ea_idx[e * 3 + 1] * 6 + ea_idx[e * 3 + 2];
    int pos = atomicAdd(&g_cur[dst], 1);
    g_epack[pos] = (uint32_t)src * 256u + (uint32_t)code;
}

// CSR aggregation fused with gin_combine: z = (1+eps)*h[node] + sum relu(h[src]+lut)
// block 0 also zeroes the ping-pong stats buffers (no reader conflict: all prior
// stats consumers completed by stream order; agg itself never reads stats).
__global__ void __launch_bounds__(256)
k_agg(const float* __restrict__ h, const float* __restrict__ epsp) {
    if (blockIdx.x == 0) {
        int t = threadIdx.x;
        g_stats[t] = 0.f;
        g_stats[t + 256] = 0.f;
        g_stats2[t] = 0.f;
        g_stats2[t + 256] = 0.f;
    }
    int gw = (blockIdx.x * 256 + threadIdx.x) >> 5;
    if (gw >= NN) return;
    int lane = threadIdx.x & 31;
    int base = lane * 8;
    float e = 1.0f + __ldg(epsp);
    float acc[8] = {0.f, 0.f, 0.f, 0.f, 0.f, 0.f, 0.f, 0.f};
    int p0 = g_off[gw], p1 = g_off[gw + 1];
    for (int p = p0; p < p1; p++) {
        uint32_t pk = __ldg(&g_epack[p]);
        const float* hr = h + (size_t)(pk >> 8) * DD + base;
        const float* lr = g_lut + (size_t)(pk & 255u) * DD + base;
        float4 h0 = *(const float4*)hr;
        float4 h1 = *(const float4*)(hr + 4);
        float4 l0 = *(const float4*)lr;
        float4 l1 = *(const float4*)(lr + 4);
        acc[0] += fmaxf(h0.x + l0.x, 0.f);
        acc[1] += fmaxf(h0.y + l0.y, 0.f);
        acc[2] += fmaxf(h0.z + l0.z, 0.f);
        acc[3] += fmaxf(h0.w + l0.w, 0.f);
        acc[4] += fmaxf(h1.x + l1.x, 0.f);
        acc[5] += fmaxf(h1.y + l1.y, 0.f);
        acc[6] += fmaxf(h1.z + l1.z, 0.f);
        acc[7] += fmaxf(h1.w + l1.w, 0.f);
    }
    const float* hn = h + (size_t)gw * DD + base;
    float4 s0 = *(const float4*)hn;
    float4 s1 = *(const float4*)(hn + 4);
    float* o = g_t + (size_t)gw * DD + base;
    *(float4*)o = make_float4(e * s0.x + acc[0], e * s0.y + acc[1],
                              e * s0.z + acc[2], e * s0.w + acc[3]);
    *(float4*)(o + 4) = make_float4(e * s1.x + acc[4], e * s1.y + acc[5],
                                    e * s1.z + acc[6], e * s1.w + acc[7]);
}

// atom encoder: h0 = sum emb + vn0; also scatter h0 row into pooled
__global__ void k_encode_atoms(const int* __restrict__ x,
                               const float* __restrict__ atom_emb,
                               const float* __restrict__ vn_emb,
                               const int* __restrict__ batch,
                               float* __restrict__ out0) {
    int idx = blockIdx.x * blockDim.x + threadIdx.x;
    if (idx >= NN * 64) return;
    int n = idx >> 6;
    int d4 = (idx & 63) * 4;
    float4 acc = *(const float4*)(vn_emb + d4);
#pragma unroll
    for (int f = 0; f < 9; f++) {
        int v = __ldg(&x[n * 9 + f]);
        float4 e = *(const float4*)(atom_emb + ((size_t)(f * 120 + v) * DD + d4));
        acc.x += e.x; acc.y += e.y; acc.z += e.z; acc.w += e.w;
    }
    *(float4*)(out0 + (size_t)n * DD + d4) = acc;
    int g = __ldg(&batch[n]);
    red4(g_pooled + (size_t)g * DD + d4, acc.x, acc.y, acc.z, acc.w);
}

__global__ void k_vn_init(const float* __restrict__ vn_emb) {
    int i = blockIdx.x * blockDim.x + threadIdx.x;
    if (i < GG * DD) g_vn[i] = vn_emb[i & (DD - 1)];
}

// ---------------- GEMM common ----------------
__device__ __forceinline__ void mma_bf16(float* c, const uint32_t* a, uint32_t b0, uint32_t b1) {
    asm volatile(
        "mma.sync.aligned.m16n8k16.row.col.f32.bf16.bf16.f32 "
        "{%0,%1,%2,%3}, {%4,%5,%6,%7}, {%8,%9}, {%0,%1,%2,%3};"
        : "+f"(c[0]), "+f"(c[1]), "+f"(c[2]), "+f"(c[3])
        : "r"(a[0]), "r"(a[1]), "r"(a[2]), "r"(a[3]), "r"(b0), "r"(b1));
}

// MODE 0: A as-is.  MODE 2: A=relu(y*scale+shift).  MODE 3: A=A+A2.
template <int MODE>
__device__ __forceinline__ float4 load_a4(const float* A, const float* A2,
                                          const float* bnp, size_t off, int kidx) {
    float4 v;
    if (MODE == 0) {
        v = *(const float4*)(A + off);
    } else if (MODE == 2) {
        float4 yv = *(const float4*)(A + off);
        float4 sc = *(const float4*)(bnp + kidx);
        float4 sh = *(const float4*)(bnp + DD + kidx);
        v.x = fmaxf(yv.x * sc.x + sh.x, 0.f);
        v.y = fmaxf(yv.y * sc.y + sh.y, 0.f);
        v.z = fmaxf(yv.z * sc.z + sh.z, 0.f);
        v.w = fmaxf(yv.w * sc.w + sh.w, 0.f);
    } else {
        float4 hv = *(const float4*)(A + off);
        float4 av = *(const float4*)(A2 + off);
        v.x = hv.x + av.x; v.y = hv.y + av.y;
        v.z = hv.z + av.z; v.w = hv.w + av.w;
    }
    return v;
}

// ---------------- big GEMM: BM=64, BN=256, BK=32, 256 threads, occ 2 ----
// MODE 2 computes BN scale/shift in-prologue from stats_in (ping-pong buffers).
#define BM 64
#define A_SZ 1152
#define B_SZ 4224
#define B_BASE (4 * A_SZ)
#define SMEM_BIG ((4 * A_SZ + 4 * B_SZ) * 4)

template <int MODE>
__global__ void __launch_bounds__(256, 2)
k_gemm_big(const float* __restrict__ A, const uint32_t* __restrict__ Whi,
           const uint32_t* __restrict__ Wlo, const float* __restrict__ bias,
           float* __restrict__ C, int M, float* __restrict__ stats_out,
           const float* __restrict__ stats_in, const float* __restrict__ gamma,
           const float* __restrict__ beta, float Minv) {
    extern __shared__ uint32_t sm[];
    __shared__ __align__(16) float sbnp[2 * DD];
    const uint32_t sbase = (uint32_t)__cvta_generic_to_shared(sm);

    int tid = threadIdx.x;
    int lane = tid & 31;
    int wid = tid >> 5;
    int wr = wid >> 2;
    int wc = wid & 3;
    int row0 = blockIdx.x * BM;

    if (MODE == 2) {
        float mn = __ldg(&stats_in[tid]) * Minv;
        float var = __ldg(&stats_in[DD + tid]) * Minv - mn * mn;
        float rs = rsqrtf(var + BN_EPS);
        float sc = __ldg(&gamma[tid]) * rs;
        sbnp[tid] = sc;
        sbnp[DD + tid] = __ldg(&beta[tid]) - mn * sc;
        __syncthreads();
    }

    const int ar0 = tid >> 3;
    const int akk = (tid & 7) * 4;
    const int br = tid >> 6;
    const int bn4 = (tid & 63) * 4;

    float acc[2][8][4];
#pragma unroll
    for (int i = 0; i < 2; i++)
#pragma unroll
        for (int j = 0; j < 8; j++)
#pragma unroll
            for (int r = 0; r < 4; r++) acc[i][j][r] = 0.f;

    float4 vA[2];

    auto issueB = [&](int k0, int buf) {
        const uint32_t* wh = Whi + (size_t)(k0 >> 1) * DD;
        const uint32_t* wl = Wlo + (size_t)(k0 >> 1) * DD;
        uint32_t bhi = sbase + (B_BASE + buf * 2 * B_SZ) * 4;
        uint32_t blo = bhi + B_SZ * 4;
#pragma unroll
        for (int q = 0; q < 4; q++) {
            int r = br + q * 4;
            cp16(bhi + (r * 264 + bn4) * 4, wh + (size_t)r * DD + bn4);
            cp16(blo + (r * 264 + bn4) * 4, wl + (size_t)r * DD + bn4);
        }
        cp_commit();
    };
    auto loadA = [&](int k0) {
#pragma unroll
        for (int q = 0; q < 2; q++) {
            int gr = row0 + ar0 + q * 32;
            vA[q] = make_float4(0.f, 0.f, 0.f, 0.f);
            if (gr < M)
                vA[q] = load_a4<MODE>(A, nullptr, sbnp, (size_t)gr * DD + k0 + akk, k0 + akk);
        }
    };
    auto storeA = [&](int buf) {
        uint32_t* ahi = sm + buf * 2 * A_SZ;
        uint32_t* alo = ahi + A_SZ;
        int k2 = akk >> 1;
#pragma unroll
        for (int q = 0; q < 2; q++) {
            int r = ar0 + q * 32;
            uint32_t h0, l0, h1, l1;
            split_pack(vA[q].x, vA[q].y, h0, l0);
            split_pack(vA[q].z, vA[q].w, h1, l1);
            ahi[k2 * 72 + r] = h0;       alo[k2 * 72 + r] = l0;
            ahi[(k2 + 1) * 72 + r] = h1; alo[(k2 + 1) * 72 + r] = l1;
        }
    };

    issueB(0, 0);
    loadA(0);
    storeA(0);
    cp_wait0();
    __syncthreads();

#pragma unroll 1
    for (int it = 0; it < 8; it++) {
        int cur = it & 1;
        int nxt = cur ^ 1;
        if (it < 7) {
            issueB((it + 1) * 32, nxt);
            loadA((it + 1) * 32);
        }
        {
            const uint32_t* ahi = sm + cur * 2 * A_SZ;
            const uint32_t* alo = ahi + A_SZ;
            const uint32_t* bhi = sm + B_BASE + cur * 2 * B_SZ;
            const uint32_t* blo = bhi + B_SZ;
#pragma unroll
            for (int s = 0; s < 2; s++) {
                int kb = s * 8 + (lane & 3);
                uint32_t ah[2][4], al[2][4];
#pragma unroll
                for (int i = 0; i < 2; i++) {
                    int m = wr * 32 + i * 16 + (lane >> 2);
                    ah[i][0] = ahi[kb * 72 + m];       ah[i][1] = ahi[kb * 72 + m + 8];
                    ah[i][2] = ahi[(kb + 4) * 72 + m]; ah[i][3] = ahi[(kb + 4) * 72 + m + 8];
                    al[i][0] = alo[kb * 72 + m];       al[i][1] = alo[kb * 72 + m + 8];
                    al[i][2] = alo[(kb + 4) * 72 + m]; al[i][3] = alo[(kb + 4) * 72 + m + 8];
                }
#pragma unroll
                for (int j = 0; j < 8; j++) {
                    int n = wc * 64 + j * 8 + (lane >> 2);
                    uint32_t bh0 = bhi[kb * 264 + n], bh1 = bhi[(kb + 4) * 264 + n];
                    uint32_t bl0 = blo[kb * 264 + n], bl1 = blo[(kb + 4) * 264 + n];
#pragma unroll
                    for (int i = 0; i < 2; i++) {
                        mma_bf16(acc[i][j], ah[i], bh0, bh1);
                        mma_bf16(acc[i][j], ah[i], bl0, bl1);
                        mma_bf16(acc[i][j], al[i], bh0, bh1);
                    }
                }
            }
        }
        if (it < 7) {
            storeA(nxt);
            cp_wait0();
        }
        __syncthreads();
    }

#pragma unroll
    for (int j = 0; j < 8; j++) {
        int gc = wc * 64 + j * 8 + (lane & 3) * 2;
        float bx = __ldg(&bias[gc]);
        float by = __ldg(&bias[gc + 1]);
        float sx = 0.f, sy = 0.f, qx = 0.f, qy = 0.f;
#pragma unroll
        for (int i = 0; i < 2; i++) {
            int gr = row0 + wr * 32 + i * 16 + (lane >> 2);
            if (gr < M) {
                float2 v0 = make_float2(acc[i][j][0] + bx, acc[i][j][1] + by);
                *(float2*)(C + (size_t)gr * DD + gc) = v0;
                sx += v0.x; sy += v0.y; qx += v0.x * v0.x; qy += v0.y * v0.y;
            }
            if (gr + 8 < M) {
                float2 v1 = make_float2(acc[i][j][2] + bx, acc[i][j][3] + by);
                *(float2*)(C + (size_t)(gr + 8) * DD + gc) = v1;
                sx += v1.x; sy += v1.y; qx += v1.x * v1.x; qy += v1.y * v1.y;
            }
        }
#pragma unroll
        for (int d = 4; d < 32; d <<= 1) {
            sx += __shfl_xor_sync(0xffffffff, sx, d);
            sy += __shfl_xor_sync(0xffffffff, sy, d);
            qx += __shfl_xor_sync(0xffffffff, qx, d);
            qy += __shfl_xor_sync(0xffffffff, qy, d);
        }
        if ((lane >> 2) == 0) {
            red2(&stats_out[gc], sx, sy);
            red2(&stats_out[DD + gc], qx, qy);
        }
    }
}

// ---------------- small GEMM: BM=64, BN=128 (grid.y=2), 256 threads (unchanged) ----
template <int MODE>
__global__ void __launch_bounds__(256, 2)
k_gemm_small(const float* __restrict__ A, const float* __restrict__ A2,
             const uint32_t* __restrict__ Whi, const uint32_t* __restrict__ Wlo,
             const float* __restrict__ bias, float* __restrict__ C, int M,
             float* __restrict__ stats, const float* __restrict__ bnp) {
    __shared__ uint32_t As_hi[16][72];
    __shared__ uint32_t As_lo[16][72];
    __shared__ uint32_t Bs_hi[16][136];
    __shared__ uint32_t Bs_lo[16][136];

    int tid = threadIdx.x;
    int lane = tid & 31;
    int wid = tid >> 5;
    int wr = wid >> 1;
    int wc = wid & 1;
    int row0 = blockIdx.x * 64;
    int col0 = blockIdx.y * 128;

    float acc[8][4];
#pragma unroll
    for (int j = 0; j < 8; j++)
#pragma unroll
        for (int r = 0; r < 4; r++) acc[j][r] = 0.f;

    for (int k0 = 0; k0 < DD; k0 += 32) {
#pragma unroll
        for (int q = 0; q < 2; q++) {
            int li = tid + q * 256;
            int r = li >> 3;
            int kk = (li & 7) * 4;
            float4 v = make_float4(0.f, 0.f, 0.f, 0.f);
            int gr = row0 + r;
            if (gr < M) v = load_a4<MODE>(A, A2, bnp, (size_t)gr * DD + k0 + kk, k0 + kk);
            int k2 = kk >> 1;
            uint32_t h0, l0, h1, l1;
            split_pack(v.x, v.y, h0, l0);
            split_pack(v.z, v.w, h1, l1);
            As_hi[k2][r] = h0;     As_lo[k2][r] = l0;
            As_hi[k2 + 1][r] = h1; As_lo[k2 + 1][r] = l1;
        }
        {
            const uint32_t* wh = Whi + (size_t)(k0 >> 1) * DD + col0;
            const uint32_t* wl = Wlo + (size_t)(k0 >> 1) * DD + col0;
#pragma unroll
            for (int q = 0; q < 2; q++) {
                int li = tid + q * 256;
                int r = li >> 5;
                int n4 = (li & 31) * 4;
                *(uint4*)&Bs_hi[r][n4] = *(const uint4*)(wh + (size_t)r * DD + n4);
                *(uint4*)&Bs_lo[r][n4] = *(const uint4*)(wl + (size_t)r * DD + n4);
            }
        }
        __syncthreads();

#pragma unroll
        for (int s = 0; s < 2; s++) {
            int kb = s * 8 + (lane & 3);
            int m = wr * 16 + (lane >> 2);
            uint32_t ah[4], al[4];
            ah[0] = As_hi[kb][m];     ah[1] = As_hi[kb][m + 8];
            ah[2] = As_hi[kb + 4][m]; ah[3] = As_hi[kb + 4][m + 8];
            al[0] = As_lo[kb][m];     al[1] = As_lo[kb][m + 8];
            al[2] = As_lo[kb + 4][m]; al[3] = As_lo[kb + 4][m + 8];
#pragma unroll
            for (int j = 0; j < 8; j++) {
                int n = wc * 64 + j * 8 + (lane >> 2);
                uint32_t bh0 = Bs_hi[kb][n], bh1 = Bs_hi[kb + 4][n];
                uint32_t bl0 = Bs_lo[kb][n], bl1 = Bs_lo[kb + 4][n];
                mma_bf16(acc[j], ah, bh0, bh1);
                mma_bf16(acc[j], ah, bl0, bl1);
                mma_bf16(acc[j], al, bh0, bh1);
            }
        }
        __syncthreads();
    }

#pragma unroll
    for (int j = 0; j < 8; j++) {
        int gc = col0 + wc * 64 + j * 8 + (lane & 3) * 2;
        float bx = __ldg(&bias[gc]);
        float by = __ldg(&bias[gc + 1]);
        float sx = 0.f, sy = 0.f, qx = 0.f, qy = 0.f;
        int gr = row0 + wr * 16 + (lane >> 2);
        if (gr < M) {
            float2 v0 = make_float2(acc[j][0] + bx, acc[j][1] + by);
            *(float2*)(C + (size_t)gr * DD + gc) = v0;
            sx += v0.x; sy += v0.y; qx += v0.x * v0.x; qy += v0.y * v0.y;
        }
        if (gr + 8 < M) {
            float2 v1 = make_float2(acc[j][2] + bx, acc[j][3] + by);
            *(float2*)(C + (size_t)(gr + 8) * DD + gc) = v1;
            sx += v1.x; sy += v1.y; qx += v1.x * v1.x; qy += v1.y * v1.y;
        }
#pragma unroll
        for (int d = 4; d < 32; d <<= 1) {
            sx += __shfl_xor_sync(0xffffffff, sx, d);
            sy += __shfl_xor_sync(0xffffffff, sy, d);
            qx += __shfl_xor_sync(0xffffffff, qx, d);
            qy += __shfl_xor_sync(0xffffffff, qy, d);
        }
        if ((lane >> 2) == 0) {
            red2(&stats[gc], sx, sy);
            red2(&stats[DD + gc], qx, qy);
        }
    }
}

// ---------------- BN prep (vn path only) ----------------
__global__ void k_bn_prep(float* __restrict__ stats, float* __restrict__ bnp,
                          const float* __restrict__ gamma, const float* __restrict__ beta,
                          float Minv) {
    int c = threadIdx.x;
    float m = stats[c] * Minv;
    float var = stats[DD + c] * Minv - m * m;
    float rs = rsqrtf(var + BN_EPS);
    float sc = gamma[c] * rs;
    bnp[c] = sc;
    bnp[DD + c] = beta[c] - m * sc;
    stats[c] = 0.f;
    stats[DD + c] = 0.f;
}

// BN apply; if stats != nullptr compute scale/shift in-block from stats, else use bnp_pre
__global__ void k_bn_apply(const float* __restrict__ Yin, float* __restrict__ Yout,
                           const float* __restrict__ bnp_pre, const float* __restrict__ stats,
                           const float* __restrict__ gamma, const float* __restrict__ beta,
                           float Minv, const int* __restrict__ batch,
                           int M, int do_relu, int do_vn, int do_pool) {
    __shared__ __align__(16) float sb[2 * DD];
    int tid = threadIdx.x;
    if (stats) {
        float m = __ldg(&stats[tid]) * Minv;
        float var = __ldg(&stats[DD + tid]) * Minv - m * m;
        float rs = rsqrtf(var + BN_EPS);
        float sc = __ldg(&gamma[tid]) * rs;
        sb[tid] = sc;
        sb[DD + tid] = __ldg(&beta[tid]) - m * sc;
    } else {
        sb[tid] = bnp_pre[tid];
        sb[DD + tid] = bnp_pre[DD + tid];
    }
    __syncthreads();

    int idx = blockIdx.x * blockDim.x + tid;
    if (idx >= M * 64) return;
    int r = idx >> 6;
    int c4 = (idx & 63) * 4;
    float4 sc = *(const float4*)(sb + c4);
    float4 sh = *(const float4*)(sb + DD + c4);
    float4 v = *(const float4*)(Yin + (size_t)r * DD + c4);
    v.x = v.x * sc.x + sh.x;
    v.y = v.y * sc.y + sh.y;
    v.z = v.z * sc.z + sh.z;
    v.w = v.w * sc.w + sh.w;
    if (do_relu) {
        v.x = fmaxf(v.x, 0.f); v.y = fmaxf(v.y, 0.f);
        v.z = fmaxf(v.z, 0.f); v.w = fmaxf(v.w, 0.f);
    }
    int g = 0;
    if (do_vn || do_pool) g = __ldg(&batch[r]);
    if (do_vn) {
        float4 w = *(const float4*)(g_vn + (size_t)g * DD + c4);
        v.x += w.x; v.y += w.y; v.z += w.z; v.w += w.w;
    }
    *(float4*)(Yout + (size_t)r * DD + c4) = v;
    if (do_pool) red4(g_pooled + (size_t)g * DD + c4, v.x, v.y, v.z, v.w);
}

// ---------------- host orchestration ----------------
extern "C" void kernel_launch(void* const* d_in, const int* in_sizes, int n_in,
                              void* d_out, int out_size) {
    const int* x          = (const int*)d_in[0];
    const int* edge_index = (const int*)d_in[1];
    const int* edge_attr  = (const int*)d_in[2];
    const int* batch      = (const int*)d_in[3];
    const float* atom_emb = (const float*)d_in[4];
    const float* bond_emb = (const float*)d_in[5];
    const float* vn_emb   = (const float*)d_in[6];
    const float* gin_eps  = (const float*)d_in[7];
    const float* conv_W1  = (const float*)d_in[8];
    const float* conv_b1  = (const float*)d_in[9];
    const float* conv_bn_g = (const float*)d_in[10];
    const float* conv_bn_b = (const float*)d_in[11];
    const float* conv_W2  = (const float*)d_in[12];
    const float* conv_b2  = (const float*)d_in[13];
    const float* outer_bn_g = (const float*)d_in[14];
    const float* outer_bn_b = (const float*)d_in[15];
    const float* vn_W1    = (const float*)d_in[16];
    const float* vn_b1    = (const float*)d_in[17];
    const float* vn_bn1_g = (const float*)d_in[18];
    const float* vn_bn1_b = (const float*)d_in[19];
    const float* vn_W2    = (const float*)d_in[20];
    const float* vn_b2    = (const float*)d_in[21];
    const float* vn_bn2_g = (const float*)d_in[22];
    const float* vn_bn2_b = (const float*)d_in[23];
    float* out = (float*)d_out;

    cudaFuncSetAttribute(k_gemm_big<0>, cudaFuncAttributeMaxDynamicSharedMemorySize, SMEM_BIG);
    cudaFuncSetAttribute(k_gemm_big<2>, cudaFuncAttributeMaxDynamicSharedMemorySize, SMEM_BIG);

    float *p_t, *p_y, *p_pooled, *p_vt, *p_vt2, *p_vn;
    float *p_stats, *p_stats2, *p_stats_v, *p_bnp_v;
    uint32_t *p_whi, *p_wlo;
    cudaGetSymbolAddress((void**)&p_t, g_t);
    cudaGetSymbolAddress((void**)&p_y, g_y);
    cudaGetSymbolAddress((void**)&p_pooled, g_pooled);
    cudaGetSymbolAddress((void**)&p_vt, g_vt);
    cudaGetSymbolAddress((void**)&p_vt2, g_vt2);
    cudaGetSymbolAddress((void**)&p_vn, g_vn);
    cudaGetSymbolAddress((void**)&p_stats, g_stats);
    cudaGetSymbolAddress((void**)&p_stats2, g_stats2);
    cudaGetSymbolAddress((void**)&p_stats_v, g_stats_v);
    cudaGetSymbolAddress((void**)&p_bnp_v, g_bnp_v);
    cudaGetSymbolAddress((void**)&p_whi, g_whi);
    cudaGetSymbolAddress((void**)&p_wlo, g_wlo);

    const size_t slot = (size_t)NN * DD;
    const size_t wslot = (size_t)128 * DD;
    const int blkN = (NN * 64 + 255) / 256;
    const float invN = 1.0f / (float)NN;
    const float invG = 1.0f / (float)GG;

    // static stream/events: created once on first (correctness) call so all
    // driver-side pools predate the capture baseline
    static cudaStream_t sv = nullptr;
    static cudaEvent_t ev_start, ev_pre, ev_fork[LL], ev_join[LL];
    if (!sv) {
        cudaStreamCreateWithFlags(&sv, cudaStreamNonBlocking);
        cudaEventCreateWithFlags(&ev_start, cudaEventDisableTiming);
        cudaEventCreateWithFlags(&ev_pre, cudaEventDisableTiming);
        for (int l = 0; l < LL; l++) {
            cudaEventCreateWithFlags(&ev_fork[l], cudaEventDisableTiming);
            cudaEventCreateWithFlags(&ev_join[l], cudaEventDisableTiming);
        }
    }

    // ---- prologue fork ----
    cudaEventRecord(ev_start, 0);
    cudaStreamWaitEvent(sv, ev_start, 0);

    // sv chain
    k_zero_off<<<(NN + 2 + 255) / 256, 256, 0, sv>>>();
    k_hist<<<(EE + 255) / 256, 256, 0, sv>>>(edge_index);
    k_scan<<<1, SCAN_T, 0, sv>>>();
    k_scatter_e<<<(EE + 255) / 256, 256, 0, sv>>>(edge_index, edge_attr);
    k_zero<<<1, 128, 0, sv>>>(p_stats, 128);
    k_zero<<<1, 128, 0, sv>>>(p_stats2, 128);
    k_zero<<<1, 128, 0, sv>>>(p_stats_v, 128);
    const int wgrid = (128 * DD + 255) / 256;
    for (int l = 0; l < LL; l++) {
        k_split_w<<<wgrid, 256, 0, sv>>>(conv_W1 + (size_t)l * DD * DD,
                                         p_whi + (size_t)l * wslot, p_wlo + (size_t)l * wslot);
        k_split_w<<<wgrid, 256, 0, sv>>>(conv_W2 + (size_t)l * DD * DD,
                                         p_whi + (size_t)(5 + l) * wslot,
                                         p_wlo + (size_t)(5 + l) * wslot);
    }
    for (int l = 0; l < LL - 1; l++) {
        k_split_w<<<wgrid, 256, 0, sv>>>(vn_W1 + (size_t)l * DD * DD,
                                         p_whi + (size_t)(10 + l) * wslot,
                                         p_wlo + (size_t)(10 + l) * wslot);
        k_split_w<<<wgrid, 256, 0, sv>>>(vn_W2 + (size_t)l * DD * DD,
                                         p_whi + (size_t)(14 + l) * wslot,
                                         p_wlo + (size_t)(14 + l) * wslot);
    }
    cudaEventRecord(ev_pre, sv);

    // main chain
    k_zero<<<(GG * 64 + 255) / 256, 256>>>(p_pooled, GG * 64);
    k_build_lut<<<(216 * 64 + 255) / 256, 256>>>(bond_emb);
    k_encode_atoms<<<blkN, 256>>>(x, atom_emb, vn_emb, batch, out);
    k_vn_init<<<(GG * DD + 255) / 256, 256>>>(vn_emb);
    cudaStreamWaitEvent(0, ev_pre, 0);

    const int gBig = (NN + BM - 1) / BM;
    const dim3 gSmall((GG + 63) / 64, 2);
    const int gAgg = (NN * 32 + 255) / 256;

    for (int l = 0; l < LL; l++) {
        float* h = out + (size_t)l * slot;
        float* z_out = out + (size_t)(l + 1) * slot;

        // vn chain on sv (unchanged)
        if (l < LL - 1) {
            cudaEventRecord(ev_fork[l], 0);
            cudaStreamWaitEvent(sv, ev_fork[l], 0);
            k_gemm_small<3><<<gSmall, 256, 0, sv>>>(p_pooled, p_vn,
                                                    p_whi + (size_t)(10 + l) * wslot,
                                                    p_wlo + (size_t)(10 + l) * wslot,
                                                    vn_b1 + l * DD, p_vt, GG,
                                                    p_stats_v, nullptr);
            k_zero<<<(GG * 64 + 255) / 256, 256, 0, sv>>>(p_pooled, GG * 64);
            k_bn_prep<<<1, 256, 0, sv>>>(p_stats_v, p_bnp_v,
                                         vn_bn1_g + l * DD, vn_bn1_b + l * DD, invG);
            k_gemm_small<2><<<gSmall, 256, 0, sv>>>(p_vt, nullptr,
                                                    p_whi + (size_t)(14 + l) * wslot,
                                                    p_wlo + (size_t)(14 + l) * wslot,
                                                    vn_b2 + l * DD, p_vt2, GG,
                                                    p_stats_v, p_bnp_v);
            k_bn_prep<<<1, 256, 0, sv>>>(p_stats_v, p_bnp_v,
                                         vn_bn2_g + l * DD, vn_bn2_b + l * DD, invG);
            k_bn_apply<<<(GG * 64 + 255) / 256, 256, 0, sv>>>(p_vt2, p_vn, p_bnp_v,
                                                              nullptr, nullptr, nullptr, 0.f,
                                                              nullptr, GG, 1, 0, 0);
            cudaEventRecord(ev_join[l], sv);
        }

        // main path: agg (+stats zero) -> GEMM1 -> GEMM2(fused prep) -> bn_apply(fused prep)
        k_agg<<<gAgg, 256>>>(h, gin_eps + l);
        k_gemm_big<0><<<gBig, 256, SMEM_BIG>>>(p_t,
                                               p_whi + (size_t)l * wslot,
                                               p_wlo + (size_t)l * wslot,
                                               conv_b1 + l * DD, p_y, NN,
                                               p_stats, nullptr, nullptr, nullptr, 0.f);
        k_gemm_big<2><<<gBig, 256, SMEM_BIG>>>(p_y,
                                               p_whi + (size_t)(5 + l) * wslot,
                                               p_wlo + (size_t)(5 + l) * wslot,
                                               conv_b2 + l * DD, p_t, NN,
                                               p_stats2, p_stats,
                                               conv_bn_g + l * DD, conv_bn_b + l * DD, invN);
        if (l < LL - 1) cudaStreamWaitEvent(0, ev_join[l], 0);
        int relu = (l < LL - 1) ? 1 : 0;
        int vnadd = (l < LL - 1) ? 1 : 0;
        int pool = (l < LL - 2) ? 1 : 0;
        k_bn_apply<<<blkN, 256>>>(p_t, z_out, nullptr, p_stats2,
                                  outer_bn_g + l * DD, outer_bn_b + l * DD, invN,
                                  batch, NN, relu, vnadd, pool);
    }
}

// round 15
// speedup vs baseline: 1.1419x; 1.0275x over previous
#include <cuda_runtime.h>
#include <cuda_bf16.h>
#include <cstdint>

#define NN 100000
#define EE 300000
#define GG 4096
#define DD 256
#define LL 5
#define BN_EPS 1e-5f
#define NW 18

// ---------------- scratch (device globals; no allocations) ----------------
__device__ int g_off[NN + 2];
__device__ int g_cur[NN];
__device__ uint32_t g_epack[EE];
__device__ float g_lut[216 * DD];
__device__ float g_t[(size_t)NN * DD];
__device__ float g_y[(size_t)NN * DD];
__device__ float g_vn[(size_t)GG * DD];
__device__ float g_pooled[(size_t)GG * DD];
__device__ float g_vt[(size_t)GG * DD];
__device__ float g_vt2[(size_t)GG * DD];
__device__ float g_stats[2 * DD];                  // GEMM1 output stats
__device__ float g_stats2[2 * DD];                 // GEMM2 output stats
__device__ float g_stats_v[2 * DD];                // vn-path stats
__device__ float g_bnp_v[2 * DD];                  // vn-path bn scale/shift
__device__ uint32_t g_whi[(size_t)NW * 128 * DD];
__device__ uint32_t g_wlo[(size_t)NW * 128 * DD];

__device__ __forceinline__ void red2(float* p, float a, float b) {
    asm volatile("red.global.add.v2.f32 [%0], {%1,%2};" :: "l"(p), "f"(a), "f"(b) : "memory");
}
__device__ __forceinline__ void red4(float* p, float a, float b, float c, float d) {
    asm volatile("red.global.add.v4.f32 [%0], {%1,%2,%3,%4};"
                 :: "l"(p), "f"(a), "f"(b), "f"(c), "f"(d) : "memory");
}
__device__ __forceinline__ void cp16(uint32_t smem_addr, const void* g) {
    asm volatile("cp.async.cg.shared.global [%0], [%1], 16;" :: "r"(smem_addr), "l"(g));
}
__device__ __forceinline__ void cp_commit() {
    asm volatile("cp.async.commit_group;");
}
__device__ __forceinline__ void cp_wait0() {
    asm volatile("cp.async.wait_group 0;");
}

__device__ __forceinline__ uint32_t pack_bf2(float a, float b) {
    __nv_bfloat162 t = __floats2bfloat162_rn(a, b);
    return *(uint32_t*)&t;
}
__device__ __forceinline__ void split_pack(float a, float b, uint32_t& hi, uint32_t& lo) {
    __nv_bfloat16 ah = __float2bfloat16_rn(a);
    __nv_bfloat16 bh = __float2bfloat16_rn(b);
    float al = a - __bfloat162float(ah);
    float bl = b - __bfloat162float(bh);
    __nv_bfloat162 h2; h2.x = ah; h2.y = bh;
    hi = *(uint32_t*)&h2;
    lo = pack_bf2(al, bl);
}

// ---------------- small kernels ----------------
__global__ void k_zero(float* p, int n4) {
    int i = blockIdx.x * blockDim.x + threadIdx.x;
    if (i < n4) ((float4*)p)[i] = make_float4(0.f, 0.f, 0.f, 0.f);
}
__global__ void k_zero_off() {
    int i = blockIdx.x * blockDim.x + threadIdx.x;
    if (i < NN + 2) g_off[i] = 0;
}

__global__ void k_split_w(const float* __restrict__ W, uint32_t* __restrict__ hi,
                          uint32_t* __restrict__ lo) {
    int i = blockIdx.x * blockDim.x + threadIdx.x;
    if (i >= 128 * DD) return;
    int k2 = i >> 8, n = i & 255;
    float a = W[(size_t)(2 * k2) * DD + n];
    float b = W[(size_t)(2 * k2 + 1) * DD + n];
    split_pack(a, b, hi[i], lo[i]);
}

__global__ void k_build_lut(const float* __restrict__ bond_emb) {
    int idx = blockIdx.x * blockDim.x + threadIdx.x;
    if (idx >= 216 * 64) return;
    int c = idx >> 6;
    int d4 = (idx & 63) * 4;
    int v0 = c / 36, v1 = (c / 6) % 6, v2 = c % 6;
    float4 a = *(const float4*)(bond_emb + ((size_t)(0 * 6 + v0) * DD + d4));
    float4 b = *(const float4*)(bond_emb + ((size_t)(1 * 6 + v1) * DD + d4));
    float4 d = *(const float4*)(bond_emb + ((size_t)(2 * 6 + v2) * DD + d4));
    *(float4*)(g_lut + (size_t)c * DD + d4) =
        make_float4(a.x + b.x + d.x, a.y + b.y + d.y, a.z + b.z + d.z, a.w + b.w + d.w);
}

// ---- CSR build ----
__global__ void k_hist(const int* __restrict__ ei) {
    int e = blockIdx.x * blockDim.x + threadIdx.x;
    if (e < EE) atomicAdd(&g_off[ei[EE + e]], 1);
}

#define SCAN_T 1024
#define SCAN_CH 98
__global__ void k_scan() {
    __shared__ int ssum[SCAN_T];
    int t = threadIdx.x;
    int begin = t * SCAN_CH;
    int end = min(NN, begin + SCAN_CH);
    int s = 0;
    for (int i = begin; i < end; i++) s += g_off[i];
    ssum[t] = s;
    __syncthreads();
    for (int d = 1; d < SCAN_T; d <<= 1) {
        int v = (t >= d) ? ssum[t - d] : 0;
        __syncthreads();
        ssum[t] += v;
        __syncthreads();
    }
    int run = ssum[t] - s;
    for (int i = begin; i < end; i++) {
        int c = g_off[i];
        g_off[i] = run;
        g_cur[i] = run;
        run += c;
    }
    if (t == SCAN_T - 1) g_off[NN] = ssum[SCAN_T - 1];
}

__global__ void k_scatter_e(const int* __restrict__ ei, const int* __restrict__ ea_idx) {
    int e = blockIdx.x * blockDim.x + threadIdx.x;
    if (e >= EE) return;
    int dst = ei[EE + e];
    int src = ei[e];
    int code = ea_idx[e * 3 + 0] * 36 + ea_idx[e * 3 + 1] * 6 + ea_idx[e * 3 + 2];
    int pos = atomicAdd(&g_cur[dst], 1);
    g_epack[pos] = (uint32_t)src * 256u + (uint32_t)code;
}

// CSR aggregation fused with gin_combine, edge loop unrolled x2 for MLP.
// z = (1+eps)*h[node] + sum relu(h[src]+lut). Accumulation order preserved.
// block 0 zeroes the ping-pong stats buffers.
__global__ void __launch_bounds__(256)
k_agg(const float* __restrict__ h, const float* __restrict__ epsp) {
    if (blockIdx.x == 0) {
        int t = threadIdx.x;
        g_stats[t] = 0.f;
        g_stats[t + 256] = 0.f;
        g_stats2[t] = 0.f;
        g_stats2[t + 256] = 0.f;
    }
    int gw = (blockIdx.x * 256 + threadIdx.x) >> 5;
    if (gw >= NN) return;
    int lane = threadIdx.x & 31;
    int base = lane * 8;
    float e = 1.0f + __ldg(epsp);
    float acc[8] = {0.f, 0.f, 0.f, 0.f, 0.f, 0.f, 0.f, 0.f};
    int p0 = g_off[gw], p1 = g_off[gw + 1];
    int p = p0;
    for (; p + 1 < p1; p += 2) {
        uint32_t pk0 = __ldg(&g_epack[p]);
        uint32_t pk1 = __ldg(&g_epack[p + 1]);
        const float* hr0 = h + (size_t)(pk0 >> 8) * DD + base;
        const float* hr1 = h + (size_t)(pk1 >> 8) * DD + base;
        const float* lr0 = g_lut + (size_t)(pk0 & 255u) * DD + base;
        const float* lr1 = g_lut + (size_t)(pk1 & 255u) * DD + base;
        // issue all 8 loads before consuming any
        float4 a0 = *(const float4*)hr0;
        float4 a1 = *(const float4*)(hr0 + 4);
        float4 b0 = *(const float4*)hr1;
        float4 b1 = *(const float4*)(hr1 + 4);
        float4 la0 = *(const float4*)lr0;
        float4 la1 = *(const float4*)(lr0 + 4);
        float4 lb0 = *(const float4*)lr1;
        float4 lb1 = *(const float4*)(lr1 + 4);
        acc[0] += fmaxf(a0.x + la0.x, 0.f);
        acc[1] += fmaxf(a0.y + la0.y, 0.f);
        acc[2] += fmaxf(a0.z + la0.z, 0.f);
        acc[3] += fmaxf(a0.w + la0.w, 0.f);
        acc[4] += fmaxf(a1.x + la1.x, 0.f);
        acc[5] += fmaxf(a1.y + la1.y, 0.f);
        acc[6] += fmaxf(a1.z + la1.z, 0.f);
        acc[7] += fmaxf(a1.w + la1.w, 0.f);
        acc[0] += fmaxf(b0.x + lb0.x, 0.f);
        acc[1] += fmaxf(b0.y + lb0.y, 0.f);
        acc[2] += fmaxf(b0.z + lb0.z, 0.f);
        acc[3] += fmaxf(b0.w + lb0.w, 0.f);
        acc[4] += fmaxf(b1.x + lb1.x, 0.f);
        acc[5] += fmaxf(b1.y + lb1.y, 0.f);
        acc[6] += fmaxf(b1.z + lb1.z, 0.f);
        acc[7] += fmaxf(b1.w + lb1.w, 0.f);
    }
    if (p < p1) {
        uint32_t pk = __ldg(&g_epack[p]);
        const float* hr = h + (size_t)(pk >> 8) * DD + base;
        const float* lr = g_lut + (size_t)(pk & 255u) * DD + base;
        float4 h0 = *(const float4*)hr;
        float4 h1 = *(const float4*)(hr + 4);
        float4 l0 = *(const float4*)lr;
        float4 l1 = *(const float4*)(lr + 4);
        acc[0] += fmaxf(h0.x + l0.x, 0.f);
        acc[1] += fmaxf(h0.y + l0.y, 0.f);
        acc[2] += fmaxf(h0.z + l0.z, 0.f);
        acc[3] += fmaxf(h0.w + l0.w, 0.f);
        acc[4] += fmaxf(h1.x + l1.x, 0.f);
        acc[5] += fmaxf(h1.y + l1.y, 0.f);
        acc[6] += fmaxf(h1.z + l1.z, 0.f);
        acc[7] += fmaxf(h1.w + l1.w, 0.f);
    }
    const float* hn = h + (size_t)gw * DD + base;
    float4 s0 = *(const float4*)hn;
    float4 s1 = *(const float4*)(hn + 4);
    float* o = g_t + (size_t)gw * DD + base;
    *(float4*)o = make_float4(e * s0.x + acc[0], e * s0.y + acc[1],
                              e * s0.z + acc[2], e * s0.w + acc[3]);
    *(float4*)(o + 4) = make_float4(e * s1.x + acc[4], e * s1.y + acc[5],
                                    e * s1.z + acc[6], e * s1.w + acc[7]);
}

// atom encoder: h0 = sum emb + vn0; also scatter h0 row into pooled
__global__ void k_encode_atoms(const int* __restrict__ x,
                               const float* __restrict__ atom_emb,
                               const float* __restrict__ vn_emb,
                               const int* __restrict__ batch,
                               float* __restrict__ out0) {
    int idx = blockIdx.x * blockDim.x + threadIdx.x;
    if (idx >= NN * 64) return;
    int n = idx >> 6;
    int d4 = (idx & 63) * 4;
    float4 acc = *(const float4*)(vn_emb + d4);
#pragma unroll
    for (int f = 0; f < 9; f++) {
        int v = __ldg(&x[n * 9 + f]);
        float4 e = *(const float4*)(atom_emb + ((size_t)(f * 120 + v) * DD + d4));
        acc.x += e.x; acc.y += e.y; acc.z += e.z; acc.w += e.w;
    }
    *(float4*)(out0 + (size_t)n * DD + d4) = acc;
    int g = __ldg(&batch[n]);
    red4(g_pooled + (size_t)g * DD + d4, acc.x, acc.y, acc.z, acc.w);
}

__global__ void k_vn_init(const float* __restrict__ vn_emb) {
    int i = blockIdx.x * blockDim.x + threadIdx.x;
    if (i < GG * DD) g_vn[i] = vn_emb[i & (DD - 1)];
}

// ---------------- GEMM common ----------------
__device__ __forceinline__ void mma_bf16(float* c, const uint32_t* a, uint32_t b0, uint32_t b1) {
    asm volatile(
        "mma.sync.aligned.m16n8k16.row.col.f32.bf16.bf16.f32 "
        "{%0,%1,%2,%3}, {%4,%5,%6,%7}, {%8,%9}, {%0,%1,%2,%3};"
        : "+f"(c[0]), "+f"(c[1]), "+f"(c[2]), "+f"(c[3])
        : "r"(a[0]), "r"(a[1]), "r"(a[2]), "r"(a[3]), "r"(b0), "r"(b1));
}

// MODE 0: A as-is.  MODE 2: A=relu(y*scale+shift).  MODE 3: A=A+A2.
template <int MODE>
__device__ __forceinline__ float4 load_a4(const float* A, const float* A2,
                                          const float* bnp, size_t off, int kidx) {
    float4 v;
    if (MODE == 0) {
        v = *(const float4*)(A + off);
    } else if (MODE == 2) {
        float4 yv = *(const float4*)(A + off);
        float4 sc = *(const float4*)(bnp + kidx);
        float4 sh = *(const float4*)(bnp + DD + kidx);
        v.x = fmaxf(yv.x * sc.x + sh.x, 0.f);
        v.y = fmaxf(yv.y * sc.y + sh.y, 0.f);
        v.z = fmaxf(yv.z * sc.z + sh.z, 0.f);
        v.w = fmaxf(yv.w * sc.w + sh.w, 0.f);
    } else {
        float4 hv = *(const float4*)(A + off);
        float4 av = *(const float4*)(A2 + off);
        v.x = hv.x + av.x; v.y = hv.y + av.y;
        v.z = hv.z + av.z; v.w = hv.w + av.w;
    }
    return v;
}

// ---------------- big GEMM: BM=64, BN=256, BK=32, 256 threads, occ 2 ----
// MODE 2 computes BN scale/shift in-prologue from stats_in (ping-pong buffers).
#define BM 64
#define A_SZ 1152
#define B_SZ 4224
#define B_BASE (4 * A_SZ)
#define SMEM_BIG ((4 * A_SZ + 4 * B_SZ) * 4)

template <int MODE>
__global__ void __launch_bounds__(256, 2)
k_gemm_big(const float* __restrict__ A, const uint32_t* __restrict__ Whi,
           const uint32_t* __restrict__ Wlo, const float* __restrict__ bias,
           float* __restrict__ C, int M, float* __restrict__ stats_out,
           const float* __restrict__ stats_in, const float* __restrict__ gamma,
           const float* __restrict__ beta, float Minv) {
    extern __shared__ uint32_t sm[];
    __shared__ __align__(16) float sbnp[2 * DD];
    const uint32_t sbase = (uint32_t)__cvta_generic_to_shared(sm);

    int tid = threadIdx.x;
    int lane = tid & 31;
    int wid = tid >> 5;
    int wr = wid >> 2;
    int wc = wid & 3;
    int row0 = blockIdx.x * BM;

    if (MODE == 2) {
        float mn = __ldg(&stats_in[tid]) * Minv;
        float var = __ldg(&stats_in[DD + tid]) * Minv - mn * mn;
        float rs = rsqrtf(var + BN_EPS);
        float sc = __ldg(&gamma[tid]) * rs;
        sbnp[tid] = sc;
        sbnp[DD + tid] = __ldg(&beta[tid]) - mn * sc;
        __syncthreads();
    }

    const int ar0 = tid >> 3;
    const int akk = (tid & 7) * 4;
    const int br = tid >> 6;
    const int bn4 = (tid & 63) * 4;

    float acc[2][8][4];
#pragma unroll
    for (int i = 0; i < 2; i++)
#pragma unroll
        for (int j = 0; j < 8; j++)
#pragma unroll
            for (int r = 0; r < 4; r++) acc[i][j][r] = 0.f;

    float4 vA[2];

    auto issueB = [&](int k0, int buf) {
        const uint32_t* wh = Whi + (size_t)(k0 >> 1) * DD;
        const uint32_t* wl = Wlo + (size_t)(k0 >> 1) * DD;
        uint32_t bhi = sbase + (B_BASE + buf * 2 * B_SZ) * 4;
        uint32_t blo = bhi + B_SZ * 4;
#pragma unroll
        for (int q = 0; q < 4; q++) {
            int r = br + q * 4;
            cp16(bhi + (r * 264 + bn4) * 4, wh + (size_t)r * DD + bn4);
            cp16(blo + (r * 264 + bn4) * 4, wl + (size_t)r * DD + bn4);
        }
        cp_commit();
    };
    auto loadA = [&](int k0) {
#pragma unroll
        for (int q = 0; q < 2; q++) {
            int gr = row0 + ar0 + q * 32;
            vA[q] = make_float4(0.f, 0.f, 0.f, 0.f);
            if (gr < M)
                vA[q] = load_a4<MODE>(A, nullptr, sbnp, (size_t)gr * DD + k0 + akk, k0 + akk);
        }
    };
    auto storeA = [&](int buf) {
        uint32_t* ahi = sm + buf * 2 * A_SZ;
        uint32_t* alo = ahi + A_SZ;
        int k2 = akk >> 1;
#pragma unroll
        for (int q = 0; q < 2; q++) {
            int r = ar0 + q * 32;
            uint32_t h0, l0, h1, l1;
            split_pack(vA[q].x, vA[q].y, h0, l0);
            split_pack(vA[q].z, vA[q].w, h1, l1);
            ahi[k2 * 72 + r] = h0;       alo[k2 * 72 + r] = l0;
            ahi[(k2 + 1) * 72 + r] = h1; alo[(k2 + 1) * 72 + r] = l1;
        }
    };

    issueB(0, 0);
    loadA(0);
    storeA(0);
    cp_wait0();
    __syncthreads();

#pragma unroll 1
    for (int it = 0; it < 8; it++) {
        int cur = it & 1;
        int nxt = cur ^ 1;
        if (it < 7) {
            issueB((it + 1) * 32, nxt);
            loadA((it + 1) * 32);
        }
        {
            const uint32_t* ahi = sm + cur * 2 * A_SZ;
            const uint32_t* alo = ahi + A_SZ;
            const uint32_t* bhi = sm + B_BASE + cur * 2 * B_SZ;
            const uint32_t* blo = bhi + B_SZ;
#pragma unroll
            for (int s = 0; s < 2; s++) {
                int kb = s * 8 + (lane & 3);
                uint32_t ah[2][4], al[2][4];
#pragma unroll
                for (int i = 0; i < 2; i++) {
                    int m = wr * 32 + i * 16 + (lane >> 2);
                    ah[i][0] = ahi[kb * 72 + m];       ah[i][1] = ahi[kb * 72 + m + 8];
                    ah[i][2] = ahi[(kb + 4) * 72 + m]; ah[i][3] = ahi[(kb + 4) * 72 + m + 8];
                    al[i][0] = alo[kb * 72 + m];       al[i][1] = alo[kb * 72 + m + 8];
                    al[i][2] = alo[(kb + 4) * 72 + m]; al[i][3] = alo[(kb + 4) * 72 + m + 8];
                }
#pragma unroll
                for (int j = 0; j < 8; j++) {
                    int n = wc * 64 + j * 8 + (lane >> 2);
                    uint32_t bh0 = bhi[kb * 264 + n], bh1 = bhi[(kb + 4) * 264 + n];
                    uint32_t bl0 = blo[kb * 264 + n], bl1 = blo[(kb + 4) * 264 + n];
#pragma unroll
                    for (int i = 0; i < 2; i++) {
                        mma_bf16(acc[i][j], ah[i], bh0, bh1);
                        mma_bf16(acc[i][j], ah[i], bl0, bl1);
                        mma_bf16(acc[i][j], al[i], bh0, bh1);
                    }
                }
            }
        }
        if (it < 7) {
            storeA(nxt);
            cp_wait0();
        }
        __syncthreads();
    }

#pragma unroll
    for (int j = 0; j < 8; j++) {
        int gc = wc * 64 + j * 8 + (lane & 3) * 2;
        float bx = __ldg(&bias[gc]);
        float by = __ldg(&bias[gc + 1]);
        float sx = 0.f, sy = 0.f, qx = 0.f, qy = 0.f;
#pragma unroll
        for (int i = 0; i < 2; i++) {
            int gr = row0 + wr * 32 + i * 16 + (lane >> 2);
            if (gr < M) {
                float2 v0 = make_float2(acc[i][j][0] + bx, acc[i][j][1] + by);
                *(float2*)(C + (size_t)gr * DD + gc) = v0;
                sx += v0.x; sy += v0.y; qx += v0.x * v0.x; qy += v0.y * v0.y;
            }
            if (gr + 8 < M) {
                float2 v1 = make_float2(acc[i][j][2] + bx, acc[i][j][3] + by);
                *(float2*)(C + (size_t)(gr + 8) * DD + gc) = v1;
                sx += v1.x; sy += v1.y; qx += v1.x * v1.x; qy += v1.y * v1.y;
            }
        }
#pragma unroll
        for (int d = 4; d < 32; d <<= 1) {
            sx += __shfl_xor_sync(0xffffffff, sx, d);
            sy += __shfl_xor_sync(0xffffffff, sy, d);
            qx += __shfl_xor_sync(0xffffffff, qx, d);
            qy += __shfl_xor_sync(0xffffffff, qy, d);
        }
        if ((lane >> 2) == 0) {
            red2(&stats_out[gc], sx, sy);
            red2(&stats_out[DD + gc], qx, qy);
        }
    }
}

// ---------------- small GEMM: BM=64, BN=128 (grid.y=2), 256 threads (unchanged) ----
template <int MODE>
__global__ void __launch_bounds__(256, 2)
k_gemm_small(const float* __restrict__ A, const float* __restrict__ A2,
             const uint32_t* __restrict__ Whi, const uint32_t* __restrict__ Wlo,
             const float* __restrict__ bias, float* __restrict__ C, int M,
             float* __restrict__ stats, const float* __restrict__ bnp) {
    __shared__ uint32_t As_hi[16][72];
    __shared__ uint32_t As_lo[16][72];
    __shared__ uint32_t Bs_hi[16][136];
    __shared__ uint32_t Bs_lo[16][136];

    int tid = threadIdx.x;
    int lane = tid & 31;
    int wid = tid >> 5;
    int wr = wid >> 1;
    int wc = wid & 1;
    int row0 = blockIdx.x * 64;
    int col0 = blockIdx.y * 128;

    float acc[8][4];
#pragma unroll
    for (int j = 0; j < 8; j++)
#pragma unroll
        for (int r = 0; r < 4; r++) acc[j][r] = 0.f;

    for (int k0 = 0; k0 < DD; k0 += 32) {
#pragma unroll
        for (int q = 0; q < 2; q++) {
            int li = tid + q * 256;
            int r = li >> 3;
            int kk = (li & 7) * 4;
            float4 v = make_float4(0.f, 0.f, 0.f, 0.f);
            int gr = row0 + r;
            if (gr < M) v = load_a4<MODE>(A, A2, bnp, (size_t)gr * DD + k0 + kk, k0 + kk);
            int k2 = kk >> 1;
            uint32_t h0, l0, h1, l1;
            split_pack(v.x, v.y, h0, l0);
            split_pack(v.z, v.w, h1, l1);
            As_hi[k2][r] = h0;     As_lo[k2][r] = l0;
            As_hi[k2 + 1][r] = h1; As_lo[k2 + 1][r] = l1;
        }
        {
            const uint32_t* wh = Whi + (size_t)(k0 >> 1) * DD + col0;
            const uint32_t* wl = Wlo + (size_t)(k0 >> 1) * DD + col0;
#pragma unroll
            for (int q = 0; q < 2; q++) {
                int li = tid + q * 256;
                int r = li >> 5;
                int n4 = (li & 31) * 4;
                *(uint4*)&Bs_hi[r][n4] = *(const uint4*)(wh + (size_t)r * DD + n4);
                *(uint4*)&Bs_lo[r][n4] = *(const uint4*)(wl + (size_t)r * DD + n4);
            }
        }
        __syncthreads();

#pragma unroll
        for (int s = 0; s < 2; s++) {
            int kb = s * 8 + (lane & 3);
            int m = wr * 16 + (lane >> 2);
            uint32_t ah[4], al[4];
            ah[0] = As_hi[kb][m];     ah[1] = As_hi[kb][m + 8];
            ah[2] = As_hi[kb + 4][m]; ah[3] = As_hi[kb + 4][m + 8];
            al[0] = As_lo[kb][m];     al[1] = As_lo[kb][m + 8];
            al[2] = As_lo[kb + 4][m]; al[3] = As_lo[kb + 4][m + 8];
#pragma unroll
            for (int j = 0; j < 8; j++) {
                int n = wc * 64 + j * 8 + (lane >> 2);
                uint32_t bh0 = Bs_hi[kb][n], bh1 = Bs_hi[kb + 4][n];
                uint32_t bl0 = Bs_lo[kb][n], bl1 = Bs_lo[kb + 4][n];
                mma_bf16(acc[j], ah, bh0, bh1);
                mma_bf16(acc[j], ah, bl0, bl1);
                mma_bf16(acc[j], al, bh0, bh1);
            }
        }
        __syncthreads();
    }

#pragma unroll
    for (int j = 0; j < 8; j++) {
        int gc = col0 + wc * 64 + j * 8 + (lane & 3) * 2;
        float bx = __ldg(&bias[gc]);
        float by = __ldg(&bias[gc + 1]);
        float sx = 0.f, sy = 0.f, qx = 0.f, qy = 0.f;
        int gr = row0 + wr * 16 + (lane >> 2);
        if (gr < M) {
            float2 v0 = make_float2(acc[j][0] + bx, acc[j][1] + by);
            *(float2*)(C + (size_t)gr * DD + gc) = v0;
            sx += v0.x; sy += v0.y; qx += v0.x * v0.x; qy += v0.y * v0.y;
        }
        if (gr + 8 < M) {
            float2 v1 = make_float2(acc[j][2] + bx, acc[j][3] + by);
            *(float2*)(C + (size_t)(gr + 8) * DD + gc) = v1;
            sx += v1.x; sy += v1.y; qx += v1.x * v1.x; qy += v1.y * v1.y;
        }
#pragma unroll
        for (int d = 4; d < 32; d <<= 1) {
            sx += __shfl_xor_sync(0xffffffff, sx, d);
            sy += __shfl_xor_sync(0xffffffff, sy, d);
            qx += __shfl_xor_sync(0xffffffff, qx, d);
            qy += __shfl_xor_sync(0xffffffff, qy, d);
        }
        if ((lane >> 2) == 0) {
            red2(&stats[gc], sx, sy);
            red2(&stats[DD + gc], qx, qy);
        }
    }
}

// ---------------- BN prep (vn path only) ----------------
__global__ void k_bn_prep(float* __restrict__ stats, float* __restrict__ bnp,
                          const float* __restrict__ gamma, const float* __restrict__ beta,
                          float Minv) {
    int c = threadIdx.x;
    float m = stats[c] * Minv;
    float var = stats[DD + c] * Minv - m * m;
    float rs = rsqrtf(var + BN_EPS);
    float sc = gamma[c] * rs;
    bnp[c] = sc;
    bnp[DD + c] = beta[c] - m * sc;
    stats[c] = 0.f;
    stats[DD + c] = 0.f;
}

// BN apply; if stats != nullptr compute scale/shift in-block from stats, else use bnp_pre
__global__ void k_bn_apply(const float* __restrict__ Yin, float* __restrict__ Yout,
                           const float* __restrict__ bnp_pre, const float* __restrict__ stats,
                           const float* __restrict__ gamma, const float* __restrict__ beta,
                           float Minv, const int* __restrict__ batch,
                           int M, int do_relu, int do_vn, int do_pool) {
    __shared__ __align__(16) float sb[2 * DD];
    int tid = threadIdx.x;
    if (stats) {
        float m = __ldg(&stats[tid]) * Minv;
        float var = __ldg(&stats[DD + tid]) * Minv - m * m;
        float rs = rsqrtf(var + BN_EPS);
        float sc = __ldg(&gamma[tid]) * rs;
        sb[tid] = sc;
        sb[DD + tid] = __ldg(&beta[tid]) - m * sc;
    } else {
        sb[tid] = bnp_pre[tid];
        sb[DD + tid] = bnp_pre[DD + tid];
    }
    __syncthreads();

    int idx = blockIdx.x * blockDim.x + tid;
    if (idx >= M * 64) return;
    int r = idx >> 6;
    int c4 = (idx & 63) * 4;
    float4 sc = *(const float4*)(sb + c4);
    float4 sh = *(const float4*)(sb + DD + c4);
    float4 v = *(const float4*)(Yin + (size_t)r * DD + c4);
    v.x = v.x * sc.x + sh.x;
    v.y = v.y * sc.y + sh.y;
    v.z = v.z * sc.z + sh.z;
    v.w = v.w * sc.w + sh.w;
    if (do_relu) {
        v.x = fmaxf(v.x, 0.f); v.y = fmaxf(v.y, 0.f);
        v.z = fmaxf(v.z, 0.f); v.w = fmaxf(v.w, 0.f);
    }
    int g = 0;
    if (do_vn || do_pool) g = __ldg(&batch[r]);
    if (do_vn) {
        float4 w = *(const float4*)(g_vn + (size_t)g * DD + c4);
        v.x += w.x; v.y += w.y; v.z += w.z; v.w += w.w;
    }
    *(float4*)(Yout + (size_t)r * DD + c4) = v;
    if (do_pool) red4(g_pooled + (size_t)g * DD + c4, v.x, v.y, v.z, v.w);
}

// ---------------- host orchestration ----------------
extern "C" void kernel_launch(void* const* d_in, const int* in_sizes, int n_in,
                              void* d_out, int out_size) {
    const int* x          = (const int*)d_in[0];
    const int* edge_index = (const int*)d_in[1];
    const int* edge_attr  = (const int*)d_in[2];
    const int* batch      = (const int*)d_in[3];
    const float* atom_emb = (const float*)d_in[4];
    const float* bond_emb = (const float*)d_in[5];
    const float* vn_emb   = (const float*)d_in[6];
    const float* gin_eps  = (const float*)d_in[7];
    const float* conv_W1  = (const float*)d_in[8];
    const float* conv_b1  = (const float*)d_in[9];
    const float* conv_bn_g = (const float*)d_in[10];
    const float* conv_bn_b = (const float*)d_in[11];
    const float* conv_W2  = (const float*)d_in[12];
    const float* conv_b2  = (const float*)d_in[13];
    const float* outer_bn_g = (const float*)d_in[14];
    const float* outer_bn_b = (const float*)d_in[15];
    const float* vn_W1    = (const float*)d_in[16];
    const float* vn_b1    = (const float*)d_in[17];
    const float* vn_bn1_g = (const float*)d_in[18];
    const float* vn_bn1_b = (const float*)d_in[19];
    const float* vn_W2    = (const float*)d_in[20];
    const float* vn_b2    = (const float*)d_in[21];
    const float* vn_bn2_g = (const float*)d_in[22];
    const float* vn_bn2_b = (const float*)d_in[23];
    float* out = (float*)d_out;

    cudaFuncSetAttribute(k_gemm_big<0>, cudaFuncAttributeMaxDynamicSharedMemorySize, SMEM_BIG);
    cudaFuncSetAttribute(k_gemm_big<2>, cudaFuncAttributeMaxDynamicSharedMemorySize, SMEM_BIG);

    float *p_t, *p_y, *p_pooled, *p_vt, *p_vt2, *p_vn;
    float *p_stats, *p_stats2, *p_stats_v, *p_bnp_v;
    uint32_t *p_whi, *p_wlo;
    cudaGetSymbolAddress((void**)&p_t, g_t);
    cudaGetSymbolAddress((void**)&p_y, g_y);
    cudaGetSymbolAddress((void**)&p_pooled, g_pooled);
    cudaGetSymbolAddress((void**)&p_vt, g_vt);
    cudaGetSymbolAddress((void**)&p_vt2, g_vt2);
    cudaGetSymbolAddress((void**)&p_vn, g_vn);
    cudaGetSymbolAddress((void**)&p_stats, g_stats);
    cudaGetSymbolAddress((void**)&p_stats2, g_stats2);
    cudaGetSymbolAddress((void**)&p_stats_v, g_stats_v);
    cudaGetSymbolAddress((void**)&p_bnp_v, g_bnp_v);
    cudaGetSymbolAddress((void**)&p_whi, g_whi);
    cudaGetSymbolAddress((void**)&p_wlo, g_wlo);

    const size_t slot = (size_t)NN * DD;
    const size_t wslot = (size_t)128 * DD;
    const int blkN = (NN * 64 + 255) / 256;
    const float invN = 1.0f / (float)NN;
    const float invG = 1.0f / (float)GG;

    // static stream/events: created once on first (correctness) call so all
    // driver-side pools predate the capture baseline
    static cudaStream_t sv = nullptr;
    static cudaEvent_t ev_start, ev_pre, ev_fork[LL], ev_join[LL];
    if (!sv) {
        cudaStreamCreateWithFlags(&sv, cudaStreamNonBlocking);
        cudaEventCreateWithFlags(&ev_start, cudaEventDisableTiming);
        cudaEventCreateWithFlags(&ev_pre, cudaEventDisableTiming);
        for (int l = 0; l < LL; l++) {
            cudaEventCreateWithFlags(&ev_fork[l], cudaEventDisableTiming);
            cudaEventCreateWithFlags(&ev_join[l], cudaEventDisableTiming);
        }
    }

    // ---- prologue fork ----
    cudaEventRecord(ev_start, 0);
    cudaStreamWaitEvent(sv, ev_start, 0);

    // sv chain
    k_zero_off<<<(NN + 2 + 255) / 256, 256, 0, sv>>>();
    k_hist<<<(EE + 255) / 256, 256, 0, sv>>>(edge_index);
    k_scan<<<1, SCAN_T, 0, sv>>>();
    k_scatter_e<<<(EE + 255) / 256, 256, 0, sv>>>(edge_index, edge_attr);
    k_zero<<<1, 128, 0, sv>>>(p_stats, 128);
    k_zero<<<1, 128, 0, sv>>>(p_stats2, 128);
    k_zero<<<1, 128, 0, sv>>>(p_stats_v, 128);
    const int wgrid = (128 * DD + 255) / 256;
    for (int l = 0; l < LL; l++) {
        k_split_w<<<wgrid, 256, 0, sv>>>(conv_W1 + (size_t)l * DD * DD,
                                         p_whi + (size_t)l * wslot, p_wlo + (size_t)l * wslot);
        k_split_w<<<wgrid, 256, 0, sv>>>(conv_W2 + (size_t)l * DD * DD,
                                         p_whi + (size_t)(5 + l) * wslot,
                                         p_wlo + (size_t)(5 + l) * wslot);
    }
    for (int l = 0; l < LL - 1; l++) {
        k_split_w<<<wgrid, 256, 0, sv>>>(vn_W1 + (size_t)l * DD * DD,
                                         p_whi + (size_t)(10 + l) * wslot,
                                         p_wlo + (size_t)(10 + l) * wslot);
        k_split_w<<<wgrid, 256, 0, sv>>>(vn_W2 + (size_t)l * DD * DD,
                                         p_whi + (size_t)(14 + l) * wslot,
                                         p_wlo + (size_t)(14 + l) * wslot);
    }
    cudaEventRecord(ev_pre, sv);

    // main chain
    k_zero<<<(GG * 64 + 255) / 256, 256>>>(p_pooled, GG * 64);
    k_build_lut<<<(216 * 64 + 255) / 256, 256>>>(bond_emb);
    k_encode_atoms<<<blkN, 256>>>(x, atom_emb, vn_emb, batch, out);
    k_vn_init<<<(GG * DD + 255) / 256, 256>>>(vn_emb);
    cudaStreamWaitEvent(0, ev_pre, 0);

    const int gBig = (NN + BM - 1) / BM;
    const dim3 gSmall((GG + 63) / 64, 2);
    const int gAgg = (NN * 32 + 255) / 256;

    for (int l = 0; l < LL; l++) {
        float* h = out + (size_t)l * slot;
        float* z_out = out + (size_t)(l + 1) * slot;

        // vn chain on sv (unchanged)
        if (l < LL - 1) {
            cudaEventRecord(ev_fork[l], 0);
            cudaStreamWaitEvent(sv, ev_fork[l], 0);
            k_gemm_small<3><<<gSmall, 256, 0, sv>>>(p_pooled, p_vn,
                                                    p_whi + (size_t)(10 + l) * wslot,
                                                    p_wlo + (size_t)(10 + l) * wslot,
                                                    vn_b1 + l * DD, p_vt, GG,
                                                    p_stats_v, nullptr);
            k_zero<<<(GG * 64 + 255) / 256, 256, 0, sv>>>(p_pooled, GG * 64);
            k_bn_prep<<<1, 256, 0, sv>>>(p_stats_v, p_bnp_v,
                                         vn_bn1_g + l * DD, vn_bn1_b + l * DD, invG);
            k_gemm_small<2><<<gSmall, 256, 0, sv>>>(p_vt, nullptr,
                                                    p_whi + (size_t)(14 + l) * wslot,
                                                    p_wlo + (size_t)(14 + l) * wslot,
                                                    vn_b2 + l * DD, p_vt2, GG,
                                                    p_stats_v, p_bnp_v);
            k_bn_prep<<<1, 256, 0, sv>>>(p_stats_v, p_bnp_v,
                                         vn_bn2_g + l * DD, vn_bn2_b + l * DD, invG);
            k_bn_apply<<<(GG * 64 + 255) / 256, 256, 0, sv>>>(p_vt2, p_vn, p_bnp_v,
                                                              nullptr, nullptr, nullptr, 0.f,
                                                              nullptr, GG, 1, 0, 0);
            cudaEventRecord(ev_join[l], sv);
        }

        // main path: agg (+stats zero) -> GEMM1 -> GEMM2(fused prep) -> bn_apply(fused prep)
        k_agg<<<gAgg, 256>>>(h, gin_eps + l);
        k_gemm_big<0><<<gBig, 256, SMEM_BIG>>>(p_t,
                                               p_whi + (size_t)l * wslot,
                                               p_wlo + (size_t)l * wslot,
                                               conv_b1 + l * DD, p_y, NN,
                                               p_stats, nullptr, nullptr, nullptr, 0.f);
        k_gemm_big<2><<<gBig, 256, SMEM_BIG>>>(p_y,
                                               p_whi + (size_t)(5 + l) * wslot,
                                               p_wlo + (size_t)(5 + l) * wslot,
                                               conv_b2 + l * DD, p_t, NN,
                                               p_stats2, p_stats,
                                               conv_bn_g + l * DD, conv_bn_b + l * DD, invN);
        if (l < LL - 1) cudaStreamWaitEvent(0, ev_join[l], 0);
        int relu = (l < LL - 1) ? 1 : 0;
        int vnadd = (l < LL - 1) ? 1 : 0;
        int pool = (l < LL - 2) ? 1 : 0;
        k_bn_apply<<<blkN, 256>>>(p_t, z_out, nullptr, p_stats2,
                                  outer_bn_g + l * DD, outer_bn_b + l * DD, invN,
                                  batch, NN, relu, vnadd, pool);
    }
}

// round 16
// speedup vs baseline: 1.1437x; 1.0016x over previous
#include <cuda_runtime.h>
#include <cuda_bf16.h>
#include <cstdint>

#define NN 100000
#define EE 300000
#define GG 4096
#define DD 256
#define LL 5
#define BN_EPS 1e-5f
#define NW 18

// ---------------- scratch (device globals; no allocations) ----------------
__device__ int g_off[NN + 2];
__device__ int g_cur[NN];
__device__ uint32_t g_epack[EE];
__device__ float g_lut[216 * DD];
__device__ float g_t[(size_t)NN * DD];
__device__ float g_y[(size_t)NN * DD];
__device__ float g_vn[(size_t)GG * DD];
__device__ float g_pooled[(size_t)GG * DD];
__device__ float g_vt[(size_t)GG * DD];
__device__ float g_vt2[(size_t)GG * DD];
__device__ float g_stats[2 * DD];                  // GEMM1 output stats
__device__ float g_stats2[2 * DD];                 // GEMM2 output stats
__device__ float g_stats_v[2 * DD];                // vn-path stats
__device__ float g_bnp_v[2 * DD];                  // vn-path bn scale/shift
__device__ uint32_t g_whi[(size_t)NW * 128 * DD];
__device__ uint32_t g_wlo[(size_t)NW * 128 * DD];

__device__ __forceinline__ void red2(float* p, float a, float b) {
    asm volatile("red.global.add.v2.f32 [%0], {%1,%2};" :: "l"(p), "f"(a), "f"(b) : "memory");
}
__device__ __forceinline__ void red4(float* p, float a, float b, float c, float d) {
    asm volatile("red.global.add.v4.f32 [%0], {%1,%2,%3,%4};"
                 :: "l"(p), "f"(a), "f"(b), "f"(c), "f"(d) : "memory");
}
__device__ __forceinline__ void cp16(uint32_t smem_addr, const void* g) {
    asm volatile("cp.async.cg.shared.global [%0], [%1], 16;" :: "r"(smem_addr), "l"(g));
}
__device__ __forceinline__ void cp_commit() {
    asm volatile("cp.async.commit_group;");
}
__device__ __forceinline__ void cp_wait0() {
    asm volatile("cp.async.wait_group 0;");
}

__device__ __forceinline__ uint32_t pack_bf2(float a, float b) {
    __nv_bfloat162 t = __floats2bfloat162_rn(a, b);
    return *(uint32_t*)&t;
}
__device__ __forceinline__ void split_pack(float a, float b, uint32_t& hi, uint32_t& lo) {
    __nv_bfloat16 ah = __float2bfloat16_rn(a);
    __nv_bfloat16 bh = __float2bfloat16_rn(b);
    float al = a - __bfloat162float(ah);
    float bl = b - __bfloat162float(bh);
    __nv_bfloat162 h2; h2.x = ah; h2.y = bh;
    hi = *(uint32_t*)&h2;
    lo = pack_bf2(al, bl);
}

// ---------------- small kernels ----------------
__global__ void k_zero(float* p, int n4) {
    int i = blockIdx.x * blockDim.x + threadIdx.x;
    if (i < n4) ((float4*)p)[i] = make_float4(0.f, 0.f, 0.f, 0.f);
}
__global__ void k_zero_off() {
    int i = blockIdx.x * blockDim.x + threadIdx.x;
    if (i < NN + 2) g_off[i] = 0;
}

__global__ void k_split_w(const float* __restrict__ W, uint32_t* __restrict__ hi,
                          uint32_t* __restrict__ lo) {
    int i = blockIdx.x * blockDim.x + threadIdx.x;
    if (i >= 128 * DD) return;
    int k2 = i >> 8, n = i & 255;
    float a = W[(size_t)(2 * k2) * DD + n];
    float b = W[(size_t)(2 * k2 + 1) * DD + n];
    split_pack(a, b, hi[i], lo[i]);
}

__global__ void k_build_lut(const float* __restrict__ bond_emb) {
    int idx = blockIdx.x * blockDim.x + threadIdx.x;
    if (idx >= 216 * 64) return;
    int c = idx >> 6;
    int d4 = (idx & 63) * 4;
    int v0 = c / 36, v1 = (c / 6) % 6, v2 = c % 6;
    float4 a = *(const float4*)(bond_emb + ((size_t)(0 * 6 + v0) * DD + d4));
    float4 b = *(const float4*)(bond_emb + ((size_t)(1 * 6 + v1) * DD + d4));
    float4 d = *(const float4*)(bond_emb + ((size_t)(2 * 6 + v2) * DD + d4));
    *(float4*)(g_lut + (size_t)c * DD + d4) =
        make_float4(a.x + b.x + d.x, a.y + b.y + d.y, a.z + b.z + d.z, a.w + b.w + d.w);
}

// ---- CSR build ----
__global__ void k_hist(const int* __restrict__ ei) {
    int e = blockIdx.x * blockDim.x + threadIdx.x;
    if (e < EE) atomicAdd(&g_off[ei[EE + e]], 1);
}

#define SCAN_T 1024
#define SCAN_CH 98
__global__ void k_scan() {
    __shared__ int ssum[SCAN_T];
    int t = threadIdx.x;
    int begin = t * SCAN_CH;
    int end = min(NN, begin + SCAN_CH);
    int s = 0;
    for (int i = begin; i < end; i++) s += g_off[i];
    ssum[t] = s;
    __syncthreads();
    for (int d = 1; d < SCAN_T; d <<= 1) {
        int v = (t >= d) ? ssum[t - d] : 0;
        __syncthreads();
        ssum[t] += v;
        __syncthreads();
    }
    int run = ssum[t] - s;
    for (int i = begin; i < end; i++) {
        int c = g_off[i];
        g_off[i] = run;
        g_cur[i] = run;
        run += c;
    }
    if (t == SCAN_T - 1) g_off[NN] = ssum[SCAN_T - 1];
}

__global__ void k_scatter_e(const int* __restrict__ ei, const int* __restrict__ ea_idx) {
    int e = blockIdx.x * blockDim.x + threadIdx.x;
    if (e >= EE) return;
    int dst = ei[EE + e];
    int src = ei[e];
    int code = ea_idx[e * 3 + 0] * 36 + ea_idx[e * 3 + 1] * 6 + ea_idx[e * 3 + 2];
    int pos = atomicAdd(&g_cur[dst], 1);
    g_epack[pos] = (uint32_t)src * 256u + (uint32_t)code;
}

// CSR aggregation fused with gin_combine, edge loop unrolled x2 for MLP.
// z = (1+eps)*h[node] + sum relu(h[src]+lut). Accumulation order preserved.
// block 0 zeroes the ping-pong stats buffers.
__global__ void __launch_bounds__(256)
k_agg(const float* __restrict__ h, const float* __restrict__ epsp) {
    if (blockIdx.x == 0) {
        int t = threadIdx.x;
        g_stats[t] = 0.f;
        g_stats[t + 256] = 0.f;
        g_stats2[t] = 0.f;
        g_stats2[t + 256] = 0.f;
    }
    int gw = (blockIdx.x * 256 + threadIdx.x) >> 5;
    if (gw >= NN) return;
    int lane = threadIdx.x & 31;
    int base = lane * 8;
    float e = 1.0f + __ldg(epsp);
    float acc[8] = {0.f, 0.f, 0.f, 0.f, 0.f, 0.f, 0.f, 0.f};
    int p0 = g_off[gw], p1 = g_off[gw + 1];
    int p = p0;
    for (; p + 1 < p1; p += 2) {
        uint32_t pk0 = __ldg(&g_epack[p]);
        uint32_t pk1 = __ldg(&g_epack[p + 1]);
        const float* hr0 = h + (size_t)(pk0 >> 8) * DD + base;
        const float* hr1 = h + (size_t)(pk1 >> 8) * DD + base;
        const float* lr0 = g_lut + (size_t)(pk0 & 255u) * DD + base;
        const float* lr1 = g_lut + (size_t)(pk1 & 255u) * DD + base;
        float4 a0 = *(const float4*)hr0;
        float4 a1 = *(const float4*)(hr0 + 4);
        float4 b0 = *(const float4*)hr1;
        float4 b1 = *(const float4*)(hr1 + 4);
        float4 la0 = *(const float4*)lr0;
        float4 la1 = *(const float4*)(lr0 + 4);
        float4 lb0 = *(const float4*)lr1;
        float4 lb1 = *(const float4*)(lr1 + 4);
        acc[0] += fmaxf(a0.x + la0.x, 0.f);
        acc[1] += fmaxf(a0.y + la0.y, 0.f);
        acc[2] += fmaxf(a0.z + la0.z, 0.f);
        acc[3] += fmaxf(a0.w + la0.w, 0.f);
        acc[4] += fmaxf(a1.x + la1.x, 0.f);
        acc[5] += fmaxf(a1.y + la1.y, 0.f);
        acc[6] += fmaxf(a1.z + la1.z, 0.f);
        acc[7] += fmaxf(a1.w + la1.w, 0.f);
        acc[0] += fmaxf(b0.x + lb0.x, 0.f);
        acc[1] += fmaxf(b0.y + lb0.y, 0.f);
        acc[2] += fmaxf(b0.z + lb0.z, 0.f);
        acc[3] += fmaxf(b0.w + lb0.w, 0.f);
        acc[4] += fmaxf(b1.x + lb1.x, 0.f);
        acc[5] += fmaxf(b1.y + lb1.y, 0.f);
        acc[6] += fmaxf(b1.z + lb1.z, 0.f);
        acc[7] += fmaxf(b1.w + lb1.w, 0.f);
    }
    if (p < p1) {
        uint32_t pk = __ldg(&g_epack[p]);
        const float* hr = h + (size_t)(pk >> 8) * DD + base;
        const float* lr = g_lut + (size_t)(pk & 255u) * DD + base;
        float4 h0 = *(const float4*)hr;
        float4 h1 = *(const float4*)(hr + 4);
        float4 l0 = *(const float4*)lr;
        float4 l1 = *(const float4*)(lr + 4);
        acc[0] += fmaxf(h0.x + l0.x, 0.f);
        acc[1] += fmaxf(h0.y + l0.y, 0.f);
        acc[2] += fmaxf(h0.z + l0.z, 0.f);
        acc[3] += fmaxf(h0.w + l0.w, 0.f);
        acc[4] += fmaxf(h1.x + l1.x, 0.f);
        acc[5] += fmaxf(h1.y + l1.y, 0.f);
        acc[6] += fmaxf(h1.z + l1.z, 0.f);
        acc[7] += fmaxf(h1.w + l1.w, 0.f);
    }
    const float* hn = h + (size_t)gw * DD + base;
    float4 s0 = *(const float4*)hn;
    float4 s1 = *(const float4*)(hn + 4);
    float* o = g_t + (size_t)gw * DD + base;
    *(float4*)o = make_float4(e * s0.x + acc[0], e * s0.y + acc[1],
                              e * s0.z + acc[2], e * s0.w + acc[3]);
    *(float4*)(o + 4) = make_float4(e * s1.x + acc[4], e * s1.y + acc[5],
                                    e * s1.z + acc[6], e * s1.w + acc[7]);
}

// atom encoder: h0 = sum emb + vn0; also scatter h0 row into pooled
__global__ void k_encode_atoms(const int* __restrict__ x,
                               const float* __restrict__ atom_emb,
                               const float* __restrict__ vn_emb,
                               const int* __restrict__ batch,
                               float* __restrict__ out0) {
    int idx = blockIdx.x * blockDim.x + threadIdx.x;
    if (idx >= NN * 64) return;
    int n = idx >> 6;
    int d4 = (idx & 63) * 4;
    float4 acc = *(const float4*)(vn_emb + d4);
#pragma unroll
    for (int f = 0; f < 9; f++) {
        int v = __ldg(&x[n * 9 + f]);
        float4 e = *(const float4*)(atom_emb + ((size_t)(f * 120 + v) * DD + d4));
        acc.x += e.x; acc.y += e.y; acc.z += e.z; acc.w += e.w;
    }
    *(float4*)(out0 + (size_t)n * DD + d4) = acc;
    int g = __ldg(&batch[n]);
    red4(g_pooled + (size_t)g * DD + d4, acc.x, acc.y, acc.z, acc.w);
}

__global__ void k_vn_init(const float* __restrict__ vn_emb) {
    int i = blockIdx.x * blockDim.x + threadIdx.x;
    if (i < GG * DD) g_vn[i] = vn_emb[i & (DD - 1)];
}

// ---------------- GEMM common ----------------
__device__ __forceinline__ void mma_bf16(float* c, const uint32_t* a, uint32_t b0, uint32_t b1) {
    asm volatile(
        "mma.sync.aligned.m16n8k16.row.col.f32.bf16.bf16.f32 "
        "{%0,%1,%2,%3}, {%4,%5,%6,%7}, {%8,%9}, {%0,%1,%2,%3};"
        : "+f"(c[0]), "+f"(c[1]), "+f"(c[2]), "+f"(c[3])
        : "r"(a[0]), "r"(a[1]), "r"(a[2]), "r"(a[3]), "r"(b0), "r"(b1));
}

// MODE 0: A as-is.  MODE 2: A=relu(y*scale+shift).  MODE 3: A=A+A2.
template <int MODE>
__device__ __forceinline__ float4 load_a4(const float* A, const float* A2,
                                          const float* bnp, size_t off, int kidx) {
    float4 v;
    if (MODE == 0) {
        v = *(const float4*)(A + off);
    } else if (MODE == 2) {
        float4 yv = *(const float4*)(A + off);
        float4 sc = *(const float4*)(bnp + kidx);
        float4 sh = *(const float4*)(bnp + DD + kidx);
        v.x = fmaxf(yv.x * sc.x + sh.x, 0.f);
        v.y = fmaxf(yv.y * sc.y + sh.y, 0.f);
        v.z = fmaxf(yv.z * sc.z + sh.z, 0.f);
        v.w = fmaxf(yv.w * sc.w + sh.w, 0.f);
    } else {
        float4 hv = *(const float4*)(A + off);
        float4 av = *(const float4*)(A2 + off);
        v.x = hv.x + av.x; v.y = hv.y + av.y;
        v.z = hv.z + av.z; v.w = hv.w + av.w;
    }
    return v;
}

// ---------------- big GEMM: BM=64, BN=256, BK=32, 256 threads, occ 2 ----
// MODE 2 computes BN scale/shift in-prologue from stats_in (ping-pong buffers).
#define BM 64
#define A_SZ 1152
#define B_SZ 4224
#define B_BASE (4 * A_SZ)
#define SMEM_BIG ((4 * A_SZ + 4 * B_SZ) * 4)

template <int MODE>
__global__ void __launch_bounds__(256, 2)
k_gemm_big(const float* __restrict__ A, const uint32_t* __restrict__ Whi,
           const uint32_t* __restrict__ Wlo, const float* __restrict__ bias,
           float* __restrict__ C, int M, float* __restrict__ stats_out,
           const float* __restrict__ stats_in, const float* __restrict__ gamma,
           const float* __restrict__ beta, float Minv) {
    extern __shared__ uint32_t sm[];
    __shared__ __align__(16) float sbnp[2 * DD];
    const uint32_t sbase = (uint32_t)__cvta_generic_to_shared(sm);

    int tid = threadIdx.x;
    int lane = tid & 31;
    int wid = tid >> 5;
    int wr = wid >> 2;
    int wc = wid & 3;
    int row0 = blockIdx.x * BM;

    if (MODE == 2) {
        float mn = __ldg(&stats_in[tid]) * Minv;
        float var = __ldg(&stats_in[DD + tid]) * Minv - mn * mn;
        float rs = rsqrtf(var + BN_EPS);
        float sc = __ldg(&gamma[tid]) * rs;
        sbnp[tid] = sc;
        sbnp[DD + tid] = __ldg(&beta[tid]) - mn * sc;
        __syncthreads();
    }

    const int ar0 = tid >> 3;
    const int akk = (tid & 7) * 4;
    const int br = tid >> 6;
    const int bn4 = (tid & 63) * 4;

    float acc[2][8][4];
#pragma unroll
    for (int i = 0; i < 2; i++)
#pragma unroll
        for (int j = 0; j < 8; j++)
#pragma unroll
            for (int r = 0; r < 4; r++) acc[i][j][r] = 0.f;

    float4 vA[2];

    auto issueB = [&](int k0, int buf) {
        const uint32_t* wh = Whi + (size_t)(k0 >> 1) * DD;
        const uint32_t* wl = Wlo + (size_t)(k0 >> 1) * DD;
        uint32_t bhi = sbase + (B_BASE + buf * 2 * B_SZ) * 4;
        uint32_t blo = bhi + B_SZ * 4;
#pragma unroll
        for (int q = 0; q < 4; q++) {
            int r = br + q * 4;
            cp16(bhi + (r * 264 + bn4) * 4, wh + (size_t)r * DD + bn4);
            cp16(blo + (r * 264 + bn4) * 4, wl + (size_t)r * DD + bn4);
        }
        cp_commit();
    };
    auto loadA = [&](int k0) {
#pragma unroll
        for (int q = 0; q < 2; q++) {
            int gr = row0 + ar0 + q * 32;
            vA[q] = make_float4(0.f, 0.f, 0.f, 0.f);
            if (gr < M)
                vA[q] = load_a4<MODE>(A, nullptr, sbnp, (size_t)gr * DD + k0 + akk, k0 + akk);
        }
    };
    auto storeA = [&](int buf) {
        uint32_t* ahi = sm + buf * 2 * A_SZ;
        uint32_t* alo = ahi + A_SZ;
        int k2 = akk >> 1;
#pragma unroll
        for (int q = 0; q < 2; q++) {
            int r = ar0 + q * 32;
            uint32_t h0, l0, h1, l1;
            split_pack(vA[q].x, vA[q].y, h0, l0);
            split_pack(vA[q].z, vA[q].w, h1, l1);
            ahi[k2 * 72 + r] = h0;       alo[k2 * 72 + r] = l0;
            ahi[(k2 + 1) * 72 + r] = h1; alo[(k2 + 1) * 72 + r] = l1;
        }
    };

    issueB(0, 0);
    loadA(0);
    storeA(0);
    cp_wait0();
    __syncthreads();

#pragma unroll 1
    for (int it = 0; it < 8; it++) {
        int cur = it & 1;
        int nxt = cur ^ 1;
        if (it < 7) {
            issueB((it + 1) * 32, nxt);
            loadA((it + 1) * 32);
        }
        {
            const uint32_t* ahi = sm + cur * 2 * A_SZ;
            const uint32_t* alo = ahi + A_SZ;
            const uint32_t* bhi = sm + B_BASE + cur * 2 * B_SZ;
            const uint32_t* blo = bhi + B_SZ;
#pragma unroll
            for (int s = 0; s < 2; s++) {
                int kb = s * 8 + (lane & 3);
                uint32_t ah[2][4], al[2][4];
#pragma unroll
                for (int i = 0; i < 2; i++) {
                    int m = wr * 32 + i * 16 + (lane >> 2);
                    ah[i][0] = ahi[kb * 72 + m];       ah[i][1] = ahi[kb * 72 + m + 8];
                    ah[i][2] = ahi[(kb + 4) * 72 + m]; ah[i][3] = ahi[(kb + 4) * 72 + m + 8];
                    al[i][0] = alo[kb * 72 + m];       al[i][1] = alo[kb * 72 + m + 8];
                    al[i][2] = alo[(kb + 4) * 72 + m]; al[i][3] = alo[(kb + 4) * 72 + m + 8];
                }
#pragma unroll
                for (int j = 0; j < 8; j++) {
                    int n = wc * 64 + j * 8 + (lane >> 2);
                    uint32_t bh0 = bhi[kb * 264 + n], bh1 = bhi[(kb + 4) * 264 + n];
                    uint32_t bl0 = blo[kb * 264 + n], bl1 = blo[(kb + 4) * 264 + n];
#pragma unroll
                    for (int i = 0; i < 2; i++) {
                        mma_bf16(acc[i][j], ah[i], bh0, bh1);
                        mma_bf16(acc[i][j], ah[i], bl0, bl1);
                        mma_bf16(acc[i][j], al[i], bh0, bh1);
                    }
                }
            }
        }
        if (it < 7) {
            storeA(nxt);
            cp_wait0();
        }
        __syncthreads();
    }

#pragma unroll
    for (int j = 0; j < 8; j++) {
        int gc = wc * 64 + j * 8 + (lane & 3) * 2;
        float bx = __ldg(&bias[gc]);
        float by = __ldg(&bias[gc + 1]);
        float sx = 0.f, sy = 0.f, qx = 0.f, qy = 0.f;
#pragma unroll
        for (int i = 0; i < 2; i++) {
            int gr = row0 + wr * 32 + i * 16 + (lane >> 2);
            if (gr < M) {
                float2 v0 = make_float2(acc[i][j][0] + bx, acc[i][j][1] + by);
                *(float2*)(C + (size_t)gr * DD + gc) = v0;
                sx += v0.x; sy += v0.y; qx += v0.x * v0.x; qy += v0.y * v0.y;
            }
            if (gr + 8 < M) {
                float2 v1 = make_float2(acc[i][j][2] + bx, acc[i][j][3] + by);
                *(float2*)(C + (size_t)(gr + 8) * DD + gc) = v1;
                sx += v1.x; sy += v1.y; qx += v1.x * v1.x; qy += v1.y * v1.y;
            }
        }
#pragma unroll
        for (int d = 4; d < 32; d <<= 1) {
            sx += __shfl_xor_sync(0xffffffff, sx, d);
            sy += __shfl_xor_sync(0xffffffff, sy, d);
            qx += __shfl_xor_sync(0xffffffff, qx, d);
            qy += __shfl_xor_sync(0xffffffff, qy, d);
        }
        if ((lane >> 2) == 0) {
            red2(&stats_out[gc], sx, sy);
            red2(&stats_out[DD + gc], qx, qy);
        }
    }
}

// ---------------- small GEMM: BM=64, BN=128 (grid.y=2), 256 threads (unchanged) ----
template <int MODE>
__global__ void __launch_bounds__(256, 2)
k_gemm_small(const float* __restrict__ A, const float* __restrict__ A2,
             const uint32_t* __restrict__ Whi, const uint32_t* __restrict__ Wlo,
             const float* __restrict__ bias, float* __restrict__ C, int M,
             float* __restrict__ stats, const float* __restrict__ bnp) {
    __shared__ uint32_t As_hi[16][72];
    __shared__ uint32_t As_lo[16][72];
    __shared__ uint32_t Bs_hi[16][136];
    __shared__ uint32_t Bs_lo[16][136];

    int tid = threadIdx.x;
    int lane = tid & 31;
    int wid = tid >> 5;
    int wr = wid >> 1;
    int wc = wid & 1;
    int row0 = blockIdx.x * 64;
    int col0 = blockIdx.y * 128;

    float acc[8][4];
#pragma unroll
    for (int j = 0; j < 8; j++)
#pragma unroll
        for (int r = 0; r < 4; r++) acc[j][r] = 0.f;

    for (int k0 = 0; k0 < DD; k0 += 32) {
#pragma unroll
        for (int q = 0; q < 2; q++) {
            int li = tid + q * 256;
            int r = li >> 3;
            int kk = (li & 7) * 4;
            float4 v = make_float4(0.f, 0.f, 0.f, 0.f);
            int gr = row0 + r;
            if (gr < M) v = load_a4<MODE>(A, A2, bnp, (size_t)gr * DD + k0 + kk, k0 + kk);
            int k2 = kk >> 1;
            uint32_t h0, l0, h1, l1;
            split_pack(v.x, v.y, h0, l0);
            split_pack(v.z, v.w, h1, l1);
            As_hi[k2][r] = h0;     As_lo[k2][r] = l0;
            As_hi[k2 + 1][r] = h1; As_lo[k2 + 1][r] = l1;
        }
        {
            const uint32_t* wh = Whi + (size_t)(k0 >> 1) * DD + col0;
            const uint32_t* wl = Wlo + (size_t)(k0 >> 1) * DD + col0;
#pragma unroll
            for (int q = 0; q < 2; q++) {
                int li = tid + q * 256;
                int r = li >> 5;
                int n4 = (li & 31) * 4;
                *(uint4*)&Bs_hi[r][n4] = *(const uint4*)(wh + (size_t)r * DD + n4);
                *(uint4*)&Bs_lo[r][n4] = *(const uint4*)(wl + (size_t)r * DD + n4);
            }
        }
        __syncthreads();

#pragma unroll
        for (int s = 0; s < 2; s++) {
            int kb = s * 8 + (lane & 3);
            int m = wr * 16 + (lane >> 2);
            uint32_t ah[4], al[4];
            ah[0] = As_hi[kb][m];     ah[1] = As_hi[kb][m + 8];
            ah[2] = As_hi[kb + 4][m]; ah[3] = As_hi[kb + 4][m + 8];
            al[0] = As_lo[kb][m];     al[1] = As_lo[kb][m + 8];
            al[2] = As_lo[kb + 4][m]; al[3] = As_lo[kb + 4][m + 8];
#pragma unroll
            for (int j = 0; j < 8; j++) {
                int n = wc * 64 + j * 8 + (lane >> 2);
                uint32_t bh0 = Bs_hi[kb][n], bh1 = Bs_hi[kb + 4][n];
                uint32_t bl0 = Bs_lo[kb][n], bl1 = Bs_lo[kb + 4][n];
                mma_bf16(acc[j], ah, bh0, bh1);
                mma_bf16(acc[j], ah, bl0, bl1);
                mma_bf16(acc[j], al, bh0, bh1);
            }
        }
        __syncthreads();
    }

#pragma unroll
    for (int j = 0; j < 8; j++) {
        int gc = col0 + wc * 64 + j * 8 + (lane & 3) * 2;
        float bx = __ldg(&bias[gc]);
        float by = __ldg(&bias[gc + 1]);
        float sx = 0.f, sy = 0.f, qx = 0.f, qy = 0.f;
        int gr = row0 + wr * 16 + (lane >> 2);
        if (gr < M) {
            float2 v0 = make_float2(acc[j][0] + bx, acc[j][1] + by);
            *(float2*)(C + (size_t)gr * DD + gc) = v0;
            sx += v0.x; sy += v0.y; qx += v0.x * v0.x; qy += v0.y * v0.y;
        }
        if (gr + 8 < M) {
            float2 v1 = make_float2(acc[j][2] + bx, acc[j][3] + by);
            *(float2*)(C + (size_t)(gr + 8) * DD + gc) = v1;
            sx += v1.x; sy += v1.y; qx += v1.x * v1.x; qy += v1.y * v1.y;
        }
#pragma unroll
        for (int d = 4; d < 32; d <<= 1) {
            sx += __shfl_xor_sync(0xffffffff, sx, d);
            sy += __shfl_xor_sync(0xffffffff, sy, d);
            qx += __shfl_xor_sync(0xffffffff, qx, d);
            qy += __shfl_xor_sync(0xffffffff, qy, d);
        }
        if ((lane >> 2) == 0) {
            red2(&stats[gc], sx, sy);
            red2(&stats[DD + gc], qx, qy);
        }
    }
}

// ---------------- BN prep (vn path only) ----------------
__global__ void k_bn_prep(float* __restrict__ stats, float* __restrict__ bnp,
                          const float* __restrict__ gamma, const float* __restrict__ beta,
                          float Minv) {
    int c = threadIdx.x;
    float m = stats[c] * Minv;
    float var = stats[DD + c] * Minv - m * m;
    float rs = rsqrtf(var + BN_EPS);
    float sc = gamma[c] * rs;
    bnp[c] = sc;
    bnp[DD + c] = beta[c] - m * sc;
    stats[c] = 0.f;
    stats[DD + c] = 0.f;
}

// BN apply; if stats != nullptr compute scale/shift in-block from stats, else use bnp_pre
__global__ void k_bn_apply(const float* __restrict__ Yin, float* __restrict__ Yout,
                           const float* __restrict__ bnp_pre, const float* __restrict__ stats,
                           const float* __restrict__ gamma, const float* __restrict__ beta,
                           float Minv, const int* __restrict__ batch,
                           int M, int do_relu, int do_vn, int do_pool) {
    __shared__ __align__(16) float sb[2 * DD];
    int tid = threadIdx.x;
    if (stats) {
        float m = __ldg(&stats[tid]) * Minv;
        float var = __ldg(&stats[DD + tid]) * Minv - m * m;
        float rs = rsqrtf(var + BN_EPS);
        float sc = __ldg(&gamma[tid]) * rs;
        sb[tid] = sc;
        sb[DD + tid] = __ldg(&beta[tid]) - m * sc;
    } else {
        sb[tid] = bnp_pre[tid];
        sb[DD + tid] = bnp_pre[DD + tid];
    }
    __syncthreads();

    int idx = blockIdx.x * blockDim.x + tid;
    if (idx >= M * 64) return;
    int r = idx >> 6;
    int c4 = (idx & 63) * 4;
    float4 sc = *(const float4*)(sb + c4);
    float4 sh = *(const float4*)(sb + DD + c4);
    float4 v = *(const float4*)(Yin + (size_t)r * DD + c4);
    v.x = v.x * sc.x + sh.x;
    v.y = v.y * sc.y + sh.y;
    v.z = v.z * sc.z + sh.z;
    v.w = v.w * sc.w + sh.w;
    if (do_relu) {
        v.x = fmaxf(v.x, 0.f); v.y = fmaxf(v.y, 0.f);
        v.z = fmaxf(v.z, 0.f); v.w = fmaxf(v.w, 0.f);
    }
    int g = 0;
    if (do_vn || do_pool) g = __ldg(&batch[r]);
    if (do_vn) {
        float4 w = *(const float4*)(g_vn + (size_t)g * DD + c4);
        v.x += w.x; v.y += w.y; v.z += w.z; v.w += w.w;
    }
    *(float4*)(Yout + (size_t)r * DD + c4) = v;
    if (do_pool) red4(g_pooled + (size_t)g * DD + c4, v.x, v.y, v.z, v.w);
}

// ---------------- host orchestration ----------------
extern "C" void kernel_launch(void* const* d_in, const int* in_sizes, int n_in,
                              void* d_out, int out_size) {
    const int* x          = (const int*)d_in[0];
    const int* edge_index = (const int*)d_in[1];
    const int* edge_attr  = (const int*)d_in[2];
    const int* batch      = (const int*)d_in[3];
    const float* atom_emb = (const float*)d_in[4];
    const float* bond_emb = (const float*)d_in[5];
    const float* vn_emb   = (const float*)d_in[6];
    const float* gin_eps  = (const float*)d_in[7];
    const float* conv_W1  = (const float*)d_in[8];
    const float* conv_b1  = (const float*)d_in[9];
    const float* conv_bn_g = (const float*)d_in[10];
    const float* conv_bn_b = (const float*)d_in[11];
    const float* conv_W2  = (const float*)d_in[12];
    const float* conv_b2  = (const float*)d_in[13];
    const float* outer_bn_g = (const float*)d_in[14];
    const float* outer_bn_b = (const float*)d_in[15];
    const float* vn_W1    = (const float*)d_in[16];
    const float* vn_b1    = (const float*)d_in[17];
    const float* vn_bn1_g = (const float*)d_in[18];
    const float* vn_bn1_b = (const float*)d_in[19];
    const float* vn_W2    = (const float*)d_in[20];
    const float* vn_b2    = (const float*)d_in[21];
    const float* vn_bn2_g = (const float*)d_in[22];
    const float* vn_bn2_b = (const float*)d_in[23];
    float* out = (float*)d_out;

    cudaFuncSetAttribute(k_gemm_big<0>, cudaFuncAttributeMaxDynamicSharedMemorySize, SMEM_BIG);
    cudaFuncSetAttribute(k_gemm_big<2>, cudaFuncAttributeMaxDynamicSharedMemorySize, SMEM_BIG);

    float *p_t, *p_y, *p_pooled, *p_vt, *p_vt2, *p_vn;
    float *p_stats, *p_stats2, *p_stats_v, *p_bnp_v;
    uint32_t *p_whi, *p_wlo;
    cudaGetSymbolAddress((void**)&p_t, g_t);
    cudaGetSymbolAddress((void**)&p_y, g_y);
    cudaGetSymbolAddress((void**)&p_pooled, g_pooled);
    cudaGetSymbolAddress((void**)&p_vt, g_vt);
    cudaGetSymbolAddress((void**)&p_vt2, g_vt2);
    cudaGetSymbolAddress((void**)&p_vn, g_vn);
    cudaGetSymbolAddress((void**)&p_stats, g_stats);
    cudaGetSymbolAddress((void**)&p_stats2, g_stats2);
    cudaGetSymbolAddress((void**)&p_stats_v, g_stats_v);
    cudaGetSymbolAddress((void**)&p_bnp_v, g_bnp_v);
    cudaGetSymbolAddress((void**)&p_whi, g_whi);
    cudaGetSymbolAddress((void**)&p_wlo, g_wlo);

    const size_t slot = (size_t)NN * DD;
    const size_t wslot = (size_t)128 * DD;
    const int blkN = (NN * 64 + 255) / 256;
    const float invN = 1.0f / (float)NN;
    const float invG = 1.0f / (float)GG;

    // static stream/events: created once on first (correctness) call so all
    // driver-side pools predate the capture baseline
    static cudaStream_t sv = nullptr;
    static cudaEvent_t ev_start, ev_pre, ev_fork[LL], ev_join[LL];
    if (!sv) {
        cudaStreamCreateWithFlags(&sv, cudaStreamNonBlocking);
        cudaEventCreateWithFlags(&ev_start, cudaEventDisableTiming);
        cudaEventCreateWithFlags(&ev_pre, cudaEventDisableTiming);
        for (int l = 0; l < LL; l++) {
            cudaEventCreateWithFlags(&ev_fork[l], cudaEventDisableTiming);
            cudaEventCreateWithFlags(&ev_join[l], cudaEventDisableTiming);
        }
    }

    // ---- prologue fork ----
    cudaEventRecord(ev_start, 0);
    cudaStreamWaitEvent(sv, ev_start, 0);

    const int wgrid = (128 * DD + 255) / 256;

    // sv chain, phase 1: CSR + stats zeros + LAYER-0 conv splits only
    k_zero_off<<<(NN + 2 + 255) / 256, 256, 0, sv>>>();
    k_hist<<<(EE + 255) / 256, 256, 0, sv>>>(edge_index);
    k_scan<<<1, SCAN_T, 0, sv>>>();
    k_scatter_e<<<(EE + 255) / 256, 256, 0, sv>>>(edge_index, edge_attr);
    k_zero<<<1, 128, 0, sv>>>(p_stats, 128);
    k_zero<<<1, 128, 0, sv>>>(p_stats2, 128);
    k_zero<<<1, 128, 0, sv>>>(p_stats_v, 128);
    k_split_w<<<wgrid, 256, 0, sv>>>(conv_W1, p_whi, p_wlo);
    k_split_w<<<wgrid, 256, 0, sv>>>(conv_W2, p_whi + (size_t)5 * wslot,
                                     p_wlo + (size_t)5 * wslot);
    cudaEventRecord(ev_pre, sv);   // layer 0 main path can start after this

    // sv chain, phase 2: remaining splits (overlap with layer-0 main path;
    // guaranteed done before vn chain layer 0 ends -> before any layer>=1 use)
    for (int l = 1; l < LL; l++) {
        k_split_w<<<wgrid, 256, 0, sv>>>(conv_W1 + (size_t)l * DD * DD,
                                         p_whi + (size_t)l * wslot, p_wlo + (size_t)l * wslot);
        k_split_w<<<wgrid, 256, 0, sv>>>(conv_W2 + (size_t)l * DD * DD,
                                         p_whi + (size_t)(5 + l) * wslot,
                                         p_wlo + (size_t)(5 + l) * wslot);
    }
    for (int l = 0; l < LL - 1; l++) {
        k_split_w<<<wgrid, 256, 0, sv>>>(vn_W1 + (size_t)l * DD * DD,
                                         p_whi + (size_t)(10 + l) * wslot,
                                         p_wlo + (size_t)(10 + l) * wslot);
        k_split_w<<<wgrid, 256, 0, sv>>>(vn_W2 + (size_t)l * DD * DD,
                                         p_whi + (size_t)(14 + l) * wslot,
                                         p_wlo + (size_t)(14 + l) * wslot);
    }

    // main chain
    k_zero<<<(GG * 64 + 255) / 256, 256>>>(p_pooled, GG * 64);
    k_build_lut<<<(216 * 64 + 255) / 256, 256>>>(bond_emb);
    k_encode_atoms<<<blkN, 256>>>(x, atom_emb, vn_emb, batch, out);
    k_vn_init<<<(GG * DD + 255) / 256, 256>>>(vn_emb);
    cudaStreamWaitEvent(0, ev_pre, 0);   // CSR + layer-0 conv weights ready

    const int gBig = (NN + BM - 1) / BM;
    const dim3 gSmall((GG + 63) / 64, 2);
    const int gAgg = (NN * 32 + 255) / 256;

    for (int l = 0; l < LL; l++) {
        float* h = out + (size_t)l * slot;
        float* z_out = out + (size_t)(l + 1) * slot;

        // vn chain on sv (runs after phase-2 splits by stream order)
        if (l < LL - 1) {
            cudaEventRecord(ev_fork[l], 0);
            cudaStreamWaitEvent(sv, ev_fork[l], 0);
            k_gemm_small<3><<<gSmall, 256, 0, sv>>>(p_pooled, p_vn,
                                                    p_whi + (size_t)(10 + l) * wslot,
                                                    p_wlo + (size_t)(10 + l) * wslot,
                                                    vn_b1 + l * DD, p_vt, GG,
                                                    p_stats_v, nullptr);
            k_zero<<<(GG * 64 + 255) / 256, 256, 0, sv>>>(p_pooled, GG * 64);
            k_bn_prep<<<1, 256, 0, sv>>>(p_stats_v, p_bnp_v,
                                         vn_bn1_g + l * DD, vn_bn1_b + l * DD, invG);
            k_gemm_small<2><<<gSmall, 256, 0, sv>>>(p_vt, nullptr,
                                                    p_whi + (size_t)(14 + l) * wslot,
                                                    p_wlo + (size_t)(14 + l) * wslot,
                                                    vn_b2 + l * DD, p_vt2, GG,
                                                    p_stats_v, p_bnp_v);
            k_bn_prep<<<1, 256, 0, sv>>>(p_stats_v, p_bnp_v,
                                         vn_bn2_g + l * DD, vn_bn2_b + l * DD, invG);
            k_bn_apply<<<(GG * 64 + 255) / 256, 256, 0, sv>>>(p_vt2, p_vn, p_bnp_v,
                                                              nullptr, nullptr, nullptr, 0.f,
                                                              nullptr, GG, 1, 0, 0);
            cudaEventRecord(ev_join[l], sv);
        }

        // main path: agg (+stats zero) -> GEMM1 -> GEMM2(fused prep) -> bn_apply(fused prep)
        k_agg<<<gAgg, 256>>>(h, gin_eps + l);
        k_gemm_big<0><<<gBig, 256, SMEM_BIG>>>(p_t,
                                               p_whi + (size_t)l * wslot,
                                               p_wlo + (size_t)l * wslot,
                                               conv_b1 + l * DD, p_y, NN,
                                               p_stats, nullptr, nullptr, nullptr, 0.f);
        k_gemm_big<2><<<gBig, 256, SMEM_BIG>>>(p_y,
                                               p_whi + (size_t)(5 + l) * wslot,
                                               p_wlo + (size_t)(5 + l) * wslot,
                                               conv_b2 + l * DD, p_t, NN,
                                               p_stats2, p_stats,
                                               conv_bn_g + l * DD, conv_bn_b + l * DD, invN);
        if (l < LL - 1) cudaStreamWaitEvent(0, ev_join[l], 0);
        int relu = (l < LL - 1) ? 1 : 0;
        int vnadd = (l < LL - 1) ? 1 : 0;
        int pool = (l < LL - 2) ? 1 : 0;
        k_bn_apply<<<blkN, 256>>>(p_t, z_out, nullptr, p_stats2,
                                  outer_bn_g + l * DD, outer_bn_b + l * DD, invN,
                                  batch, NN, relu, vnadd, pool);
    }
}